// round 3
// baseline (speedup 1.0000x reference)
#include <cuda_runtime.h>
#include <cstdint>

#define HD   512
#define BT   32768            // B*T = 128*256
#define BSZ  128
#define KBM  4096             // 128*32 attention rows per idx
#define KBTOT 32768

// ---------------- scratch (device globals; no allocations allowed) ----------
__device__ float g_bufA[BT * HD];
__device__ float g_bufB[BT * HD];
__device__ float g_arn [BT * HD];
__device__ float g_add [BT * HD];
__device__ float g_E   [6 * KBM * HD];
__device__ float g_u   [6 * KBM];      // [idx][b*32+r]
__device__ float g_eng [BT];
__device__ int   g_maskmode;           // 0=uint8, 1=int32, 2=float32

typedef unsigned long long u64;

__device__ __forceinline__ u64 pack2(float lo, float hi) {
    u64 r; asm("mov.b64 %0,{%1,%2};" : "=l"(r) : "f"(lo), "f"(hi)); return r;
}
__device__ __forceinline__ void fma2(u64& d, u64 a, u64 b) {
    asm("fma.rn.f32x2 %0,%1,%2,%0;" : "+l"(d) : "l"(a), "l"(b));
}
__device__ __forceinline__ float2 unpack2(u64 v) {
    float lo, hi; asm("mov.b64 {%0,%1},%2;" : "=f"(lo), "=f"(hi) : "l"(v));
    return make_float2(lo, hi);
}

__device__ __forceinline__ float actf(float v, int act) {
    if (act == 1) return fmaxf(v, 0.0f);
    if (act == 2) return 1.0f / (1.0f + expf(-v));
    if (act == 3) return tanhf(v);
    return v;
}

// Dual-source loads: logical K axis is [0, Ksplit) from src0 (row width Ksplit)
// and [Ksplit, K) from src1 (row width K1).
__device__ __forceinline__ float4 ldA(const float* __restrict__ A0,
                                      const float* __restrict__ A1,
                                      int a1shift, int Ksplit, int K1,
                                      int row, int kg) {
    if (kg < Ksplit) return *(const float4*)(A0 + (size_t)row * Ksplit + kg);
    return *(const float4*)(A1 + (size_t)(row >> a1shift) * K1 + (kg - Ksplit));
}
__device__ __forceinline__ float4 ldB(const float* __restrict__ B0,
                                      const float* __restrict__ B1,
                                      int Ksplit, int N, int kg, int col) {
    if (kg < Ksplit) return *(const float4*)(B0 + (size_t)kg * N + col);
    return *(const float4*)(B1 + (size_t)(kg - Ksplit) * N + col);
}

// ---------------- SGEMM: C[M,N] = act(A @ B + bias), fp32, f32x2 inner ------
// 128x128 block tile, 256 threads, 8x8 per thread, K-tile 8, double-buffered.
__global__ __launch_bounds__(256, 2)
void sgemm_f32x2(const float* __restrict__ A0, const float* __restrict__ A1,
                 int a1shift,
                 const float* __restrict__ B0, const float* __restrict__ B1,
                 const float* __restrict__ bias,
                 float* __restrict__ C,
                 int M, int N, int K, int Ksplit,
                 int act, int finalMode,
                 const float* __restrict__ p_arn, const float* __restrict__ p_add,
                 const float* __restrict__ p_cell, const float* __restrict__ p_eng,
                 float* __restrict__ outH, float* __restrict__ outC) {
    __shared__ float As[2][8][132];
    __shared__ float Bs[2][8][132];

    const int tid   = threadIdx.x;
    const int mBase = blockIdx.y * 128;
    const int nBase = blockIdx.x * 128;
    const int K1    = K - Ksplit;

    const int am = tid >> 1;            // 0..127 (A row within tile)
    const int ak = (tid & 1) << 2;      // 0 or 4 (A k sub-chunk)
    const int bk = tid >> 5;            // 0..7  (B k row)
    const int bn = (tid & 31) << 2;     // 0..124 (B col chunk)

    const int tm = (tid >> 4) << 3;     // 0..120
    const int tn = (tid & 15) << 3;     // 0..120

    u64 acc[8][4];
#pragma unroll
    for (int i = 0; i < 8; i++)
#pragma unroll
        for (int j = 0; j < 4; j++) acc[i][j] = 0ull;

    const int nk = K >> 3;

    // prologue: tile 0 -> stage 0
    {
        float4 av = ldA(A0, A1, a1shift, Ksplit, K1, mBase + am, ak);
        float4 bv = ldB(B0, B1, Ksplit, N, bk, nBase + bn);
        As[0][ak + 0][am] = av.x; As[0][ak + 1][am] = av.y;
        As[0][ak + 2][am] = av.z; As[0][ak + 3][am] = av.w;
        *(float4*)&Bs[0][bk][bn] = bv;
    }
    __syncthreads();

    int s = 0;
    for (int kt = 0; kt < nk; kt++) {
        float4 av, bv;
        const bool more = (kt + 1 < nk);
        if (more) {
            const int kg = (kt + 1) << 3;
            av = ldA(A0, A1, a1shift, Ksplit, K1, mBase + am, kg + ak);
            bv = ldB(B0, B1, Ksplit, N, kg + bk, nBase + bn);
        }
#pragma unroll
        for (int kk = 0; kk < 8; kk++) {
            float4 a0 = *(const float4*)&As[s][kk][tm];
            float4 a1 = *(const float4*)&As[s][kk][tm + 4];
            float4 b0 = *(const float4*)&Bs[s][kk][tn];
            float4 b1 = *(const float4*)&Bs[s][kk][tn + 4];
            u64 bb[4];
            bb[0] = pack2(b0.x, b0.y); bb[1] = pack2(b0.z, b0.w);
            bb[2] = pack2(b1.x, b1.y); bb[3] = pack2(b1.z, b1.w);
            float aa[8] = {a0.x, a0.y, a0.z, a0.w, a1.x, a1.y, a1.z, a1.w};
#pragma unroll
            for (int i = 0; i < 8; i++) {
                u64 a2 = pack2(aa[i], aa[i]);
                fma2(acc[i][0], a2, bb[0]);
                fma2(acc[i][1], a2, bb[1]);
                fma2(acc[i][2], a2, bb[2]);
                fma2(acc[i][3], a2, bb[3]);
            }
        }
        if (more) {
            const int ns = s ^ 1;
            As[ns][ak + 0][am] = av.x; As[ns][ak + 1][am] = av.y;
            As[ns][ak + 2][am] = av.z; As[ns][ak + 3][am] = av.w;
            *(float4*)&Bs[ns][bk][bn] = bv;
            __syncthreads();
            s = ns;
        }
    }

    // epilogue
#pragma unroll
    for (int i = 0; i < 8; i++) {
        const int row = mBase + tm + i;
        const size_t cro = (size_t)row * N;
#pragma unroll
        for (int j2 = 0; j2 < 4; j2++) {
            float2 v = unpack2(acc[i][j2]);
            const int col = nBase + tn + (j2 << 1);
            float x0 = v.x, x1 = v.y;
            if (bias) { x0 += bias[col]; x1 += bias[col + 1]; }
            x0 = actf(x0, act);
            x1 = actf(x1, act);
            if (finalMode) {
                const float e = p_eng[row];
                const size_t i0 = cro + col, i1 = i0 + 1;
                float ni0 = p_arn[i0] * p_add[i0];
                float ni1 = p_arn[i1] * p_add[i1];
                float uc0 = p_cell[i0] + ni0 * e;
                float uc1 = p_cell[i1] + ni1 * e;
                outC[i0] = uc0; outC[i1] = uc1;
                outH[i0] = x0 * tanhf(uc0);
                outH[i1] = x1 * tanhf(uc1);
            } else {
                C[cro + col]     = x0;
                C[cro + col + 1] = x1;
            }
        }
    }
}

// u[idx][m] = sum_n E[idx*4096+m][n] * v_att[idx][n]; one warp per row
__global__ void u_reduce_kernel(const float* __restrict__ E,
                                const float* __restrict__ v_att,
                                float* __restrict__ u) {
    const int row  = blockIdx.x * 8 + (threadIdx.x >> 5);
    const int lane = threadIdx.x & 31;
    const int idx  = row >> 12;  // row / 4096
    const float* e = E + (size_t)row * HD;
    const float* v = v_att + idx * HD;
    float sacc = 0.0f;
#pragma unroll 4
    for (int k = lane; k < HD; k += 32) sacc += e[k] * v[k];
#pragma unroll
    for (int o = 16; o; o >>= 1) sacc += __shfl_down_sync(0xffffffffu, sacc, o);
    if (!lane) u[row] = sacc;
}

// eng[row] = dot(cell[row], eng_w)
__global__ void eng_kernel(const float* __restrict__ cell,
                           const float* __restrict__ w,
                           float* __restrict__ eng) {
    const int row  = blockIdx.x * 8 + (threadIdx.x >> 5);
    const int lane = threadIdx.x & 31;
    const float* c = cell + (size_t)row * HD;
    float sacc = 0.0f;
#pragma unroll 4
    for (int k = lane; k < HD; k += 32) sacc += c[k] * w[k];
#pragma unroll
    for (int o = 16; o; o >>= 1) sacc += __shfl_down_sync(0xffffffffu, sacc, o);
    if (!lane) eng[row] = sacc;
}

// Detect the storage dtype of kb_mask (bools may arrive as uint8 / int32 /
// float32 depending on harness conversion). Scans the first 64K 32-bit words
// (256 KB — safe for every candidate layout; smallest possible buffer is 4 MB).
//   any word == 0x3F800000 (1.0f)          -> float32
//   else any word > 1                      -> packed uint8 bools
//   else                                   -> int32 0/1
__global__ void detect_mask_kernel(const unsigned int* __restrict__ w) {
    __shared__ int sF, sG;
    if (threadIdx.x == 0) { sF = 0; sG = 0; }
    __syncthreads();
    int f = 0, g = 0;
    for (int i = threadIdx.x; i < 65536; i += blockDim.x) {
        const unsigned int v = w[i];
        if (v == 0x3F800000u) f = 1;
        else if (v > 1u) g = 1;
    }
    if (f) atomicOr(&sF, 1);
    if (g) atomicOr(&sG, 1);
    __syncthreads();
    if (threadIdx.x == 0) g_maskmode = sF ? 2 : (sG ? 0 : 1);
}

// u_t_k[b][j] = mask ? 0 : sum_d S_d[digit_d(j)], S_d = sum over hops of u
__global__ void utk_kernel(const float* __restrict__ u,
                           const void* __restrict__ maskraw,
                           float* __restrict__ out) {
    __shared__ float S[3][32];
    const int b = blockIdx.y;
    if (threadIdx.x < 96) {
        const int d = threadIdx.x >> 5, i = threadIdx.x & 31;
        S[d][i] = u[(0 * 3 + d) * KBM + b * 32 + i]
                + u[(1 * 3 + d) * KBM + b * 32 + i];
    }
    __syncthreads();
    const int mode = g_maskmode;
    const int j = blockIdx.x * 256 + threadIdx.x;
    const float v = S[0][j >> 10] + S[1][(j >> 5) & 31] + S[2][j & 31];
    const size_t o = (size_t)b * KBTOT + j;
    bool m;
    if (mode == 0)      m = ((const unsigned char*)maskraw)[o] != 0;
    else if (mode == 1) m = ((const int*)maskraw)[o] != 0;
    else                m = ((const float*)maskraw)[o] != 0.0f;
    out[o] = m ? 0.0f : v;
}

extern "C" void kernel_launch(void* const* d_in, const int* in_sizes, int n_in,
                              void* d_out, int out_size) {
    const float* query   = (const float*)d_in[0];
    const float* kb_keys = (const float*)d_in[1];
    const float* Wq      = (const float*)d_in[2];
    const float* Wk      = (const float*)d_in[3];
    const float* v_att   = (const float*)d_in[4];
    const float* x       = (const float*)d_in[5];
    const float* hidden  = (const float*)d_in[6];
    const float* cell    = (const float*)d_in[7];
    const float* arn_w1  = (const float*)d_in[8];
    const float* arn_b1  = (const float*)d_in[9];
    const float* arn_w2  = (const float*)d_in[10];
    const float* arn_b2  = (const float*)d_in[11];
    const float* arn_w3  = (const float*)d_in[12];
    const float* arn_b3  = (const float*)d_in[13];
    const float* add_w1  = (const float*)d_in[14];
    const float* add_b1  = (const float*)d_in[15];
    const float* add_w2  = (const float*)d_in[16];
    const float* add_b2  = (const float*)d_in[17];
    const float* add_w3  = (const float*)d_in[18];
    const float* add_b3  = (const float*)d_in[19];
    const float* eng_w   = (const float*)d_in[20];
    const float* wc_w1   = (const float*)d_in[21];
    const float* wc_b1   = (const float*)d_in[22];
    const float* wc_w2   = (const float*)d_in[23];
    const float* wc_b2   = (const float*)d_in[24];
    const float* wc_w3   = (const float*)d_in[25];
    const float* wc_b3   = (const float*)d_in[26];
    const float* wc_w4   = (const float*)d_in[27];
    const float* wc_b4   = (const float*)d_in[28];
    const void*  kb_mask = d_in[29];

    float* out     = (float*)d_out;
    float* out_utk = out;                       // 128*32768
    float* outH    = out + (size_t)BSZ * KBTOT; // 128*256*512
    float* outC    = outH + (size_t)BT * HD;

    float *bufA, *bufB, *arnp, *addp, *Ep, *up, *engp;
    cudaGetSymbolAddress((void**)&bufA, g_bufA);
    cudaGetSymbolAddress((void**)&bufB, g_bufB);
    cudaGetSymbolAddress((void**)&arnp, g_arn);
    cudaGetSymbolAddress((void**)&addp, g_add);
    cudaGetSymbolAddress((void**)&Ep,   g_E);
    cudaGetSymbolAddress((void**)&up,   g_u);
    cudaGetSymbolAddress((void**)&engp, g_eng);

    const dim3 blk(256);
    const dim3 gAtt(HD / 128, KBM / 128);   // (4, 32)
    const dim3 gMlp(HD / 128, BT / 128);    // (4, 256)

    detect_mask_kernel<<<1, 1024>>>((const unsigned int*)kb_mask);

    // ---- attention: E[idx] = tanh([kb_keys[dim] | query(bcast)] @ [Wk;Wq]) ----
    for (int idx = 0; idx < 6; idx++) {
        const int dim = idx % 3;
        sgemm_f32x2<<<gAtt, blk>>>(
            kb_keys + (size_t)dim * KBM * HD, query, /*a1shift=*/5,
            Wk + (size_t)idx * HD * HD, Wq + (size_t)idx * HD * HD,
            nullptr, Ep + (size_t)idx * KBM * HD,
            KBM, HD, 2 * HD, HD, /*act=tanh*/3, 0,
            nullptr, nullptr, nullptr, nullptr, nullptr, nullptr);
    }
    u_reduce_kernel<<<6 * KBM / 8, 256>>>(Ep, v_att, up);
    {
        dim3 g(KBTOT / 256, BSZ);
        utk_kernel<<<g, 256>>>(up, kb_mask, out_utk);
    }

    // ---- eng = cell @ eng_w ----
    eng_kernel<<<BT / 8, 256>>>(cell, eng_w, engp);

    // ---- arn path ----
    sgemm_f32x2<<<gMlp, blk>>>(x, hidden, 0, arn_w1, arn_w1 + HD * HD, arn_b1,
                               bufA, BT, HD, 2 * HD, HD, 1, 0,
                               nullptr, nullptr, nullptr, nullptr, nullptr, nullptr);
    sgemm_f32x2<<<gMlp, blk>>>(bufA, bufA, 0, arn_w2, arn_w2, arn_b2,
                               bufB, BT, HD, HD, HD, 1, 0,
                               nullptr, nullptr, nullptr, nullptr, nullptr, nullptr);
    sgemm_f32x2<<<gMlp, blk>>>(bufB, bufB, 0, arn_w3, arn_w3, arn_b3,
                               arnp, BT, HD, HD, HD, 2, 0,
                               nullptr, nullptr, nullptr, nullptr, nullptr, nullptr);

    // ---- add path ----
    sgemm_f32x2<<<gMlp, blk>>>(x, hidden, 0, add_w1, add_w1 + HD * HD, add_b1,
                               bufA, BT, HD, 2 * HD, HD, 1, 0,
                               nullptr, nullptr, nullptr, nullptr, nullptr, nullptr);
    sgemm_f32x2<<<gMlp, blk>>>(bufA, bufA, 0, add_w2, add_w2, add_b2,
                               bufB, BT, HD, HD, HD, 1, 0,
                               nullptr, nullptr, nullptr, nullptr, nullptr, nullptr);
    sgemm_f32x2<<<gMlp, blk>>>(bufB, bufB, 0, add_w3, add_w3, add_b3,
                               addp, BT, HD, HD, HD, 3, 0,
                               nullptr, nullptr, nullptr, nullptr, nullptr, nullptr);

    // ---- wc path (final GEMM fuses the cell/hidden update epilogue) ----
    sgemm_f32x2<<<gMlp, blk>>>(x, hidden, 0, wc_w1, wc_w1 + HD * HD, wc_b1,
                               bufA, BT, HD, 2 * HD, HD, 1, 0,
                               nullptr, nullptr, nullptr, nullptr, nullptr, nullptr);
    sgemm_f32x2<<<gMlp, blk>>>(bufA, bufA, 0, wc_w2, wc_w2, wc_b2,
                               bufB, BT, HD, HD, HD, 1, 0,
                               nullptr, nullptr, nullptr, nullptr, nullptr, nullptr);
    sgemm_f32x2<<<gMlp, blk>>>(bufB, bufB, 0, wc_w3, wc_w3, wc_b3,
                               bufA, BT, HD, HD, HD, 1, 0,
                               nullptr, nullptr, nullptr, nullptr, nullptr, nullptr);
    sgemm_f32x2<<<gMlp, blk>>>(bufA, bufA, 0, wc_w4, wc_w4, wc_b4,
                               bufB /*unused*/, BT, HD, HD, HD, 2, /*final*/1,
                               arnp, addp, cell, engp, outH, outC);
}

// round 5
// speedup vs baseline: 3.3041x; 3.3041x over previous
#include <cuda_runtime.h>
#include <cuda_bf16.h>
#include <cstdint>

#define HD 512
#define BT 32768
#define BSZ 128
#define KBM 4096
#define KBTOT 32768

typedef unsigned int u32;
typedef unsigned long long u64;
typedef unsigned short u16;

// plane offsets (elements)
#define BIG    524288ULL                  // 512n x 1024k
#define SMALL  262144ULL                  // 512n x 512k
#define WSOFF  (9ULL*BIG)                 // small slots start
#define ATTZ   4194304ULL                 // 4096 x 1024 per dim
#define INFO_OFF 0ULL
#define H1S    16777216ULL                // 32768 x 512
#define H1_OFF 33554432ULL
#define H2_OFF (H1_OFF + 3*H1S)

__device__ u16   g_wbh[9*BIG + 7*SMALL];
__device__ u16   g_wbl[9*BIG + 7*SMALL];
__device__ u16   g_atth[3*ATTZ];
__device__ u16   g_attl[3*ATTZ];
__device__ u16   g_ah[134217728];         // info + h1[3] + h2[3]
__device__ u16   g_al[134217728];
__device__ float g_arn[(size_t)BT*HD];
__device__ float g_add[(size_t)BT*HD];
__device__ float g_upart[16*6*KBM];
__device__ float g_eng[BT];
__device__ int   g_maskmode;

__device__ __forceinline__ void split2(float v, u16& h, u16& l) {
    __nv_bfloat16 bh = __float2bfloat16(v);
    h = __bfloat16_as_ushort(bh);
    l = __bfloat16_as_ushort(__float2bfloat16(v - __bfloat162float(bh)));
}
__device__ __forceinline__ u32 smem_u32(const void* p) {
    u32 a;
    asm("{ .reg .u64 t; cvta.to.shared.u64 t, %1; cvt.u32.u64 %0, t; }" : "=r"(a) : "l"(p));
    return a;
}
__device__ __forceinline__ void cp16(u32 dst, const void* src) {
    asm volatile("cp.async.cg.shared.global [%0], [%1], 16;" :: "r"(dst), "l"(src));
}
__device__ __forceinline__ void ldsm4(u32* r, u32 a) {
    asm volatile("ldmatrix.sync.aligned.m8n8.x4.shared.b16 {%0,%1,%2,%3}, [%4];"
                 : "=r"(r[0]), "=r"(r[1]), "=r"(r[2]), "=r"(r[3]) : "r"(a));
}
__device__ __forceinline__ void mma16816(float* c, const u32* a, const u32* b) {
    asm volatile("mma.sync.aligned.m16n8k16.row.col.f32.bf16.bf16.f32 "
                 "{%0,%1,%2,%3},{%4,%5,%6,%7},{%8,%9},{%0,%1,%2,%3};"
                 : "+f"(c[0]), "+f"(c[1]), "+f"(c[2]), "+f"(c[3])
                 : "r"(a[0]), "r"(a[1]), "r"(a[2]), "r"(a[3]), "r"(b[0]), "r"(b[1]));
}

// ---------------- stage loader: gmem planes -> swizzled smem tiles ----------
__device__ __forceinline__ void stage_load(
    u32 sb, int stage,
    const u16* __restrict__ Ah, const u16* __restrict__ Al,
    const u16* __restrict__ Bh, const u16* __restrict__ Bl,
    int mBase, int nBase, int K, int kt, int tid) {
    const u32 so = sb + stage * 32768;
    const int kOff = kt * 32;
#pragma unroll
    for (int j = 0; j < 2; j++) {
        const int id = tid + j * 256;
        const int r = id >> 2, c = id & 3;
        const u32 dst = so + r * 64 + ((c ^ ((r >> 1) & 3)) << 4);
        const size_t aoff = (size_t)(mBase + r) * K + kOff + c * 8;
        const size_t boff = (size_t)(nBase + r) * K + kOff + c * 8;
        cp16(dst,          Ah + aoff);
        cp16(dst + 8192,   Al + aoff);
        cp16(dst + 16384,  Bh + boff);
        cp16(dst + 24576,  Bl + boff);
    }
}

// ---------------- GEMM: C[M,128tile] = act(A @ B^T + bias) -----------------
// modes: 0 relu->planes, 3 attention (tanh dot v_att), 4 final fused, 5 L3 combo
__global__ __launch_bounds__(256, 2)
void gemm_tc(const u16* __restrict__ Ahp, const u16* __restrict__ Alp,
             size_t aStrideZ, int aZmod,
             const u16* __restrict__ Bhp, const u16* __restrict__ Blp,
             size_t bStrideZ, int K,
             const float* __restrict__ bias0, const float* __restrict__ bias1,
             const float* __restrict__ bias2, int mode,
             u16* __restrict__ oH, u16* __restrict__ oL, size_t oStrideZ,
             float* __restrict__ plain0, float* __restrict__ plain1,
             const float* __restrict__ vatt, float* __restrict__ upart,
             const float* __restrict__ p_arn, const float* __restrict__ p_add,
             const float* __restrict__ p_cell, const float* __restrict__ p_eng,
             float* __restrict__ outH, float* __restrict__ outC) {
    extern __shared__ char smem[];
    const u32 sb = smem_u32(smem);
    const int tid = threadIdx.x, lane = tid & 31, warp = tid >> 5;
    const int warpM = warp >> 2, warpN = warp & 3;
    const int rowBase = warpM * 64, colBase = warpN * 32;
    const int nt = blockIdx.x, mt = blockIdx.y, z = blockIdx.z;
    const int mBase = mt * 128, nBase = nt * 128;

    const int az = aZmod ? (z % aZmod) : z;
    const u16* Ah = Ahp + (size_t)az * aStrideZ;
    const u16* Al = Alp + (size_t)az * aStrideZ;
    const u16* Bh = Bhp + (size_t)z * bStrideZ;
    const u16* Bl = Blp + (size_t)z * bStrideZ;

    float acc[4][4][4];
#pragma unroll
    for (int i = 0; i < 4; i++)
#pragma unroll
        for (int j = 0; j < 4; j++)
#pragma unroll
            for (int k = 0; k < 4; k++) acc[i][j][k] = 0.0f;

    const int nk = K >> 5;
    stage_load(sb, 0, Ah, Al, Bh, Bl, mBase, nBase, K, 0, tid);
    asm volatile("cp.async.commit_group;");

    // precompute ldmatrix row/swizzle components
    const int arow = (lane & 15);             // A: m row within 16
    const int acb  = (lane >> 4);             // A: k-half bit
    const int brow = (lane & 7) + ((lane >> 4) << 3);  // B: n row within 16
    const int bcb  = (lane >> 3) & 1;         // B: k-half bit

    for (int kt = 0; kt < nk; kt++) {
        if (kt + 1 < nk) {
            stage_load(sb, (kt + 1) & 1, Ah, Al, Bh, Bl, mBase, nBase, K, kt + 1, tid);
            asm volatile("cp.async.commit_group;");
            asm volatile("cp.async.wait_group 1;");
        } else {
            asm volatile("cp.async.wait_group 0;");
        }
        __syncthreads();
        const u32 so = sb + (kt & 1) * 32768;
#pragma unroll
        for (int ks = 0; ks < 2; ks++) {
            u32 a_hi[4][4], a_lo[4][4], b_hi[2][4], b_lo[2][4];
#pragma unroll
            for (int mi = 0; mi < 4; mi++) {
                const int r = rowBase + mi * 16 + arow;
                const int c = ks * 2 + acb;
                const u32 ad = so + r * 64 + ((c ^ ((r >> 1) & 3)) << 4);
                ldsm4(a_hi[mi], ad);
            }
#pragma unroll
            for (int nj = 0; nj < 2; nj++) {
                const int r = colBase + nj * 16 + brow;
                const int c = ks * 2 + bcb;
                const u32 bd = so + 16384 + r * 64 + ((c ^ ((r >> 1) & 3)) << 4);
                ldsm4(b_hi[nj], bd);
                ldsm4(b_lo[nj], bd + 8192);
            }
#pragma unroll
            for (int mi = 0; mi < 4; mi++)
#pragma unroll
                for (int ni = 0; ni < 4; ni++)
                    mma16816(acc[mi][ni], a_hi[mi], &b_hi[ni >> 1][(ni & 1) * 2]);
#pragma unroll
            for (int mi = 0; mi < 4; mi++)
#pragma unroll
                for (int ni = 0; ni < 4; ni++)
                    mma16816(acc[mi][ni], a_hi[mi], &b_lo[ni >> 1][(ni & 1) * 2]);
#pragma unroll
            for (int mi = 0; mi < 4; mi++) {
                const int r = rowBase + mi * 16 + arow;
                const int c = ks * 2 + acb;
                const u32 ad = so + 8192 + r * 64 + ((c ^ ((r >> 1) & 3)) << 4);
                ldsm4(a_lo[mi], ad);
            }
#pragma unroll
            for (int mi = 0; mi < 4; mi++)
#pragma unroll
                for (int ni = 0; ni < 4; ni++)
                    mma16816(acc[mi][ni], a_lo[mi], &b_hi[ni >> 1][(ni & 1) * 2]);
        }
        __syncthreads();
    }

    // ---------------- epilogue ----------------
    const float* bias = (z == 0) ? bias0 : (z == 1) ? bias1 : bias2;
    if (mode == 3) {
#pragma unroll
        for (int mi = 0; mi < 4; mi++) {
#pragma unroll
            for (int h = 0; h < 2; h++) {
                float s = 0.0f;
#pragma unroll
                for (int ni = 0; ni < 4; ni++) {
                    const int n = nBase + colBase + ni * 8 + (lane & 3) * 2;
                    s += tanhf(acc[mi][ni][h * 2])     * vatt[z * 512 + n];
                    s += tanhf(acc[mi][ni][h * 2 + 1]) * vatt[z * 512 + n + 1];
                }
                s += __shfl_xor_sync(0xffffffffu, s, 1);
                s += __shfl_xor_sync(0xffffffffu, s, 2);
                if ((lane & 3) == 0) {
                    const int m = mBase + rowBase + mi * 16 + (lane >> 2) + h * 8;
                    upart[((size_t)(nt * 4 + warpN) * 6 + z) * KBM + m] = s;
                }
            }
        }
        return;
    }
#pragma unroll
    for (int mi = 0; mi < 4; mi++) {
#pragma unroll
        for (int h = 0; h < 2; h++) {
            const int m = mBase + rowBase + mi * 16 + (lane >> 2) + h * 8;
#pragma unroll
            for (int ni = 0; ni < 4; ni++) {
                const int n = nBase + colBase + ni * 8 + (lane & 3) * 2;
                float v0 = acc[mi][ni][h * 2]     + bias[n];
                float v1 = acc[mi][ni][h * 2 + 1] + bias[n + 1];
                const size_t i0 = (size_t)m * 512 + n;
                if (mode == 4) {
                    const float e = p_eng[m];
                    const float wc0 = 1.0f / (1.0f + expf(-v0));
                    const float wc1 = 1.0f / (1.0f + expf(-v1));
                    const float2 cc = *(const float2*)&p_cell[i0];
                    const float2 aa = *(const float2*)&p_arn[i0];
                    const float2 dd = *(const float2*)&p_add[i0];
                    const float uc0 = cc.x + aa.x * dd.x * e;
                    const float uc1 = cc.y + aa.y * dd.y * e;
                    *(float2*)&outC[i0] = make_float2(uc0, uc1);
                    *(float2*)&outH[i0] = make_float2(wc0 * tanhf(uc0), wc1 * tanhf(uc1));
                } else if (mode == 5 && z < 2) {
                    float* pl = (z == 0) ? plain0 : plain1;
                    if (z == 0) { v0 = 1.0f / (1.0f + expf(-v0)); v1 = 1.0f / (1.0f + expf(-v1)); }
                    else        { v0 = tanhf(v0); v1 = tanhf(v1); }
                    *(float2*)&pl[i0] = make_float2(v0, v1);
                } else {  // relu -> bf16 hi/lo planes
                    v0 = fmaxf(v0, 0.0f); v1 = fmaxf(v1, 0.0f);
                    u16 h0, l0, h1, l1;
                    split2(v0, h0, l0); split2(v1, h1, l1);
                    u16* dH = oH + (mode == 5 ? 0 : (size_t)z * oStrideZ);
                    u16* dL = oL + (mode == 5 ? 0 : (size_t)z * oStrideZ);
                    *(u32*)&dH[i0] = (u32)h0 | ((u32)h1 << 16);
                    *(u32*)&dL[i0] = (u32)l0 | ((u32)l1 << 16);
                }
            }
        }
    }
}

// ---------------- prepack weights: w[k][512] -> planes [n][K] ---------------
__global__ void prepack_w(const float* __restrict__ s0, const float* __restrict__ s1,
                          u16* __restrict__ dh, u16* __restrict__ dl, int K) {
    __shared__ float t[32][33];
    const int k0 = blockIdx.x * 32, n0 = blockIdx.y * 32;
    const int tx = threadIdx.x, ty = threadIdx.y;
#pragma unroll
    for (int i = 0; i < 4; i++) {
        const int k = k0 + ty + i * 8;
        t[ty + i * 8][tx] = (k < 512) ? s0[(size_t)k * 512 + n0 + tx]
                                      : s1[(size_t)(k - 512) * 512 + n0 + tx];
    }
    __syncthreads();
#pragma unroll
    for (int i = 0; i < 4; i++) {
        const int n = n0 + ty + i * 8;
        const int k = k0 + tx;
        u16 h, l; split2(t[tx][ty + i * 8], h, l);
        dh[(size_t)n * K + k] = h;
        dl[(size_t)n * K + k] = l;
    }
}

// ---------------- activation converters -------------------------------------
__device__ __forceinline__ void store4(u16* dh, u16* dl, size_t off, float4 v) {
    u16 h0,l0,h1,l1,h2,l2,h3,l3;
    split2(v.x,h0,l0); split2(v.y,h1,l1); split2(v.z,h2,l2); split2(v.w,h3,l3);
    *(u64*)&dh[off] = (u64)h0 | ((u64)h1<<16) | ((u64)h2<<32) | ((u64)h3<<48);
    *(u64*)&dl[off] = (u64)l0 | ((u64)l1<<16) | ((u64)l2<<32) | ((u64)l3<<48);
}
__global__ void convert_info(const float* __restrict__ x, const float* __restrict__ h,
                             u16* __restrict__ dh, u16* __restrict__ dl) {
    const size_t T = (size_t)blockIdx.x * 256 + threadIdx.x;
    const int m = (int)(T >> 8);
    const int k = ((int)T & 255) << 2;
    const float4 v = (k < 512) ? *(const float4*)(x + (size_t)m * 512 + k)
                               : *(const float4*)(h + (size_t)m * 512 + (k - 512));
    store4(dh, dl, (size_t)m * 1024 + k, v);
}
__global__ void convert_att(const float* __restrict__ kbk, const float* __restrict__ q,
                            u16* __restrict__ dh, u16* __restrict__ dl) {
    const int dim = blockIdx.y;
    const size_t T = (size_t)blockIdx.x * 256 + threadIdx.x;
    const int m = (int)(T >> 8);
    const int k = ((int)T & 255) << 2;
    const float4 v = (k < 512)
        ? *(const float4*)(kbk + ((size_t)dim * 4096 + m) * 512 + k)
        : *(const float4*)(q + (size_t)(m >> 5) * 512 + (k - 512));
    store4(dh + (size_t)dim * ATTZ, dl + (size_t)dim * ATTZ, (size_t)m * 1024 + k, v);
}

// ---------------- small kernels ----------------------------------------------
__global__ void eng_kernel(const float* __restrict__ cell, const float* __restrict__ w,
                           float* __restrict__ eng) {
    const int row = blockIdx.x * 8 + (threadIdx.x >> 5);
    const int lane = threadIdx.x & 31;
    const float* c = cell + (size_t)row * HD;
    float s = 0.0f;
#pragma unroll 4
    for (int k = lane; k < HD; k += 32) s += c[k] * w[k];
#pragma unroll
    for (int o = 16; o; o >>= 1) s += __shfl_down_sync(0xffffffffu, s, o);
    if (!lane) eng[row] = s;
}
__global__ void detect_mask_kernel(const unsigned int* __restrict__ w) {
    __shared__ int sF, sG;
    if (threadIdx.x == 0) { sF = 0; sG = 0; }
    __syncthreads();
    int f = 0, g = 0;
    for (int i = threadIdx.x; i < 65536; i += blockDim.x) {
        const unsigned int v = w[i];
        if (v == 0x3F800000u) f = 1;
        else if (v > 1u) g = 1;
    }
    if (f) atomicOr(&sF, 1);
    if (g) atomicOr(&sG, 1);
    __syncthreads();
    if (threadIdx.x == 0) g_maskmode = sF ? 2 : (sG ? 0 : 1);
}
__global__ void utk_kernel(const float* __restrict__ up, const void* __restrict__ maskraw,
                           float* __restrict__ out) {
    __shared__ float S[3][32];
    const int b = blockIdx.y;
    if (threadIdx.x < 96) {
        const int d = threadIdx.x >> 5, i = threadIdx.x & 31;
        float s = 0.0f;
#pragma unroll
        for (int p = 0; p < 16; p++)
#pragma unroll
            for (int hop = 0; hop < 2; hop++)
                s += up[((size_t)p * 6 + hop * 3 + d) * KBM + b * 32 + i];
        S[d][i] = s;
    }
    __syncthreads();
    const int mode = g_maskmode;
    const int j = blockIdx.x * 256 + threadIdx.x;
    const float v = S[0][j >> 10] + S[1][(j >> 5) & 31] + S[2][j & 31];
    const size_t o = (size_t)b * KBTOT + j;
    bool msk;
    if (mode == 0)      msk = ((const unsigned char*)maskraw)[o] != 0;
    else if (mode == 1) msk = ((const int*)maskraw)[o] != 0;
    else                msk = ((const float*)maskraw)[o] != 0.0f;
    out[o] = msk ? 0.0f : v;
}

// ---------------- host ---------------------------------------------------------
extern "C" void kernel_launch(void* const* d_in, const int* in_sizes, int n_in,
                              void* d_out, int out_size) {
    const float* query   = (const float*)d_in[0];
    const float* kb_keys = (const float*)d_in[1];
    const float* Wq      = (const float*)d_in[2];
    const float* Wk      = (const float*)d_in[3];
    const float* v_att   = (const float*)d_in[4];
    const float* x       = (const float*)d_in[5];
    const float* hidden  = (const float*)d_in[6];
    const float* cell    = (const float*)d_in[7];
    const float* arn_w1  = (const float*)d_in[8];
    const float* arn_b1  = (const float*)d_in[9];
    const float* arn_w2  = (const float*)d_in[10];
    const float* arn_b2  = (const float*)d_in[11];
    const float* arn_w3  = (const float*)d_in[12];
    const float* arn_b3  = (const float*)d_in[13];
    const float* add_w1  = (const float*)d_in[14];
    const float* add_b1  = (const float*)d_in[15];
    const float* add_w2  = (const float*)d_in[16];
    const float* add_b2  = (const float*)d_in[17];
    const float* add_w3  = (const float*)d_in[18];
    const float* add_b3  = (const float*)d_in[19];
    const float* eng_w   = (const float*)d_in[20];
    const float* wc_w1   = (const float*)d_in[21];
    const float* wc_b1   = (const float*)d_in[22];
    const float* wc_w2   = (const float*)d_in[23];
    const float* wc_b2   = (const float*)d_in[24];
    const float* wc_w3   = (const float*)d_in[25];
    const float* wc_b3   = (const float*)d_in[26];
    const float* wc_w4   = (const float*)d_in[27];
    const float* wc_b4   = (const float*)d_in[28];
    const void*  kb_mask = d_in[29];

    float* out     = (float*)d_out;
    float* out_utk = out;
    float* outH    = out + (size_t)BSZ * KBTOT;
    float* outC    = outH + (size_t)BT * HD;

    u16 *wbh, *wbl, *atth, *attl, *ah, *al;
    float *arnp, *addp, *upart, *engp;
    cudaGetSymbolAddress((void**)&wbh,  g_wbh);
    cudaGetSymbolAddress((void**)&wbl,  g_wbl);
    cudaGetSymbolAddress((void**)&atth, g_atth);
    cudaGetSymbolAddress((void**)&attl, g_attl);
    cudaGetSymbolAddress((void**)&ah,   g_ah);
    cudaGetSymbolAddress((void**)&al,   g_al);
    cudaGetSymbolAddress((void**)&arnp, g_arn);
    cudaGetSymbolAddress((void**)&addp, g_add);
    cudaGetSymbolAddress((void**)&upart,g_upart);
    cudaGetSymbolAddress((void**)&engp, g_eng);

    static int once = 0;
    if (!once) {
        cudaFuncSetAttribute(gemm_tc, cudaFuncAttributeMaxDynamicSharedMemorySize, 65536);
        once = 1;
    }

    detect_mask_kernel<<<1, 1024>>>((const unsigned int*)kb_mask);

    const dim3 pb(32, 8);
    for (int idx = 0; idx < 6; idx++)
        prepack_w<<<dim3(32, 16), pb>>>(Wk + (size_t)idx * 262144, Wq + (size_t)idx * 262144,
                                        wbh + idx * BIG, wbl + idx * BIG, 1024);
    prepack_w<<<dim3(32, 16), pb>>>(arn_w1, arn_w1 + 262144, wbh + 6 * BIG, wbl + 6 * BIG, 1024);
    prepack_w<<<dim3(32, 16), pb>>>(add_w1, add_w1 + 262144, wbh + 7 * BIG, wbl + 7 * BIG, 1024);
    prepack_w<<<dim3(32, 16), pb>>>(wc_w1,  wc_w1  + 262144, wbh + 8 * BIG, wbl + 8 * BIG, 1024);
    const float* sw[7] = {arn_w2, arn_w3, add_w2, add_w3, wc_w2, wc_w3, wc_w4};
    for (int j = 0; j < 7; j++)
        prepack_w<<<dim3(16, 16), pb>>>(sw[j], sw[j],
                                        wbh + WSOFF + j * SMALL, wbl + WSOFF + j * SMALL, 512);

    convert_info<<<32768, 256>>>(x, hidden, ah, al);
    convert_att<<<dim3(4096, 3), 256>>>(kb_keys, query, atth, attl);
    eng_kernel<<<BT / 8, 256>>>(cell, eng_w, engp);

    // attention
    gemm_tc<<<dim3(4, 32, 6), 256, 65536>>>(
        atth, attl, ATTZ, 3, wbh, wbl, BIG, 1024,
        nullptr, nullptr, nullptr, 3,
        nullptr, nullptr, 0, nullptr, nullptr, v_att, upart,
        nullptr, nullptr, nullptr, nullptr, nullptr, nullptr);
    utk_kernel<<<dim3(KBTOT / 256, BSZ), 256>>>(upart, kb_mask, out_utk);

    // L1: info @ w1 -> h1 planes (relu)
    gemm_tc<<<dim3(4, 256, 3), 256, 65536>>>(
        ah, al, 0, 0, wbh + 6 * BIG, wbl + 6 * BIG, BIG, 1024,
        arn_b1, add_b1, wc_b1, 0,
        ah + H1_OFF, al + H1_OFF, H1S, nullptr, nullptr, nullptr, nullptr,
        nullptr, nullptr, nullptr, nullptr, nullptr, nullptr);
    // L2: h1 @ w2 -> h2 planes (relu)
    gemm_tc<<<dim3(4, 256, 3), 256, 65536>>>(
        ah + H1_OFF, al + H1_OFF, H1S, 0, wbh + WSOFF, wbl + WSOFF, 2 * SMALL, 512,
        arn_b2, add_b2, wc_b2, 0,
        ah + H2_OFF, al + H2_OFF, H1S, nullptr, nullptr, nullptr, nullptr,
        nullptr, nullptr, nullptr, nullptr, nullptr, nullptr);
    // L3: h2 @ w3; z0 sigmoid->arn, z1 tanh->add, z2 relu->h3 planes (h1 slot 0)
    gemm_tc<<<dim3(4, 256, 3), 256, 65536>>>(
        ah + H2_OFF, al + H2_OFF, H1S, 0, wbh + WSOFF + SMALL, wbl + WSOFF + SMALL, 2 * SMALL, 512,
        arn_b3, add_b3, wc_b3, 5,
        ah + H1_OFF, al + H1_OFF, 0, arnp, addp, nullptr, nullptr,
        nullptr, nullptr, nullptr, nullptr, nullptr, nullptr);
    // L4: h3 @ wc_w4 -> fused final epilogue
    gemm_tc<<<dim3(4, 256, 1), 256, 65536>>>(
        ah + H1_OFF, al + H1_OFF, 0, 0, wbh + WSOFF + 6 * SMALL, wbl + WSOFF + 6 * SMALL, SMALL, 512,
        wc_b4, wc_b4, wc_b4, 4,
        nullptr, nullptr, 0, nullptr, nullptr, nullptr, nullptr,
        arnp, addp, cell, engp, outH, outC);
}

// round 6
// speedup vs baseline: 3.4576x; 1.0465x over previous
#include <cuda_runtime.h>
#include <cuda_bf16.h>
#include <cstdint>

#define HD 512
#define BT 32768
#define BSZ 128
#define KBM 4096
#define KBTOT 32768

typedef unsigned int u32;
typedef unsigned long long u64;
typedef unsigned short u16;

// weight plane slot offsets (elements)
#define BIG    524288ULL                  // 512n x 1024k
#define SMALL  262144ULL                  // 512n x 512k
#define W1OFF  0ULL                       // 3 BIG: arn1, add1, wc1
#define WKOFF  (3ULL*BIG)                 // 6 SMALL Wk
#define WQOFF  (WKOFF + 6ULL*SMALL)       // 6 SMALL Wq
#define WSOFF2 (WQOFF + 6ULL*SMALL)       // 7 SMALL: arn2,arn3,add2,add3,wc2,wc3,wc4
#define WTOT   (WSOFF2 + 7ULL*SMALL)

#define ATTZ   2097152ULL                 // 4096 x 512 per dim
#define H1S    16777216ULL                // 32768 x 512
#define H1_OFF 33554432ULL
#define H2_OFF (H1_OFF + 3*H1S)

__device__ u16   g_wbh[WTOT];
__device__ u16   g_wbl[WTOT];
__device__ u16   g_atth[3*ATTZ];
__device__ u16   g_attl[3*ATTZ];
__device__ u16   g_qh[65536];
__device__ u16   g_ql[65536];
__device__ u16   g_ah[134217728];         // info + h1[3] + h2[3]
__device__ u16   g_al[134217728];
__device__ float g_qb[6*128*512];
__device__ float g_arn[(size_t)BT*HD];
__device__ float g_add[(size_t)BT*HD];
__device__ float g_upart[16*6*KBM];
__device__ float g_eng[BT];
__device__ int   g_maskmode;

__device__ __forceinline__ void split2(float v, u16& h, u16& l) {
    __nv_bfloat16 bh = __float2bfloat16(v);
    h = __bfloat16_as_ushort(bh);
    l = __bfloat16_as_ushort(__float2bfloat16(v - __bfloat162float(bh)));
}
__device__ __forceinline__ u32 smem_u32(const void* p) {
    u32 a;
    asm("{ .reg .u64 t; cvta.to.shared.u64 t, %1; cvt.u32.u64 %0, t; }" : "=r"(a) : "l"(p));
    return a;
}
__device__ __forceinline__ void cp16(u32 dst, const void* src) {
    asm volatile("cp.async.cg.shared.global [%0], [%1], 16;" :: "r"(dst), "l"(src));
}
__device__ __forceinline__ void ldsm4(u32* r, u32 a) {
    asm volatile("ldmatrix.sync.aligned.m8n8.x4.shared.b16 {%0,%1,%2,%3}, [%4];"
                 : "=r"(r[0]), "=r"(r[1]), "=r"(r[2]), "=r"(r[3]) : "r"(a));
}
__device__ __forceinline__ void mma16816(float* c, const u32* a, const u32* b) {
    asm volatile("mma.sync.aligned.m16n8k16.row.col.f32.bf16.bf16.f32 "
                 "{%0,%1,%2,%3},{%4,%5,%6,%7},{%8,%9},{%0,%1,%2,%3};"
                 : "+f"(c[0]), "+f"(c[1]), "+f"(c[2]), "+f"(c[3])
                 : "r"(a[0]), "r"(a[1]), "r"(a[2]), "r"(a[3]), "r"(b[0]), "r"(b[1]));
}

// ---------------- stage loader: gmem planes -> swizzled smem slot ------------
__device__ __forceinline__ void stage_load(
    u32 sb, int slot,
    const u16* __restrict__ Ah, const u16* __restrict__ Al,
    const u16* __restrict__ Bh, const u16* __restrict__ Bl,
    int mBase, int nBase, int K, int kt, int tid) {
    const u32 so = sb + slot * 32768;
    const int kOff = kt * 32;
#pragma unroll
    for (int j = 0; j < 2; j++) {
        const int id = tid + j * 256;
        const int r = id >> 2, c = id & 3;
        const u32 dst = so + r * 64 + ((c ^ ((r >> 1) & 3)) << 4);
        const size_t aoff = (size_t)(mBase + r) * K + kOff + c * 8;
        const size_t boff = (size_t)(nBase + r) * K + kOff + c * 8;
        cp16(dst,          Ah + aoff);
        cp16(dst + 8192,   Al + aoff);
        cp16(dst + 16384,  Bh + boff);
        cp16(dst + 24576,  Bl + boff);
    }
}

// ---------------- GEMM: C[M,128tile] = act(A @ B^T + bias) ------------------
// modes: 0 relu->planes, 3 attention, 4 final fused, 5 L3 combo, 6 raw->plain0
__global__ __launch_bounds__(256, 2)
void gemm_tc(const u16* __restrict__ Ahp, const u16* __restrict__ Alp,
             size_t aStrideZ, int aZmod,
             const u16* __restrict__ Bhp, const u16* __restrict__ Blp,
             size_t bStrideZ, int K,
             const float* __restrict__ bias0, const float* __restrict__ bias1,
             const float* __restrict__ bias2, int mode,
             u16* __restrict__ oH, u16* __restrict__ oL, size_t oStrideZ,
             float* __restrict__ plain0, float* __restrict__ plain1,
             const float* __restrict__ vatt, float* __restrict__ upart,
             const float* __restrict__ p_arn, const float* __restrict__ p_add,
             const float* __restrict__ p_cell, const float* __restrict__ p_eng,
             float* __restrict__ outH, float* __restrict__ outC) {
    extern __shared__ char smem[];
    const u32 sb = smem_u32(smem);
    const int tid = threadIdx.x, lane = tid & 31, warp = tid >> 5;
    const int warpM = warp >> 2, warpN = warp & 3;
    const int rowBase = warpM * 64, colBase = warpN * 32;
    const int nt = blockIdx.x, mt = blockIdx.y, z = blockIdx.z;
    const int mBase = mt * 128, nBase = nt * 128;

    const int az = aZmod ? (z % aZmod) : z;
    const u16* Ah = Ahp + (size_t)az * aStrideZ;
    const u16* Al = Alp + (size_t)az * aStrideZ;
    const u16* Bh = Bhp + (size_t)z * bStrideZ;
    const u16* Bl = Blp + (size_t)z * bStrideZ;

    float acc[4][4][4];
#pragma unroll
    for (int i = 0; i < 4; i++)
#pragma unroll
        for (int j = 0; j < 4; j++)
#pragma unroll
            for (int k = 0; k < 4; k++) acc[i][j][k] = 0.0f;

    const int nk = K >> 5;

    // 3-stage pipeline prologue
    stage_load(sb, 0, Ah, Al, Bh, Bl, mBase, nBase, K, 0, tid);
    asm volatile("cp.async.commit_group;");
    stage_load(sb, 1, Ah, Al, Bh, Bl, mBase, nBase, K, 1, tid);
    asm volatile("cp.async.commit_group;");

    const int arow = (lane & 15);
    const int acb  = (lane >> 4);
    const int brow = (lane & 7) + ((lane >> 4) << 3);
    const int bcb  = (lane >> 3) & 1;

    int slot = 0;
    for (int kt = 0; kt < nk; kt++) {
        if (kt + 1 < nk) asm volatile("cp.async.wait_group 1;");
        else             asm volatile("cp.async.wait_group 0;");
        __syncthreads();
        if (kt + 2 < nk) {
            int ps = slot + 2; if (ps >= 3) ps -= 3;
            stage_load(sb, ps, Ah, Al, Bh, Bl, mBase, nBase, K, kt + 2, tid);
            asm volatile("cp.async.commit_group;");
        }
        const u32 so = sb + slot * 32768;
#pragma unroll
        for (int ks = 0; ks < 2; ks++) {
            u32 a_hi[4][4], a_lo[4][4], b_hi[2][4], b_lo[2][4];
#pragma unroll
            for (int mi = 0; mi < 4; mi++) {
                const int r = rowBase + mi * 16 + arow;
                const int c = ks * 2 + acb;
                ldsm4(a_hi[mi], so + r * 64 + ((c ^ ((r >> 1) & 3)) << 4));
            }
#pragma unroll
            for (int nj = 0; nj < 2; nj++) {
                const int r = colBase + nj * 16 + brow;
                const int c = ks * 2 + bcb;
                const u32 bd = so + 16384 + r * 64 + ((c ^ ((r >> 1) & 3)) << 4);
                ldsm4(b_hi[nj], bd);
                ldsm4(b_lo[nj], bd + 8192);
            }
#pragma unroll
            for (int mi = 0; mi < 4; mi++)
#pragma unroll
                for (int ni = 0; ni < 4; ni++)
                    mma16816(acc[mi][ni], a_hi[mi], &b_hi[ni >> 1][(ni & 1) * 2]);
#pragma unroll
            for (int mi = 0; mi < 4; mi++)
#pragma unroll
                for (int ni = 0; ni < 4; ni++)
                    mma16816(acc[mi][ni], a_hi[mi], &b_lo[ni >> 1][(ni & 1) * 2]);
#pragma unroll
            for (int mi = 0; mi < 4; mi++) {
                const int r = rowBase + mi * 16 + arow;
                const int c = ks * 2 + acb;
                ldsm4(a_lo[mi], so + 8192 + r * 64 + ((c ^ ((r >> 1) & 3)) << 4));
            }
#pragma unroll
            for (int mi = 0; mi < 4; mi++)
#pragma unroll
                for (int ni = 0; ni < 4; ni++)
                    mma16816(acc[mi][ni], a_lo[mi], &b_hi[ni >> 1][(ni & 1) * 2]);
        }
        slot++; if (slot == 3) slot = 0;
    }

    // ---------------- epilogue ----------------
    const float* bias = (z == 0) ? bias0 : (z == 1) ? bias1 : bias2;
    if (mode == 3) {
        const float* qbz = plain0 + (size_t)z * 65536;   // qbias[z][128][512]
#pragma unroll
        for (int mi = 0; mi < 4; mi++) {
#pragma unroll
            for (int h = 0; h < 2; h++) {
                const int m = mBase + rowBase + mi * 16 + (lane >> 2) + h * 8;
                const float* qrow = qbz + (size_t)(m >> 5) * 512;
                float s = 0.0f;
#pragma unroll
                for (int ni = 0; ni < 4; ni++) {
                    const int n = nBase + colBase + ni * 8 + (lane & 3) * 2;
                    const float2 qv = *(const float2*)&qrow[n];
                    s += tanhf(acc[mi][ni][h * 2]     + qv.x) * vatt[z * 512 + n];
                    s += tanhf(acc[mi][ni][h * 2 + 1] + qv.y) * vatt[z * 512 + n + 1];
                }
                s += __shfl_xor_sync(0xffffffffu, s, 1);
                s += __shfl_xor_sync(0xffffffffu, s, 2);
                if ((lane & 3) == 0)
                    upart[((size_t)(nt * 4 + warpN) * 6 + z) * KBM + m] = s;
            }
        }
        return;
    }
#pragma unroll
    for (int mi = 0; mi < 4; mi++) {
#pragma unroll
        for (int h = 0; h < 2; h++) {
            const int m = mBase + rowBase + mi * 16 + (lane >> 2) + h * 8;
#pragma unroll
            for (int ni = 0; ni < 4; ni++) {
                const int n = nBase + colBase + ni * 8 + (lane & 3) * 2;
                float v0 = acc[mi][ni][h * 2];
                float v1 = acc[mi][ni][h * 2 + 1];
                if (mode != 6) { v0 += bias[n]; v1 += bias[n + 1]; }
                const size_t i0 = (size_t)m * 512 + n;
                if (mode == 6) {
                    *(float2*)&plain0[(size_t)z * 65536 + i0] = make_float2(v0, v1);
                } else if (mode == 4) {
                    const float e = p_eng[m];
                    const float wc0 = 1.0f / (1.0f + expf(-v0));
                    const float wc1 = 1.0f / (1.0f + expf(-v1));
                    const float2 cc = *(const float2*)&p_cell[i0];
                    const float2 aa = *(const float2*)&p_arn[i0];
                    const float2 dd = *(const float2*)&p_add[i0];
                    const float uc0 = cc.x + aa.x * dd.x * e;
                    const float uc1 = cc.y + aa.y * dd.y * e;
                    *(float2*)&outC[i0] = make_float2(uc0, uc1);
                    *(float2*)&outH[i0] = make_float2(wc0 * tanhf(uc0), wc1 * tanhf(uc1));
                } else if (mode == 5 && z < 2) {
                    float* pl = (z == 0) ? plain0 : plain1;
                    if (z == 0) { v0 = 1.0f / (1.0f + expf(-v0)); v1 = 1.0f / (1.0f + expf(-v1)); }
                    else        { v0 = tanhf(v0); v1 = tanhf(v1); }
                    *(float2*)&pl[i0] = make_float2(v0, v1);
                } else {
                    v0 = fmaxf(v0, 0.0f); v1 = fmaxf(v1, 0.0f);
                    u16 h0, l0, h1, l1;
                    split2(v0, h0, l0); split2(v1, h1, l1);
                    u16* dH = oH + (mode == 5 ? 0 : (size_t)z * oStrideZ);
                    u16* dL = oL + (mode == 5 ? 0 : (size_t)z * oStrideZ);
                    *(u32*)&dH[i0] = (u32)h0 | ((u32)h1 << 16);
                    *(u32*)&dL[i0] = (u32)l0 | ((u32)l1 << 16);
                }
            }
        }
    }
}

// ---------------- merged weight prepack ---------------------------------------
struct PrepackDesc { const float* s0; const float* s1; size_t off; int K; };
struct PrepackParams { PrepackDesc d[22]; };

__global__ void prepack_all(PrepackParams p) {
    __shared__ float t[32][33];
    const PrepackDesc de = p.d[blockIdx.z];
    const int K = de.K;
    const int k0 = blockIdx.x * 32;
    if (k0 >= K) return;
    const int n0 = blockIdx.y * 32;
    const int tx = threadIdx.x, ty = threadIdx.y;
#pragma unroll
    for (int i = 0; i < 4; i++) {
        const int k = k0 + ty + i * 8;
        t[ty + i * 8][tx] = (k < 512) ? de.s0[(size_t)k * 512 + n0 + tx]
                                      : de.s1[(size_t)(k - 512) * 512 + n0 + tx];
    }
    __syncthreads();
#pragma unroll
    for (int i = 0; i < 4; i++) {
        const int n = n0 + ty + i * 8;
        const int k = k0 + tx;
        u16 h, l; split2(t[tx][ty + i * 8], h, l);
        g_wbh[de.off + (size_t)n * K + k] = h;
        g_wbl[de.off + (size_t)n * K + k] = l;
    }
}

// ---------------- activation converters ---------------------------------------
__device__ __forceinline__ void store4(u16* dh, u16* dl, size_t off, float4 v) {
    u16 h0,l0,h1,l1,h2,l2,h3,l3;
    split2(v.x,h0,l0); split2(v.y,h1,l1); split2(v.z,h2,l2); split2(v.w,h3,l3);
    *(u64*)&dh[off] = (u64)h0 | ((u64)h1<<16) | ((u64)h2<<32) | ((u64)h3<<48);
    *(u64*)&dl[off] = (u64)l0 | ((u64)l1<<16) | ((u64)l2<<32) | ((u64)l3<<48);
}
__global__ void convert_info(const float* __restrict__ x, const float* __restrict__ h,
                             u16* __restrict__ dh, u16* __restrict__ dl) {
    const size_t T = (size_t)blockIdx.x * 256 + threadIdx.x;
    const int m = (int)(T >> 8);
    const int k = ((int)T & 255) << 2;
    const float4 v = (k < 512) ? *(const float4*)(x + (size_t)m * 512 + k)
                               : *(const float4*)(h + (size_t)m * 512 + (k - 512));
    store4(dh, dl, (size_t)m * 1024 + k, v);
}
__global__ void convert_att(const float* __restrict__ kbk, const float* __restrict__ q) {
    const int y = blockIdx.y;
    const size_t T = (size_t)blockIdx.x * 256 + threadIdx.x;
    const int m = (int)(T >> 7);
    const int k = ((int)T & 127) << 2;
    if (y < 3) {
        const float4 v = *(const float4*)(kbk + ((size_t)y * 4096 + m) * 512 + k);
        store4(g_atth + (size_t)y * ATTZ, g_attl + (size_t)y * ATTZ, (size_t)m * 512 + k, v);
    } else {
        if (m >= 128) return;
        const float4 v = *(const float4*)(q + (size_t)m * 512 + k);
        store4(g_qh, g_ql, (size_t)m * 512 + k, v);
    }
}

// ---------------- small kernels -------------------------------------------------
__global__ void eng_kernel(const float* __restrict__ cell, const float* __restrict__ w,
                           float* __restrict__ eng) {
    const int row = blockIdx.x * 8 + (threadIdx.x >> 5);
    const int lane = threadIdx.x & 31;
    const float* c = cell + (size_t)row * HD;
    float s = 0.0f;
#pragma unroll 4
    for (int k = lane; k < HD; k += 32) s += c[k] * w[k];
#pragma unroll
    for (int o = 16; o; o >>= 1) s += __shfl_down_sync(0xffffffffu, s, o);
    if (!lane) eng[row] = s;
}
__global__ void detect_mask_kernel(const unsigned int* __restrict__ w) {
    __shared__ int sF, sG;
    if (threadIdx.x == 0) { sF = 0; sG = 0; }
    __syncthreads();
    int f = 0, g = 0;
    for (int i = threadIdx.x; i < 65536; i += blockDim.x) {
        const unsigned int v = w[i];
        if (v == 0x3F800000u) f = 1;
        else if (v > 1u) g = 1;
    }
    if (f) atomicOr(&sF, 1);
    if (g) atomicOr(&sG, 1);
    __syncthreads();
    if (threadIdx.x == 0) g_maskmode = sF ? 2 : (sG ? 0 : 1);
}
__global__ void utk_kernel(const float* __restrict__ up, const void* __restrict__ maskraw,
                           float* __restrict__ out) {
    __shared__ float S[3][32];
    const int b = blockIdx.y;
    if (threadIdx.x < 96) {
        const int d = threadIdx.x >> 5, i = threadIdx.x & 31;
        float s = 0.0f;
#pragma unroll
        for (int p = 0; p < 16; p++)
#pragma unroll
            for (int hop = 0; hop < 2; hop++)
                s += up[((size_t)p * 6 + hop * 3 + d) * KBM + b * 32 + i];
        S[d][i] = s;
    }
    __syncthreads();
    const int mode = g_maskmode;
    const int j = blockIdx.x * 256 + threadIdx.x;
    const float v = S[0][j >> 10] + S[1][(j >> 5) & 31] + S[2][j & 31];
    const size_t o = (size_t)b * KBTOT + j;
    bool msk;
    if (mode == 0)      msk = ((const unsigned char*)maskraw)[o] != 0;
    else if (mode == 1) msk = ((const int*)maskraw)[o] != 0;
    else                msk = ((const float*)maskraw)[o] != 0.0f;
    out[o] = msk ? 0.0f : v;
}

// ---------------- host -----------------------------------------------------------
extern "C" void kernel_launch(void* const* d_in, const int* in_sizes, int n_in,
                              void* d_out, int out_size) {
    const float* query   = (const float*)d_in[0];
    const float* kb_keys = (const float*)d_in[1];
    const float* Wq      = (const float*)d_in[2];
    const float* Wk      = (const float*)d_in[3];
    const float* v_att   = (const float*)d_in[4];
    const float* x       = (const float*)d_in[5];
    const float* hidden  = (const float*)d_in[6];
    const float* cell    = (const float*)d_in[7];
    const float* arn_w1  = (const float*)d_in[8];
    const float* arn_b1  = (const float*)d_in[9];
    const float* arn_w2  = (const float*)d_in[10];
    const float* arn_b2  = (const float*)d_in[11];
    const float* arn_w3  = (const float*)d_in[12];
    const float* arn_b3  = (const float*)d_in[13];
    const float* add_w1  = (const float*)d_in[14];
    const float* add_b1  = (const float*)d_in[15];
    const float* add_w2  = (const float*)d_in[16];
    const float* add_b2  = (const float*)d_in[17];
    const float* add_w3  = (const float*)d_in[18];
    const float* add_b3  = (const float*)d_in[19];
    const float* eng_w   = (const float*)d_in[20];
    const float* wc_w1   = (const float*)d_in[21];
    const float* wc_b1   = (const float*)d_in[22];
    const float* wc_w2   = (const float*)d_in[23];
    const float* wc_b2   = (const float*)d_in[24];
    const float* wc_w3   = (const float*)d_in[25];
    const float* wc_b3   = (const float*)d_in[26];
    const float* wc_w4   = (const float*)d_in[27];
    const float* wc_b4   = (const float*)d_in[28];
    const void*  kb_mask = d_in[29];

    float* out     = (float*)d_out;
    float* out_utk = out;
    float* outH    = out + (size_t)BSZ * KBTOT;
    float* outC    = outH + (size_t)BT * HD;

    u16 *wbh, *wbl, *atth, *attl, *qh, *ql, *ah, *al;
    float *qb, *arnp, *addp, *upart, *engp;
    cudaGetSymbolAddress((void**)&wbh,  g_wbh);
    cudaGetSymbolAddress((void**)&wbl,  g_wbl);
    cudaGetSymbolAddress((void**)&atth, g_atth);
    cudaGetSymbolAddress((void**)&attl, g_attl);
    cudaGetSymbolAddress((void**)&qh,   g_qh);
    cudaGetSymbolAddress((void**)&ql,   g_ql);
    cudaGetSymbolAddress((void**)&ah,   g_ah);
    cudaGetSymbolAddress((void**)&al,   g_al);
    cudaGetSymbolAddress((void**)&qb,   g_qb);
    cudaGetSymbolAddress((void**)&arnp, g_arn);
    cudaGetSymbolAddress((void**)&addp, g_add);
    cudaGetSymbolAddress((void**)&upart,g_upart);
    cudaGetSymbolAddress((void**)&engp, g_eng);

    static int once = 0;
    if (!once) {
        cudaFuncSetAttribute(gemm_tc, cudaFuncAttributeMaxDynamicSharedMemorySize, 98304);
        once = 1;
    }

    // launch 0
    detect_mask_kernel<<<1, 1024>>>((const unsigned int*)kb_mask);

    // launch 1: merged prepack
    PrepackParams pp;
    pp.d[0] = {arn_w1, arn_w1 + 262144, W1OFF + 0 * BIG, 1024};
    pp.d[1] = {add_w1, add_w1 + 262144, W1OFF + 1 * BIG, 1024};
    pp.d[2] = {wc_w1,  wc_w1  + 262144, W1OFF + 2 * BIG, 1024};
    for (int i = 0; i < 6; i++) {
        pp.d[3 + i] = {Wk + (size_t)i * 262144, Wk + (size_t)i * 262144, WKOFF + i * SMALL, 512};
        pp.d[9 + i] = {Wq + (size_t)i * 262144, Wq + (size_t)i * 262144, WQOFF + i * SMALL, 512};
    }
    const float* sw[7] = {arn_w2, arn_w3, add_w2, add_w3, wc_w2, wc_w3, wc_w4};
    for (int j = 0; j < 7; j++)
        pp.d[15 + j] = {sw[j], sw[j], WSOFF2 + j * SMALL, 512};
    prepack_all<<<dim3(32, 16, 22), dim3(32, 8)>>>(pp);

    // launch 2, 3
    convert_info<<<32768, 256>>>(x, hidden, ah, al);
    convert_att<<<dim3(2048, 4), 256>>>(kb_keys, query);

    // launch 4: qbias[z] = query @ Wq[z]  (raw fp32 out)
    gemm_tc<<<dim3(4, 1, 6), 256, 98304>>>(
        qh, ql, 0, 1, wbh + WQOFF, wbl + WQOFF, SMALL, 512,
        nullptr, nullptr, nullptr, 6,
        nullptr, nullptr, 0, qb, nullptr, nullptr, nullptr,
        nullptr, nullptr, nullptr, nullptr, nullptr, nullptr);

    // launch 5: attention (profiled by ncu -s 5 -c 1)
    gemm_tc<<<dim3(4, 32, 6), 256, 98304>>>(
        atth, attl, ATTZ, 3, wbh + WKOFF, wbl + WKOFF, SMALL, 512,
        nullptr, nullptr, nullptr, 3,
        nullptr, nullptr, 0, qb, nullptr, v_att, upart,
        nullptr, nullptr, nullptr, nullptr, nullptr, nullptr);

    utk_kernel<<<dim3(KBTOT / 256, BSZ), 256>>>(upart, kb_mask, out_utk);
    eng_kernel<<<BT / 8, 256>>>(cell, eng_w, engp);

    // L1: info @ w1 -> h1 planes (relu)
    gemm_tc<<<dim3(4, 256, 3), 256, 98304>>>(
        ah, al, 0, 0, wbh + W1OFF, wbl + W1OFF, BIG, 1024,
        arn_b1, add_b1, wc_b1, 0,
        ah + H1_OFF, al + H1_OFF, H1S, nullptr, nullptr, nullptr, nullptr,
        nullptr, nullptr, nullptr, nullptr, nullptr, nullptr);
    // L2: h1 @ w2 -> h2 planes (relu)
    gemm_tc<<<dim3(4, 256, 3), 256, 98304>>>(
        ah + H1_OFF, al + H1_OFF, H1S, 0, wbh + WSOFF2, wbl + WSOFF2, 2 * SMALL, 512,
        arn_b2, add_b2, wc_b2, 0,
        ah + H2_OFF, al + H2_OFF, H1S, nullptr, nullptr, nullptr, nullptr,
        nullptr, nullptr, nullptr, nullptr, nullptr, nullptr);
    // L3: h2 @ w3; z0 sigmoid->arn, z1 tanh->add, z2 relu->h3 planes
    gemm_tc<<<dim3(4, 256, 3), 256, 98304>>>(
        ah + H2_OFF, al + H2_OFF, H1S, 0, wbh + WSOFF2 + SMALL, wbl + WSOFF2 + SMALL, 2 * SMALL, 512,
        arn_b3, add_b3, wc_b3, 5,
        ah + H1_OFF, al + H1_OFF, 0, arnp, addp, nullptr, nullptr,
        nullptr, nullptr, nullptr, nullptr, nullptr, nullptr);
    // L4: h3 @ wc_w4 -> fused final epilogue
    gemm_tc<<<dim3(4, 256, 1), 256, 98304>>>(
        ah + H1_OFF, al + H1_OFF, 0, 0, wbh + WSOFF2 + 6 * SMALL, wbl + WSOFF2 + 6 * SMALL, SMALL, 512,
        wc_b4, wc_b4, wc_b4, 4,
        nullptr, nullptr, 0, nullptr, nullptr, nullptr, nullptr,
        arnp, addp, cell, engp, outH, outC);
}

// round 7
// speedup vs baseline: 3.4681x; 1.0031x over previous
#include <cuda_runtime.h>
#include <cuda_bf16.h>
#include <cstdint>

#define HD 512
#define BT 32768
#define BSZ 128
#define KBM 4096
#define KBTOT 32768

typedef unsigned int u32;
typedef unsigned long long u64;
typedef unsigned short u16;

// weight plane slot offsets (elements)
#define BIG    524288ULL                  // 512n x 1024k
#define SMALL  262144ULL                  // 512n x 512k
#define W1OFF  0ULL                       // 3 BIG: arn1, add1, wc1
#define WKOFF  (3ULL*BIG)                 // 6 SMALL Wk
#define WQOFF  (WKOFF + 6ULL*SMALL)       // 6 SMALL Wq
#define WSOFF2 (WQOFF + 6ULL*SMALL)       // 7 SMALL: arn2,arn3,add2,add3,wc2,wc3,wc4
#define WTOT   (WSOFF2 + 7ULL*SMALL)

#define ATTZ   2097152ULL                 // 4096 x 512 per dim
#define H1S    16777216ULL                // 32768 x 512
#define H1_OFF 33554432ULL
#define H2_OFF (H1_OFF + 3*H1S)

__device__ u16   g_wbh[WTOT];
__device__ u16   g_wbl[WTOT];
__device__ u16   g_atth[3*ATTZ];
__device__ u16   g_attl[3*ATTZ];
__device__ u16   g_qh[65536];
__device__ u16   g_ql[65536];
__device__ u16   g_ah[134217728];         // info + h1[3] + h2[3]
__device__ u16   g_al[134217728];
__device__ float g_qb[6*128*512];
__device__ float g_arn[(size_t)BT*HD];
__device__ float g_add[(size_t)BT*HD];
__device__ float g_upart[16*6*KBM];
__device__ float g_eng[BT];
__device__ int   g_maskmode;

__device__ __forceinline__ void split2(float v, u16& h, u16& l) {
    __nv_bfloat16 bh = __float2bfloat16(v);
    h = __bfloat16_as_ushort(bh);
    l = __bfloat16_as_ushort(__float2bfloat16(v - __bfloat162float(bh)));
}
// packed: hi2 = {bf16(v1)<<16 | bf16(v0)}, lo2 likewise for the residuals
__device__ __forceinline__ void split2x2(float v0, float v1, u32& hi2, u32& lo2) {
    asm("cvt.rn.bf16x2.f32 %0, %1, %2;" : "=r"(hi2) : "f"(v1), "f"(v0));
    const float h0 = __uint_as_float(hi2 << 16);
    const float h1 = __uint_as_float(hi2 & 0xFFFF0000u);
    const float l0 = v0 - h0, l1 = v1 - h1;
    asm("cvt.rn.bf16x2.f32 %0, %1, %2;" : "=r"(lo2) : "f"(l1), "f"(l0));
}
__device__ __forceinline__ u32 smem_u32(const void* p) {
    u32 a;
    asm("{ .reg .u64 t; cvta.to.shared.u64 t, %1; cvt.u32.u64 %0, t; }" : "=r"(a) : "l"(p));
    return a;
}
__device__ __forceinline__ void cp16(u32 dst, const void* src) {
    asm volatile("cp.async.cg.shared.global [%0], [%1], 16;" :: "r"(dst), "l"(src));
}
__device__ __forceinline__ void ldsm4(u32* r, u32 a) {
    asm volatile("ldmatrix.sync.aligned.m8n8.x4.shared.b16 {%0,%1,%2,%3}, [%4];"
                 : "=r"(r[0]), "=r"(r[1]), "=r"(r[2]), "=r"(r[3]) : "r"(a));
}
__device__ __forceinline__ void mma16816(float* c, const u32* a, const u32* b) {
    asm volatile("mma.sync.aligned.m16n8k16.row.col.f32.bf16.bf16.f32 "
                 "{%0,%1,%2,%3},{%4,%5,%6,%7},{%8,%9},{%0,%1,%2,%3};"
                 : "+f"(c[0]), "+f"(c[1]), "+f"(c[2]), "+f"(c[3])
                 : "r"(a[0]), "r"(a[1]), "r"(a[2]), "r"(a[3]), "r"(b[0]), "r"(b[1]));
}

// ---------------- stage loader: gmem planes -> swizzled smem slot ------------
__device__ __forceinline__ void stage_load(
    u32 sb, int slot,
    const u16* __restrict__ Ah, const u16* __restrict__ Al,
    const u16* __restrict__ Bh, const u16* __restrict__ Bl,
    int mBase, int nBase, int K, int kt, int tid) {
    const u32 so = sb + slot * 32768;
    const int kOff = kt * 32;
#pragma unroll
    for (int j = 0; j < 2; j++) {
        const int id = tid + j * 256;
        const int r = id >> 2, c = id & 3;
        const u32 dst = so + r * 64 + ((c ^ ((r >> 1) & 3)) << 4);
        const size_t aoff = (size_t)(mBase + r) * K + kOff + c * 8;
        const size_t boff = (size_t)(nBase + r) * K + kOff + c * 8;
        cp16(dst,          Ah + aoff);
        cp16(dst + 8192,   Al + aoff);
        cp16(dst + 16384,  Bh + boff);
        cp16(dst + 24576,  Bl + boff);
    }
}

// ---------------- GEMM: C[M,128tile] = act(A @ B^T + bias) ------------------
// modes: 0 relu->planes, 3 attention, 4 final fused, 5 L3 combo, 6 raw->plain0
__global__ __launch_bounds__(256, 2)
void gemm_tc(const u16* __restrict__ Ahp, const u16* __restrict__ Alp,
             size_t aStrideZ, int aZmod,
             const u16* __restrict__ Bhp, const u16* __restrict__ Blp,
             size_t bStrideZ, int K,
             const float* __restrict__ bias0, const float* __restrict__ bias1,
             const float* __restrict__ bias2, int mode,
             u16* __restrict__ oH, u16* __restrict__ oL, size_t oStrideZ,
             float* __restrict__ plain0, float* __restrict__ plain1,
             const float* __restrict__ vatt, float* __restrict__ upart,
             const float* __restrict__ p_arn, const float* __restrict__ p_add,
             const float* __restrict__ p_cell, const float* __restrict__ p_eng,
             float* __restrict__ outH, float* __restrict__ outC) {
    extern __shared__ char smem[];
    const u32 sb = smem_u32(smem);
    const int tid = threadIdx.x, lane = tid & 31, warp = tid >> 5;
    const int warpM = warp >> 2, warpN = warp & 3;
    const int rowBase = warpM * 64, colBase = warpN * 32;
    const int nt = blockIdx.x, mt = blockIdx.y, z = blockIdx.z;
    const int mBase = mt * 128, nBase = nt * 128;

    const int az = aZmod ? (z % aZmod) : z;
    const u16* Ah = Ahp + (size_t)az * aStrideZ;
    const u16* Al = Alp + (size_t)az * aStrideZ;
    const u16* Bh = Bhp + (size_t)z * bStrideZ;
    const u16* Bl = Blp + (size_t)z * bStrideZ;

    float acc[4][4][4];
#pragma unroll
    for (int i = 0; i < 4; i++)
#pragma unroll
        for (int j = 0; j < 4; j++)
#pragma unroll
            for (int k = 0; k < 4; k++) acc[i][j][k] = 0.0f;

    const int nk = K >> 5;

    // 3-stage pipeline prologue
    stage_load(sb, 0, Ah, Al, Bh, Bl, mBase, nBase, K, 0, tid);
    asm volatile("cp.async.commit_group;");
    stage_load(sb, 1, Ah, Al, Bh, Bl, mBase, nBase, K, 1, tid);
    asm volatile("cp.async.commit_group;");

    const int arow = (lane & 15);
    const int acb  = (lane >> 4);
    const int brow = (lane & 7) + ((lane >> 4) << 3);
    const int bcb  = (lane >> 3) & 1;

    int slot = 0;
    for (int kt = 0; kt < nk; kt++) {
        if (kt + 1 < nk) asm volatile("cp.async.wait_group 1;");
        else             asm volatile("cp.async.wait_group 0;");
        __syncthreads();
        if (kt + 2 < nk) {
            int ps = slot + 2; if (ps >= 3) ps -= 3;
            stage_load(sb, ps, Ah, Al, Bh, Bl, mBase, nBase, K, kt + 2, tid);
            asm volatile("cp.async.commit_group;");
        }
        const u32 so = sb + slot * 32768;
#pragma unroll
        for (int ks = 0; ks < 2; ks++) {
            u32 a_hi[4][4], a_lo[4][4], b_hi[2][4], b_lo[2][4];
#pragma unroll
            for (int mi = 0; mi < 4; mi++) {
                const int r = rowBase + mi * 16 + arow;
                const int c = ks * 2 + acb;
                ldsm4(a_hi[mi], so + r * 64 + ((c ^ ((r >> 1) & 3)) << 4));
            }
#pragma unroll
            for (int nj = 0; nj < 2; nj++) {
                const int r = colBase + nj * 16 + brow;
                const int c = ks * 2 + bcb;
                const u32 bd = so + 16384 + r * 64 + ((c ^ ((r >> 1) & 3)) << 4);
                ldsm4(b_hi[nj], bd);
                ldsm4(b_lo[nj], bd + 8192);
            }
#pragma unroll
            for (int mi = 0; mi < 4; mi++)
#pragma unroll
                for (int ni = 0; ni < 4; ni++)
                    mma16816(acc[mi][ni], a_hi[mi], &b_hi[ni >> 1][(ni & 1) * 2]);
#pragma unroll
            for (int mi = 0; mi < 4; mi++)
#pragma unroll
                for (int ni = 0; ni < 4; ni++)
                    mma16816(acc[mi][ni], a_hi[mi], &b_lo[ni >> 1][(ni & 1) * 2]);
#pragma unroll
            for (int mi = 0; mi < 4; mi++) {
                const int r = rowBase + mi * 16 + arow;
                const int c = ks * 2 + acb;
                ldsm4(a_lo[mi], so + 8192 + r * 64 + ((c ^ ((r >> 1) & 3)) << 4));
            }
#pragma unroll
            for (int mi = 0; mi < 4; mi++)
#pragma unroll
                for (int ni = 0; ni < 4; ni++)
                    mma16816(acc[mi][ni], a_lo[mi], &b_hi[ni >> 1][(ni & 1) * 2]);
        }
        slot++; if (slot == 3) slot = 0;
    }

    // ---------------- epilogue ----------------
    const float* bias = (z == 0) ? bias0 : (z == 1) ? bias1 : bias2;
    if (mode == 3) {
        const float* qbz = plain0 + (size_t)z * 65536;   // qbias[z][128][512]
#pragma unroll
        for (int mi = 0; mi < 4; mi++) {
#pragma unroll
            for (int h = 0; h < 2; h++) {
                const int m = mBase + rowBase + mi * 16 + (lane >> 2) + h * 8;
                const float* qrow = qbz + (size_t)(m >> 5) * 512;
                float s = 0.0f;
#pragma unroll
                for (int ni = 0; ni < 4; ni++) {
                    const int n = nBase + colBase + ni * 8 + (lane & 3) * 2;
                    const float2 qv = *(const float2*)&qrow[n];
                    s += tanhf(acc[mi][ni][h * 2]     + qv.x) * vatt[z * 512 + n];
                    s += tanhf(acc[mi][ni][h * 2 + 1] + qv.y) * vatt[z * 512 + n + 1];
                }
                s += __shfl_xor_sync(0xffffffffu, s, 1);
                s += __shfl_xor_sync(0xffffffffu, s, 2);
                if ((lane & 3) == 0)
                    upart[((size_t)(nt * 4 + warpN) * 6 + z) * KBM + m] = s;
            }
        }
        return;
    }
#pragma unroll
    for (int mi = 0; mi < 4; mi++) {
#pragma unroll
        for (int h = 0; h < 2; h++) {
            const int m = mBase + rowBase + mi * 16 + (lane >> 2) + h * 8;
#pragma unroll
            for (int ni = 0; ni < 4; ni++) {
                const int n = nBase + colBase + ni * 8 + (lane & 3) * 2;
                float v0 = acc[mi][ni][h * 2];
                float v1 = acc[mi][ni][h * 2 + 1];
                if (mode != 6) { v0 += bias[n]; v1 += bias[n + 1]; }
                const size_t i0 = (size_t)m * 512 + n;
                if (mode == 6) {
                    *(float2*)&plain0[(size_t)z * 65536 + i0] = make_float2(v0, v1);
                } else if (mode == 4) {
                    const float e = p_eng[m];
                    const float wc0 = 1.0f / (1.0f + expf(-v0));
                    const float wc1 = 1.0f / (1.0f + expf(-v1));
                    const float2 cc = *(const float2*)&p_cell[i0];
                    const float2 aa = *(const float2*)&p_arn[i0];
                    const float2 dd = *(const float2*)&p_add[i0];
                    const float uc0 = cc.x + aa.x * dd.x * e;
                    const float uc1 = cc.y + aa.y * dd.y * e;
                    *(float2*)&outC[i0] = make_float2(uc0, uc1);
                    *(float2*)&outH[i0] = make_float2(wc0 * tanhf(uc0), wc1 * tanhf(uc1));
                } else if (mode == 5 && z < 2) {
                    float* pl = (z == 0) ? plain0 : plain1;
                    if (z == 0) { v0 = 1.0f / (1.0f + expf(-v0)); v1 = 1.0f / (1.0f + expf(-v1)); }
                    else        { v0 = tanhf(v0); v1 = tanhf(v1); }
                    *(float2*)&pl[i0] = make_float2(v0, v1);
                } else {
                    v0 = fmaxf(v0, 0.0f); v1 = fmaxf(v1, 0.0f);
                    u32 hi2, lo2;
                    split2x2(v0, v1, hi2, lo2);
                    u16* dH = oH + (mode == 5 ? 0 : (size_t)z * oStrideZ);
                    u16* dL = oL + (mode == 5 ? 0 : (size_t)z * oStrideZ);
                    *(u32*)&dH[i0] = hi2;
                    *(u32*)&dL[i0] = lo2;
                }
            }
        }
    }
}

// ---------------- merged weight prepack ---------------------------------------
struct PrepackDesc { const float* s0; const float* s1; size_t off; int K; };
struct PrepackParams { PrepackDesc d[22]; };

__global__ void prepack_all(PrepackParams p) {
    __shared__ float t[32][33];
    const PrepackDesc de = p.d[blockIdx.z];
    const int K = de.K;
    const int k0 = blockIdx.x * 32;
    if (k0 >= K) return;
    const int n0 = blockIdx.y * 32;
    const int tx = threadIdx.x, ty = threadIdx.y;
#pragma unroll
    for (int i = 0; i < 4; i++) {
        const int k = k0 + ty + i * 8;
        t[ty + i * 8][tx] = (k < 512) ? de.s0[(size_t)k * 512 + n0 + tx]
                                      : de.s1[(size_t)(k - 512) * 512 + n0 + tx];
    }
    __syncthreads();
#pragma unroll
    for (int i = 0; i < 4; i++) {
        const int n = n0 + ty + i * 8;
        const int k = k0 + tx;
        u16 h, l; split2(t[tx][ty + i * 8], h, l);
        g_wbh[de.off + (size_t)n * K + k] = h;
        g_wbl[de.off + (size_t)n * K + k] = l;
    }
}

// ---------------- activation converters ---------------------------------------
__device__ __forceinline__ void store4(u16* dh, u16* dl, size_t off, float4 v) {
    u32 h01, l01, h23, l23;
    split2x2(v.x, v.y, h01, l01);
    split2x2(v.z, v.w, h23, l23);
    *(u64*)&dh[off] = (u64)h01 | ((u64)h23 << 32);
    *(u64*)&dl[off] = (u64)l01 | ((u64)l23 << 32);
}
__global__ void convert_info(const float* __restrict__ x, const float* __restrict__ h,
                             u16* __restrict__ dh, u16* __restrict__ dl) {
    const size_t T = (size_t)blockIdx.x * 256 + threadIdx.x;
    const int m = (int)(T >> 8);
    const int k = ((int)T & 255) << 2;
    const float4 v = (k < 512) ? *(const float4*)(x + (size_t)m * 512 + k)
                               : *(const float4*)(h + (size_t)m * 512 + (k - 512));
    store4(dh, dl, (size_t)m * 1024 + k, v);
}
__global__ void convert_att(const float* __restrict__ kbk, const float* __restrict__ q) {
    const int y = blockIdx.y;
    const size_t T = (size_t)blockIdx.x * 256 + threadIdx.x;
    const int m = (int)(T >> 7);
    const int k = ((int)T & 127) << 2;
    if (y < 3) {
        const float4 v = *(const float4*)(kbk + ((size_t)y * 4096 + m) * 512 + k);
        store4(g_atth + (size_t)y * ATTZ, g_attl + (size_t)y * ATTZ, (size_t)m * 512 + k, v);
    } else {
        if (m >= 128) return;
        const float4 v = *(const float4*)(q + (size_t)m * 512 + k);
        store4(g_qh, g_ql, (size_t)m * 512 + k, v);
    }
}

// ---------------- small kernels -------------------------------------------------
__global__ void eng_kernel(const float* __restrict__ cell, const float* __restrict__ w,
                           float* __restrict__ eng) {
    const int row = blockIdx.x * 8 + (threadIdx.x >> 5);
    const int lane = threadIdx.x & 31;
    const float* c = cell + (size_t)row * HD;
    float s = 0.0f;
#pragma unroll 4
    for (int k = lane; k < HD; k += 32) s += c[k] * w[k];
#pragma unroll
    for (int o = 16; o; o >>= 1) s += __shfl_down_sync(0xffffffffu, s, o);
    if (!lane) eng[row] = s;
}
__global__ void detect_mask_kernel(const unsigned int* __restrict__ w) {
    __shared__ int sF, sG;
    if (threadIdx.x == 0) { sF = 0; sG = 0; }
    __syncthreads();
    int f = 0, g = 0;
    for (int i = threadIdx.x; i < 65536; i += blockDim.x) {
        const unsigned int v = w[i];
        if (v == 0x3F800000u) f = 1;
        else if (v > 1u) g = 1;
    }
    if (f) atomicOr(&sF, 1);
    if (g) atomicOr(&sG, 1);
    __syncthreads();
    if (threadIdx.x == 0) g_maskmode = sF ? 2 : (sG ? 0 : 1);
}
__global__ void utk_kernel(const float* __restrict__ up, const void* __restrict__ maskraw,
                           float* __restrict__ out) {
    __shared__ float S[3][32];
    const int b = blockIdx.y;
    if (threadIdx.x < 96) {
        const int d = threadIdx.x >> 5, i = threadIdx.x & 31;
        float s = 0.0f;
#pragma unroll
        for (int p = 0; p < 16; p++)
#pragma unroll
            for (int hop = 0; hop < 2; hop++)
                s += up[((size_t)p * 6 + hop * 3 + d) * KBM + b * 32 + i];
        S[d][i] = s;
    }
    __syncthreads();
    const int mode = g_maskmode;
    const int j = blockIdx.x * 256 + threadIdx.x;
    const float v = S[0][j >> 10] + S[1][(j >> 5) & 31] + S[2][j & 31];
    const size_t o = (size_t)b * KBTOT + j;
    bool msk;
    if (mode == 0)      msk = ((const unsigned char*)maskraw)[o] != 0;
    else if (mode == 1) msk = ((const int*)maskraw)[o] != 0;
    else                msk = ((const float*)maskraw)[o] != 0.0f;
    out[o] = msk ? 0.0f : v;
}

// ---------------- host -----------------------------------------------------------
extern "C" void kernel_launch(void* const* d_in, const int* in_sizes, int n_in,
                              void* d_out, int out_size) {
    const float* query   = (const float*)d_in[0];
    const float* kb_keys = (const float*)d_in[1];
    const float* Wq      = (const float*)d_in[2];
    const float* Wk      = (const float*)d_in[3];
    const float* v_att   = (const float*)d_in[4];
    const float* x       = (const float*)d_in[5];
    const float* hidden  = (const float*)d_in[6];
    const float* cell    = (const float*)d_in[7];
    const float* arn_w1  = (const float*)d_in[8];
    const float* arn_b1  = (const float*)d_in[9];
    const float* arn_w2  = (const float*)d_in[10];
    const float* arn_b2  = (const float*)d_in[11];
    const float* arn_w3  = (const float*)d_in[12];
    const float* arn_b3  = (const float*)d_in[13];
    const float* add_w1  = (const float*)d_in[14];
    const float* add_b1  = (const float*)d_in[15];
    const float* add_w2  = (const float*)d_in[16];
    const float* add_b2  = (const float*)d_in[17];
    const float* add_w3  = (const float*)d_in[18];
    const float* add_b3  = (const float*)d_in[19];
    const float* eng_w   = (const float*)d_in[20];
    const float* wc_w1   = (const float*)d_in[21];
    const float* wc_b1   = (const float*)d_in[22];
    const float* wc_w2   = (const float*)d_in[23];
    const float* wc_b2   = (const float*)d_in[24];
    const float* wc_w3   = (const float*)d_in[25];
    const float* wc_b3   = (const float*)d_in[26];
    const float* wc_w4   = (const float*)d_in[27];
    const float* wc_b4   = (const float*)d_in[28];
    const void*  kb_mask = d_in[29];

    float* out     = (float*)d_out;
    float* out_utk = out;
    float* outH    = out + (size_t)BSZ * KBTOT;
    float* outC    = outH + (size_t)BT * HD;

    u16 *wbh, *wbl, *atth, *attl, *qh, *ql, *ah, *al;
    float *qb, *arnp, *addp, *upart, *engp;
    cudaGetSymbolAddress((void**)&wbh,  g_wbh);
    cudaGetSymbolAddress((void**)&wbl,  g_wbl);
    cudaGetSymbolAddress((void**)&atth, g_atth);
    cudaGetSymbolAddress((void**)&attl, g_attl);
    cudaGetSymbolAddress((void**)&qh,   g_qh);
    cudaGetSymbolAddress((void**)&ql,   g_ql);
    cudaGetSymbolAddress((void**)&ah,   g_ah);
    cudaGetSymbolAddress((void**)&al,   g_al);
    cudaGetSymbolAddress((void**)&qb,   g_qb);
    cudaGetSymbolAddress((void**)&arnp, g_arn);
    cudaGetSymbolAddress((void**)&addp, g_add);
    cudaGetSymbolAddress((void**)&upart,g_upart);
    cudaGetSymbolAddress((void**)&engp, g_eng);

    static int once = 0;
    if (!once) {
        cudaFuncSetAttribute(gemm_tc, cudaFuncAttributeMaxDynamicSharedMemorySize, 98304);
        once = 1;
    }

    // launch 0: merged prepack
    PrepackParams pp;
    pp.d[0] = {arn_w1, arn_w1 + 262144, W1OFF + 0 * BIG, 1024};
    pp.d[1] = {add_w1, add_w1 + 262144, W1OFF + 1 * BIG, 1024};
    pp.d[2] = {wc_w1,  wc_w1  + 262144, W1OFF + 2 * BIG, 1024};
    for (int i = 0; i < 6; i++) {
        pp.d[3 + i] = {Wk + (size_t)i * 262144, Wk + (size_t)i * 262144, WKOFF + i * SMALL, 512};
        pp.d[9 + i] = {Wq + (size_t)i * 262144, Wq + (size_t)i * 262144, WQOFF + i * SMALL, 512};
    }
    const float* sw[7] = {arn_w2, arn_w3, add_w2, add_w3, wc_w2, wc_w3, wc_w4};
    for (int j = 0; j < 7; j++)
        pp.d[15 + j] = {sw[j], sw[j], WSOFF2 + j * SMALL, 512};
    prepack_all<<<dim3(32, 16, 22), dim3(32, 8)>>>(pp);

    // launch 1: attention operand conversion
    convert_att<<<dim3(2048, 4), 256>>>(kb_keys, query);

    // launch 2: qbias[z] = query @ Wq[z]  (raw fp32 out)
    gemm_tc<<<dim3(4, 1, 6), 256, 98304>>>(
        qh, ql, 0, 1, wbh + WQOFF, wbl + WQOFF, SMALL, 512,
        nullptr, nullptr, nullptr, 6,
        nullptr, nullptr, 0, qb, nullptr, nullptr, nullptr,
        nullptr, nullptr, nullptr, nullptr, nullptr, nullptr);

    // launch 3: attention GEMM  <-- ncu capture index
    gemm_tc<<<dim3(4, 32, 6), 256, 98304>>>(
        atth, attl, ATTZ, 3, wbh + WKOFF, wbl + WKOFF, SMALL, 512,
        nullptr, nullptr, nullptr, 3,
        nullptr, nullptr, 0, qb, nullptr, v_att, upart,
        nullptr, nullptr, nullptr, nullptr, nullptr, nullptr);

    // launch 4-7: small kernels + info conversion
    detect_mask_kernel<<<1, 1024>>>((const unsigned int*)kb_mask);
    convert_info<<<32768, 256>>>(x, hidden, ah, al);
    utk_kernel<<<dim3(KBTOT / 256, BSZ), 256>>>(upart, kb_mask, out_utk);
    eng_kernel<<<BT / 8, 256>>>(cell, eng_w, engp);

    // L1: info @ w1 -> h1 planes (relu)
    gemm_tc<<<dim3(4, 256, 3), 256, 98304>>>(
        ah, al, 0, 0, wbh + W1OFF, wbl + W1OFF, BIG, 1024,
        arn_b1, add_b1, wc_b1, 0,
        ah + H1_OFF, al + H1_OFF, H1S, nullptr, nullptr, nullptr, nullptr,
        nullptr, nullptr, nullptr, nullptr, nullptr, nullptr);
    // L2: h1 @ w2 -> h2 planes (relu)
    gemm_tc<<<dim3(4, 256, 3), 256, 98304>>>(
        ah + H1_OFF, al + H1_OFF, H1S, 0, wbh + WSOFF2, wbl + WSOFF2, 2 * SMALL, 512,
        arn_b2, add_b2, wc_b2, 0,
        ah + H2_OFF, al + H2_OFF, H1S, nullptr, nullptr, nullptr, nullptr,
        nullptr, nullptr, nullptr, nullptr, nullptr, nullptr);
    // L3: h2 @ w3; z0 sigmoid->arn, z1 tanh->add, z2 relu->h3 planes
    gemm_tc<<<dim3(4, 256, 3), 256, 98304>>>(
        ah + H2_OFF, al + H2_OFF, H1S, 0, wbh + WSOFF2 + SMALL, wbl + WSOFF2 + SMALL, 2 * SMALL, 512,
        arn_b3, add_b3, wc_b3, 5,
        ah + H1_OFF, al + H1_OFF, 0, arnp, addp, nullptr, nullptr,
        nullptr, nullptr, nullptr, nullptr, nullptr, nullptr);
    // L4: h3 @ wc_w4 -> fused final epilogue
    gemm_tc<<<dim3(4, 256, 1), 256, 98304>>>(
        ah + H1_OFF, al + H1_OFF, 0, 0, wbh + WSOFF2 + 6 * SMALL, wbl + WSOFF2 + 6 * SMALL, SMALL, 512,
        wc_b4, wc_b4, wc_b4, 4,
        nullptr, nullptr, 0, nullptr, nullptr, nullptr, nullptr,
        arnp, addp, cell, engp, outH, outC);
}

// round 8
// speedup vs baseline: 4.6364x; 1.3368x over previous
#include <cuda_runtime.h>
#include <cuda_fp16.h>
#include <cstdint>

#define HD 512
#define BT 32768
#define BSZ 128
#define KBM 4096
#define KBTOT 32768

typedef unsigned int u32;
typedef unsigned long long u64;
typedef unsigned short u16;

// weight plane slot offsets (elements)
#define BIG    524288ULL                  // 512n x 1024k
#define SMALL  262144ULL                  // 512n x 512k
#define W1OFF  0ULL                       // 3 BIG: arn1, add1, wc1
#define WKOFF  (3ULL*BIG)                 // 6 SMALL Wk
#define WQOFF  (WKOFF + 6ULL*SMALL)       // 6 SMALL Wq
#define WSOFF2 (WQOFF + 6ULL*SMALL)       // 7 SMALL: arn2,arn3,add2,add3,wc2,wc3,wc4
#define WTOT   (WSOFF2 + 7ULL*SMALL)

#define ATTZ   2097152ULL                 // 4096 x 512 per dim
#define H1S    16777216ULL                // 32768 x 512
#define H1_OFF 33554432ULL
#define H2_OFF (H1_OFF + 3*H1S)

__device__ u16   g_wbh[WTOT];
__device__ u16   g_wbl[WTOT];
__device__ u16   g_atth[3*ATTZ];
__device__ u16   g_attl[3*ATTZ];
__device__ u16   g_qh[65536];
__device__ u16   g_ql[65536];
__device__ u16   g_ah[134217728];         // hi planes: info + h1[3] + h2[3] (+h3)
__device__ float g_qb[6*128*512];
__device__ float g_arn[(size_t)BT*HD];
__device__ float g_add[(size_t)BT*HD];
__device__ float g_upart[16*6*KBM];
__device__ float g_eng[BT];
__device__ int   g_maskmode;

__device__ __forceinline__ void split2(float v, u16& h, u16& l) {
    __half hh = __float2half_rn(v);
    h = __half_as_ushort(hh);
    l = __half_as_ushort(__float2half_rn(v - __half2float(hh)));
}
// packed fp16x2: hi2 = {f16(v1)<<16 | f16(v0)}
__device__ __forceinline__ u32 cvt2(float v0, float v1) {
    u32 r;
    asm("cvt.rn.f16x2.f32 %0, %1, %2;" : "=r"(r) : "f"(v1), "f"(v0));
    return r;
}
__device__ __forceinline__ void split2x2(float v0, float v1, u32& hi2, u32& lo2) {
    hi2 = cvt2(v0, v1);
    const float h0 = __half2float(__ushort_as_half((u16)(hi2 & 0xFFFF)));
    const float h1 = __half2float(__ushort_as_half((u16)(hi2 >> 16)));
    lo2 = cvt2(v0 - h0, v1 - h1);
}
__device__ __forceinline__ u32 smem_u32(const void* p) {
    u32 a;
    asm("{ .reg .u64 t; cvta.to.shared.u64 t, %1; cvt.u32.u64 %0, t; }" : "=r"(a) : "l"(p));
    return a;
}
__device__ __forceinline__ void cp16(u32 dst, const void* src) {
    asm volatile("cp.async.cg.shared.global [%0], [%1], 16;" :: "r"(dst), "l"(src));
}
__device__ __forceinline__ void ldsm4(u32* r, u32 a) {
    asm volatile("ldmatrix.sync.aligned.m8n8.x4.shared.b16 {%0,%1,%2,%3}, [%4];"
                 : "=r"(r[0]), "=r"(r[1]), "=r"(r[2]), "=r"(r[3]) : "r"(a));
}
__device__ __forceinline__ void mma16816(float* c, const u32* a, const u32* b) {
    asm volatile("mma.sync.aligned.m16n8k16.row.col.f32.f16.f16.f32 "
                 "{%0,%1,%2,%3},{%4,%5,%6,%7},{%8,%9},{%0,%1,%2,%3};"
                 : "+f"(c[0]), "+f"(c[1]), "+f"(c[2]), "+f"(c[3])
                 : "r"(a[0]), "r"(a[1]), "r"(a[2]), "r"(a[3]), "r"(b[0]), "r"(b[1]));
}

// ---------------- stage loader: gmem planes -> swizzled smem slot ------------
// stage layout: A-hi @0 [, A-lo @8192 if TERMS==3], B-hi, B-lo (8KB each)
template <int TERMS>
__device__ __forceinline__ void stage_load(
    u32 sb, int slot,
    const u16* __restrict__ Ah, const u16* __restrict__ Al,
    const u16* __restrict__ Bh, const u16* __restrict__ Bl,
    int mBase, int nBase, int K, int kt, int tid) {
    constexpr u32 BHI = (TERMS == 3) ? 16384 : 8192;
    constexpr u32 STG = (TERMS == 3) ? 32768 : 24576;
    const u32 so = sb + slot * STG;
    const int kOff = kt * 32;
#pragma unroll
    for (int j = 0; j < 2; j++) {
        const int id = tid + j * 256;
        const int r = id >> 2, c = id & 3;
        const u32 dst = so + r * 64 + ((c ^ ((r >> 1) & 3)) << 4);
        const size_t aoff = (size_t)(mBase + r) * K + kOff + c * 8;
        const size_t boff = (size_t)(nBase + r) * K + kOff + c * 8;
        cp16(dst, Ah + aoff);
        if (TERMS == 3) cp16(dst + 8192, Al + aoff);
        cp16(dst + BHI,        Bh + boff);
        cp16(dst + BHI + 8192, Bl + boff);
    }
}

// ---------------- GEMM: C[M,128tile] = act(A @ B^T + bias) ------------------
// modes: 0 relu->hi plane, 3 attention, 4 final fused, 5 L3 combo, 6 raw->plain0
template <int TERMS>
__global__ __launch_bounds__(256, 2)
void gemm_tc(const u16* __restrict__ Ahp, const u16* __restrict__ Alp,
             size_t aStrideZ, int aZmod,
             const u16* __restrict__ Bhp, const u16* __restrict__ Blp,
             size_t bStrideZ, int K,
             const float* __restrict__ bias0, const float* __restrict__ bias1,
             const float* __restrict__ bias2, int mode,
             u16* __restrict__ oH, size_t oStrideZ,
             float* __restrict__ plain0, float* __restrict__ plain1,
             const float* __restrict__ vatt, float* __restrict__ upart,
             const float* __restrict__ p_arn, const float* __restrict__ p_add,
             const float* __restrict__ p_cell, const float* __restrict__ p_eng,
             float* __restrict__ outH, float* __restrict__ outC) {
    extern __shared__ char smem[];
    const u32 sb = smem_u32(smem);
    const int tid = threadIdx.x, lane = tid & 31, warp = tid >> 5;
    const int warpM = warp >> 2, warpN = warp & 3;
    const int rowBase = warpM * 64, colBase = warpN * 32;
    const int nt = blockIdx.x, mt = blockIdx.y, z = blockIdx.z;
    const int mBase = mt * 128, nBase = nt * 128;

    constexpr u32 BHI = (TERMS == 3) ? 16384 : 8192;
    constexpr u32 STG = (TERMS == 3) ? 32768 : 24576;

    const int az = aZmod ? (z % aZmod) : z;
    const u16* Ah = Ahp + (size_t)az * aStrideZ;
    const u16* Al = (TERMS == 3) ? (Alp + (size_t)az * aStrideZ) : nullptr;
    const u16* Bh = Bhp + (size_t)z * bStrideZ;
    const u16* Bl = Blp + (size_t)z * bStrideZ;

    float acc[4][4][4];
#pragma unroll
    for (int i = 0; i < 4; i++)
#pragma unroll
        for (int j = 0; j < 4; j++)
#pragma unroll
            for (int k = 0; k < 4; k++) acc[i][j][k] = 0.0f;

    const int nk = K >> 5;

    stage_load<TERMS>(sb, 0, Ah, Al, Bh, Bl, mBase, nBase, K, 0, tid);
    asm volatile("cp.async.commit_group;");
    stage_load<TERMS>(sb, 1, Ah, Al, Bh, Bl, mBase, nBase, K, 1, tid);
    asm volatile("cp.async.commit_group;");

    const int arow = (lane & 15);
    const int acb  = (lane >> 4);
    const int brow = (lane & 7) + ((lane >> 4) << 3);
    const int bcb  = (lane >> 3) & 1;

    int slot = 0;
    for (int kt = 0; kt < nk; kt++) {
        if (kt + 1 < nk) asm volatile("cp.async.wait_group 1;");
        else             asm volatile("cp.async.wait_group 0;");
        __syncthreads();
        if (kt + 2 < nk) {
            int ps = slot + 2; if (ps >= 3) ps -= 3;
            stage_load<TERMS>(sb, ps, Ah, Al, Bh, Bl, mBase, nBase, K, kt + 2, tid);
            asm volatile("cp.async.commit_group;");
        }
        const u32 so = sb + slot * STG;
#pragma unroll
        for (int ks = 0; ks < 2; ks++) {
            u32 a_hi[4][4], b_hi[2][4], b_lo[2][4];
#pragma unroll
            for (int mi = 0; mi < 4; mi++) {
                const int r = rowBase + mi * 16 + arow;
                const int c = ks * 2 + acb;
                ldsm4(a_hi[mi], so + r * 64 + ((c ^ ((r >> 1) & 3)) << 4));
            }
#pragma unroll
            for (int nj = 0; nj < 2; nj++) {
                const int r = colBase + nj * 16 + brow;
                const int c = ks * 2 + bcb;
                const u32 bd = so + BHI + r * 64 + ((c ^ ((r >> 1) & 3)) << 4);
                ldsm4(b_hi[nj], bd);
                ldsm4(b_lo[nj], bd + 8192);
            }
#pragma unroll
            for (int mi = 0; mi < 4; mi++)
#pragma unroll
                for (int ni = 0; ni < 4; ni++)
                    mma16816(acc[mi][ni], a_hi[mi], &b_hi[ni >> 1][(ni & 1) * 2]);
#pragma unroll
            for (int mi = 0; mi < 4; mi++)
#pragma unroll
                for (int ni = 0; ni < 4; ni++)
                    mma16816(acc[mi][ni], a_hi[mi], &b_lo[ni >> 1][(ni & 1) * 2]);
            if (TERMS == 3) {
                u32 a_lo[4][4];
#pragma unroll
                for (int mi = 0; mi < 4; mi++) {
                    const int r = rowBase + mi * 16 + arow;
                    const int c = ks * 2 + acb;
                    ldsm4(a_lo[mi], so + 8192 + r * 64 + ((c ^ ((r >> 1) & 3)) << 4));
                }
#pragma unroll
                for (int mi = 0; mi < 4; mi++)
#pragma unroll
                    for (int ni = 0; ni < 4; ni++)
                        mma16816(acc[mi][ni], a_lo[mi], &b_hi[ni >> 1][(ni & 1) * 2]);
            }
        }
        slot++; if (slot == 3) slot = 0;
    }

    // ---------------- epilogue ----------------
    const float* bias = (z == 0) ? bias0 : (z == 1) ? bias1 : bias2;
    if (mode == 3) {
        const float* qbz = plain0 + (size_t)z * 65536;   // qbias[z][128][512]
#pragma unroll
        for (int mi = 0; mi < 4; mi++) {
#pragma unroll
            for (int h = 0; h < 2; h++) {
                const int m = mBase + rowBase + mi * 16 + (lane >> 2) + h * 8;
                const float* qrow = qbz + (size_t)(m >> 5) * 512;
                float s = 0.0f;
#pragma unroll
                for (int ni = 0; ni < 4; ni++) {
                    const int n = nBase + colBase + ni * 8 + (lane & 3) * 2;
                    const float2 qv = *(const float2*)&qrow[n];
                    s += tanhf(acc[mi][ni][h * 2]     + qv.x) * vatt[z * 512 + n];
                    s += tanhf(acc[mi][ni][h * 2 + 1] + qv.y) * vatt[z * 512 + n + 1];
                }
                s += __shfl_xor_sync(0xffffffffu, s, 1);
                s += __shfl_xor_sync(0xffffffffu, s, 2);
                if ((lane & 3) == 0)
                    upart[((size_t)(nt * 4 + warpN) * 6 + z) * KBM + m] = s;
            }
        }
        return;
    }
#pragma unroll
    for (int mi = 0; mi < 4; mi++) {
#pragma unroll
        for (int h = 0; h < 2; h++) {
            const int m = mBase + rowBase + mi * 16 + (lane >> 2) + h * 8;
#pragma unroll
            for (int ni = 0; ni < 4; ni++) {
                const int n = nBase + colBase + ni * 8 + (lane & 3) * 2;
                float v0 = acc[mi][ni][h * 2];
                float v1 = acc[mi][ni][h * 2 + 1];
                if (mode != 6) { v0 += bias[n]; v1 += bias[n + 1]; }
                const size_t i0 = (size_t)m * 512 + n;
                if (mode == 6) {
                    *(float2*)&plain0[(size_t)z * 65536 + i0] = make_float2(v0, v1);
                } else if (mode == 4) {
                    const float e = p_eng[m];
                    const float wc0 = 1.0f / (1.0f + expf(-v0));
                    const float wc1 = 1.0f / (1.0f + expf(-v1));
                    const float2 cc = *(const float2*)&p_cell[i0];
                    const float2 aa = *(const float2*)&p_arn[i0];
                    const float2 dd = *(const float2*)&p_add[i0];
                    const float uc0 = cc.x + aa.x * dd.x * e;
                    const float uc1 = cc.y + aa.y * dd.y * e;
                    *(float2*)&outC[i0] = make_float2(uc0, uc1);
                    *(float2*)&outH[i0] = make_float2(wc0 * tanhf(uc0), wc1 * tanhf(uc1));
                } else if (mode == 5 && z < 2) {
                    float* pl = (z == 0) ? plain0 : plain1;
                    if (z == 0) { v0 = 1.0f / (1.0f + expf(-v0)); v1 = 1.0f / (1.0f + expf(-v1)); }
                    else        { v0 = tanhf(v0); v1 = tanhf(v1); }
                    *(float2*)&pl[i0] = make_float2(v0, v1);
                } else {
                    v0 = fmaxf(v0, 0.0f); v1 = fmaxf(v1, 0.0f);
                    u16* dH = oH + (mode == 5 ? 0 : (size_t)z * oStrideZ);
                    *(u32*)&dH[i0] = cvt2(v0, v1);
                }
            }
        }
    }
}

// ---------------- merged weight prepack ---------------------------------------
struct PrepackDesc { const float* s0; const float* s1; size_t off; int K; };
struct PrepackParams { PrepackDesc d[22]; };

__global__ void prepack_all(PrepackParams p) {
    __shared__ float t[32][33];
    const PrepackDesc de = p.d[blockIdx.z];
    const int K = de.K;
    const int k0 = blockIdx.x * 32;
    if (k0 >= K) return;
    const int n0 = blockIdx.y * 32;
    const int tx = threadIdx.x, ty = threadIdx.y;
#pragma unroll
    for (int i = 0; i < 4; i++) {
        const int k = k0 + ty + i * 8;
        t[ty + i * 8][tx] = (k < 512) ? de.s0[(size_t)k * 512 + n0 + tx]
                                      : de.s1[(size_t)(k - 512) * 512 + n0 + tx];
    }
    __syncthreads();
#pragma unroll
    for (int i = 0; i < 4; i++) {
        const int n = n0 + ty + i * 8;
        const int k = k0 + tx;
        u16 h, l; split2(t[tx][ty + i * 8], h, l);
        g_wbh[de.off + (size_t)n * K + k] = h;
        g_wbl[de.off + (size_t)n * K + k] = l;
    }
}

// ---------------- activation converters ---------------------------------------
__global__ void convert_info(const float* __restrict__ x, const float* __restrict__ h,
                             u16* __restrict__ dh) {
    const size_t T = (size_t)blockIdx.x * 256 + threadIdx.x;
    const int m = (int)(T >> 8);
    const int k = ((int)T & 255) << 2;
    const float4 v = (k < 512) ? *(const float4*)(x + (size_t)m * 512 + k)
                               : *(const float4*)(h + (size_t)m * 512 + (k - 512));
    const u64 hw = (u64)cvt2(v.x, v.y) | ((u64)cvt2(v.z, v.w) << 32);
    *(u64*)&dh[(size_t)m * 1024 + k] = hw;
}
__global__ void convert_att(const float* __restrict__ kbk, const float* __restrict__ q) {
    const int y = blockIdx.y;
    const size_t T = (size_t)blockIdx.x * 256 + threadIdx.x;
    const int m = (int)(T >> 7);
    const int k = ((int)T & 127) << 2;
    float4 v;
    u16 *dh, *dl;
    size_t off = (size_t)m * 512 + k;
    if (y < 3) {
        v = *(const float4*)(kbk + ((size_t)y * 4096 + m) * 512 + k);
        dh = g_atth + (size_t)y * ATTZ; dl = g_attl + (size_t)y * ATTZ;
    } else {
        if (m >= 128) return;
        v = *(const float4*)(q + (size_t)m * 512 + k);
        dh = g_qh; dl = g_ql;
    }
    u32 h01, l01, h23, l23;
    split2x2(v.x, v.y, h01, l01);
    split2x2(v.z, v.w, h23, l23);
    *(u64*)&dh[off] = (u64)h01 | ((u64)h23 << 32);
    *(u64*)&dl[off] = (u64)l01 | ((u64)l23 << 32);
}

// ---------------- small kernels -------------------------------------------------
__global__ void eng_kernel(const float* __restrict__ cell, const float* __restrict__ w,
                           float* __restrict__ eng) {
    const int row = blockIdx.x * 8 + (threadIdx.x >> 5);
    const int lane = threadIdx.x & 31;
    const float* c = cell + (size_t)row * HD;
    float s = 0.0f;
#pragma unroll 4
    for (int k = lane; k < HD; k += 32) s += c[k] * w[k];
#pragma unroll
    for (int o = 16; o; o >>= 1) s += __shfl_down_sync(0xffffffffu, s, o);
    if (!lane) eng[row] = s;
}
__global__ void detect_mask_kernel(const unsigned int* __restrict__ w) {
    __shared__ int sF, sG;
    if (threadIdx.x == 0) { sF = 0; sG = 0; }
    __syncthreads();
    int f = 0, g = 0;
    for (int i = threadIdx.x; i < 65536; i += blockDim.x) {
        const unsigned int v = w[i];
        if (v == 0x3F800000u) f = 1;
        else if (v > 1u) g = 1;
    }
    if (f) atomicOr(&sF, 1);
    if (g) atomicOr(&sG, 1);
    __syncthreads();
    if (threadIdx.x == 0) g_maskmode = sF ? 2 : (sG ? 0 : 1);
}
__global__ void utk_kernel(const float* __restrict__ up, const void* __restrict__ maskraw,
                           float* __restrict__ out) {
    __shared__ float S[3][32];
    const int b = blockIdx.y;
    if (threadIdx.x < 96) {
        const int d = threadIdx.x >> 5, i = threadIdx.x & 31;
        float s = 0.0f;
#pragma unroll
        for (int p = 0; p < 16; p++)
#pragma unroll
            for (int hop = 0; hop < 2; hop++)
                s += up[((size_t)p * 6 + hop * 3 + d) * KBM + b * 32 + i];
        S[d][i] = s;
    }
    __syncthreads();
    const int mode = g_maskmode;
    const int j = blockIdx.x * 256 + threadIdx.x;
    const float v = S[0][j >> 10] + S[1][(j >> 5) & 31] + S[2][j & 31];
    const size_t o = (size_t)b * KBTOT + j;
    bool msk;
    if (mode == 0)      msk = ((const unsigned char*)maskraw)[o] != 0;
    else if (mode == 1) msk = ((const int*)maskraw)[o] != 0;
    else                msk = ((const float*)maskraw)[o] != 0.0f;
    out[o] = msk ? 0.0f : v;
}

// ---------------- host -----------------------------------------------------------
extern "C" void kernel_launch(void* const* d_in, const int* in_sizes, int n_in,
                              void* d_out, int out_size) {
    const float* query   = (const float*)d_in[0];
    const float* kb_keys = (const float*)d_in[1];
    const float* Wq      = (const float*)d_in[2];
    const float* Wk      = (const float*)d_in[3];
    const float* v_att   = (const float*)d_in[4];
    const float* x       = (const float*)d_in[5];
    const float* hidden  = (const float*)d_in[6];
    const float* cell    = (const float*)d_in[7];
    const float* arn_w1  = (const float*)d_in[8];
    const float* arn_b1  = (const float*)d_in[9];
    const float* arn_w2  = (const float*)d_in[10];
    const float* arn_b2  = (const float*)d_in[11];
    const float* arn_w3  = (const float*)d_in[12];
    const float* arn_b3  = (const float*)d_in[13];
    const float* add_w1  = (const float*)d_in[14];
    const float* add_b1  = (const float*)d_in[15];
    const float* add_w2  = (const float*)d_in[16];
    const float* add_b2  = (const float*)d_in[17];
    const float* add_w3  = (const float*)d_in[18];
    const float* add_b3  = (const float*)d_in[19];
    const float* eng_w   = (const float*)d_in[20];
    const float* wc_w1   = (const float*)d_in[21];
    const float* wc_b1   = (const float*)d_in[22];
    const float* wc_w2   = (const float*)d_in[23];
    const float* wc_b2   = (const float*)d_in[24];
    const float* wc_w3   = (const float*)d_in[25];
    const float* wc_b3   = (const float*)d_in[26];
    const float* wc_w4   = (const float*)d_in[27];
    const float* wc_b4   = (const float*)d_in[28];
    const void*  kb_mask = d_in[29];

    float* out     = (float*)d_out;
    float* out_utk = out;
    float* outH    = out + (size_t)BSZ * KBTOT;
    float* outC    = outH + (size_t)BT * HD;

    u16 *wbh, *wbl, *atth, *attl, *qh, *ql, *ah;
    float *qb, *arnp, *addp, *upart, *engp;
    cudaGetSymbolAddress((void**)&wbh,  g_wbh);
    cudaGetSymbolAddress((void**)&wbl,  g_wbl);
    cudaGetSymbolAddress((void**)&atth, g_atth);
    cudaGetSymbolAddress((void**)&attl, g_attl);
    cudaGetSymbolAddress((void**)&qh,   g_qh);
    cudaGetSymbolAddress((void**)&ql,   g_ql);
    cudaGetSymbolAddress((void**)&ah,   g_ah);
    cudaGetSymbolAddress((void**)&qb,   g_qb);
    cudaGetSymbolAddress((void**)&arnp, g_arn);
    cudaGetSymbolAddress((void**)&addp, g_add);
    cudaGetSymbolAddress((void**)&upart,g_upart);
    cudaGetSymbolAddress((void**)&engp, g_eng);

    static int once = 0;
    if (!once) {
        cudaFuncSetAttribute(gemm_tc<3>, cudaFuncAttributeMaxDynamicSharedMemorySize, 98304);
        cudaFuncSetAttribute(gemm_tc<2>, cudaFuncAttributeMaxDynamicSharedMemorySize, 73728);
        once = 1;
    }

    // launch 0: merged prepack
    PrepackParams pp;
    pp.d[0] = {arn_w1, arn_w1 + 262144, W1OFF + 0 * BIG, 1024};
    pp.d[1] = {add_w1, add_w1 + 262144, W1OFF + 1 * BIG, 1024};
    pp.d[2] = {wc_w1,  wc_w1  + 262144, W1OFF + 2 * BIG, 1024};
    for (int i = 0; i < 6; i++) {
        pp.d[3 + i] = {Wk + (size_t)i * 262144, Wk + (size_t)i * 262144, WKOFF + i * SMALL, 512};
        pp.d[9 + i] = {Wq + (size_t)i * 262144, Wq + (size_t)i * 262144, WQOFF + i * SMALL, 512};
    }
    const float* sw[7] = {arn_w2, arn_w3, add_w2, add_w3, wc_w2, wc_w3, wc_w4};
    for (int j = 0; j < 7; j++)
        pp.d[15 + j] = {sw[j], sw[j], WSOFF2 + j * SMALL, 512};
    prepack_all<<<dim3(32, 16, 22), dim3(32, 8)>>>(pp);

    // launch 1: attention operand conversion
    convert_att<<<dim3(2048, 4), 256>>>(kb_keys, query);

    // launch 2: qbias[z] = query @ Wq[z]  (raw fp32 out, 3-term)
    gemm_tc<3><<<dim3(4, 1, 6), 256, 98304>>>(
        qh, ql, 0, 1, wbh + WQOFF, wbl + WQOFF, SMALL, 512,
        nullptr, nullptr, nullptr, 6,
        nullptr, 0, qb, nullptr, nullptr, nullptr,
        nullptr, nullptr, nullptr, nullptr, nullptr, nullptr);

    // launch 3: attention GEMM (3-term)  <-- ncu capture index
    gemm_tc<3><<<dim3(4, 32, 6), 256, 98304>>>(
        atth, attl, ATTZ, 3, wbh + WKOFF, wbl + WKOFF, SMALL, 512,
        nullptr, nullptr, nullptr, 3,
        nullptr, 0, qb, nullptr, v_att, upart,
        nullptr, nullptr, nullptr, nullptr, nullptr, nullptr);

    // launch 4-7: small kernels + info conversion
    detect_mask_kernel<<<1, 1024>>>((const unsigned int*)kb_mask);
    convert_info<<<32768, 256>>>(x, hidden, ah);
    utk_kernel<<<dim3(KBTOT / 256, BSZ), 256>>>(upart, kb_mask, out_utk);
    eng_kernel<<<BT / 8, 256>>>(cell, eng_w, engp);

    // L1: info @ w1 -> h1 hi planes (relu), 2-term
    gemm_tc<2><<<dim3(4, 256, 3), 256, 73728>>>(
        ah, nullptr, 0, 0, wbh + W1OFF, wbl + W1OFF, BIG, 1024,
        arn_b1, add_b1, wc_b1, 0,
        ah + H1_OFF, H1S, nullptr, nullptr, nullptr, nullptr,
        nullptr, nullptr, nullptr, nullptr, nullptr, nullptr);
    // L2: h1 @ w2 -> h2 hi planes (relu)
    gemm_tc<2><<<dim3(4, 256, 3), 256, 73728>>>(
        ah + H1_OFF, nullptr, H1S, 0, wbh + WSOFF2, wbl + WSOFF2, 2 * SMALL, 512,
        arn_b2, add_b2, wc_b2, 0,
        ah + H2_OFF, H1S, nullptr, nullptr, nullptr, nullptr,
        nullptr, nullptr, nullptr, nullptr, nullptr, nullptr);
    // L3: h2 @ w3; z0 sigmoid->arn, z1 tanh->add, z2 relu->h3 plane
    gemm_tc<2><<<dim3(4, 256, 3), 256, 73728>>>(
        ah + H2_OFF, nullptr, H1S, 0, wbh + WSOFF2 + SMALL, wbl + WSOFF2 + SMALL, 2 * SMALL, 512,
        arn_b3, add_b3, wc_b3, 5,
        ah + H1_OFF, 0, arnp, addp, nullptr, nullptr,
        nullptr, nullptr, nullptr, nullptr, nullptr, nullptr);
    // L4: h3 @ wc_w4 -> fused final epilogue
    gemm_tc<2><<<dim3(4, 256, 1), 256, 73728>>>(
        ah + H1_OFF, nullptr, 0, 0, wbh + WSOFF2 + 6 * SMALL, wbl + WSOFF2 + 6 * SMALL, SMALL, 512,
        wc_b4, wc_b4, wc_b4, 4,
        nullptr, 0, nullptr, nullptr, nullptr, nullptr,
        arnp, addp, cell, engp, outH, outC);
}

// round 9
// speedup vs baseline: 5.2243x; 1.1268x over previous
#include <cuda_runtime.h>
#include <cuda_fp16.h>
#include <cstdint>

#define HD 512
#define BT 32768
#define BSZ 128
#define KBM 4096
#define KBTOT 32768

typedef unsigned int u32;
typedef unsigned long long u64;
typedef unsigned short u16;

// weight plane slot offsets (elements)
#define BIG    524288ULL                  // 512n x 1024k
#define SMALL  262144ULL                  // 512n x 512k
#define W1OFF  0ULL                       // 3 BIG: arn1, add1, wc1
#define WKOFF  (3ULL*BIG)                 // 6 SMALL Wk
#define WQOFF  (WKOFF + 6ULL*SMALL)       // 6 SMALL Wq
#define WSOFF2 (WQOFF + 6ULL*SMALL)       // 7 SMALL: arn2,arn3,add2,add3,wc2,wc3,wc4
#define WTOT   (WSOFF2 + 7ULL*SMALL)

#define ATTZ   2097152ULL                 // 4096 x 512 per dim
#define H1S    16777216ULL                // 32768 x 512
#define H1_OFF 33554432ULL
#define H2_OFF (H1_OFF + 3*H1S)

__device__ u16   g_wbh[WTOT];
__device__ u16   g_wbl[WTOT];
__device__ u16   g_atth[3*ATTZ];
__device__ u16   g_qh[65536];
__device__ u16   g_ah[134217728];         // hi planes: info + h1[3] + h2[3] (+h3)
__device__ float g_qb[6*128*512];
__device__ float g_arn[(size_t)BT*HD];
__device__ float g_add[(size_t)BT*HD];
__device__ float g_upart[16*6*KBM];
__device__ float g_eng[BT];
__device__ int   g_maskmode;

__device__ __forceinline__ void split2(float v, u16& h, u16& l) {
    __half hh = __float2half_rn(v);
    h = __half_as_ushort(hh);
    l = __half_as_ushort(__float2half_rn(v - __half2float(hh)));
}
__device__ __forceinline__ u32 cvt2(float v0, float v1) {
    u32 r;
    asm("cvt.rn.f16x2.f32 %0, %1, %2;" : "=r"(r) : "f"(v1), "f"(v0));
    return r;
}
__device__ __forceinline__ u32 smem_u32(const void* p) {
    u32 a;
    asm("{ .reg .u64 t; cvta.to.shared.u64 t, %1; cvt.u32.u64 %0, t; }" : "=r"(a) : "l"(p));
    return a;
}
__device__ __forceinline__ void cp16(u32 dst, const void* src) {
    asm volatile("cp.async.cg.shared.global [%0], [%1], 16;" :: "r"(dst), "l"(src));
}
__device__ __forceinline__ void ldsm4(u32* r, u32 a) {
    asm volatile("ldmatrix.sync.aligned.m8n8.x4.shared.b16 {%0,%1,%2,%3}, [%4];"
                 : "=r"(r[0]), "=r"(r[1]), "=r"(r[2]), "=r"(r[3]) : "r"(a));
}
__device__ __forceinline__ void mma16816(float* c, const u32* a, const u32* b) {
    asm volatile("mma.sync.aligned.m16n8k16.row.col.f32.f16.f16.f32 "
                 "{%0,%1,%2,%3},{%4,%5,%6,%7},{%8,%9},{%0,%1,%2,%3};"
                 : "+f"(c[0]), "+f"(c[1]), "+f"(c[2]), "+f"(c[3])
                 : "r"(a[0]), "r"(a[1]), "r"(a[2]), "r"(a[3]), "r"(b[0]), "r"(b[1]));
}

// ---------------- stage loader: k-tile 64, 128B rows, chunk^(row&7) swizzle --
// stage layout: A-hi @0 (16KB), B-hi @16384, B-lo @32768; stage stride 49152.
__device__ __forceinline__ void stage_load(
    u32 sb, int slot,
    const u16* __restrict__ Ah,
    const u16* __restrict__ Bh, const u16* __restrict__ Bl,
    int mBase, int nBase, int K, int kt, int tid) {
    const u32 so = sb + slot * 49152;
    const int kOff = kt * 64;
#pragma unroll
    for (int j = 0; j < 4; j++) {
        const int id = tid + j * 256;          // 0..1023
        const int r = id >> 3, c = id & 7;
        const u32 dst = so + r * 128 + (((c ^ (r & 7)) & 7) << 4);
        const size_t aoff = (size_t)(mBase + r) * K + kOff + c * 8;
        const size_t boff = (size_t)(nBase + r) * K + kOff + c * 8;
        cp16(dst,          Ah + aoff);
        cp16(dst + 16384,  Bh + boff);
        cp16(dst + 32768,  Bl + boff);
    }
}

// ---------------- GEMM: C[M,128tile] = act(A @ B^T + bias), 2-term fp16 -----
// modes: 0 relu->hi plane, 3 attention, 4 final fused, 5 L3 combo, 6 raw->plain0
__global__ __launch_bounds__(256, 2)
void gemm_tc(const u16* __restrict__ Ahp, size_t aStrideZ, int aZmod,
             const u16* __restrict__ Bhp, const u16* __restrict__ Blp,
             size_t bStrideZ, int K,
             const float* __restrict__ bias0, const float* __restrict__ bias1,
             const float* __restrict__ bias2, int mode,
             u16* __restrict__ oH, size_t oStrideZ,
             float* __restrict__ plain0, float* __restrict__ plain1,
             const float* __restrict__ vatt, float* __restrict__ upart,
             const float* __restrict__ p_arn, const float* __restrict__ p_add,
             const float* __restrict__ p_cell, const float* __restrict__ p_eng,
             float* __restrict__ outH, float* __restrict__ outC) {
    extern __shared__ char smem[];
    const u32 sb = smem_u32(smem);
    const int tid = threadIdx.x, lane = tid & 31, warp = tid >> 5;
    const int warpM = warp >> 2, warpN = warp & 3;
    const int rowBase = warpM * 64, colBase = warpN * 32;
    const int nt = blockIdx.x, mt = blockIdx.y, z = blockIdx.z;
    const int mBase = mt * 128, nBase = nt * 128;

    const int az = aZmod ? (z % aZmod) : z;
    const u16* Ah = Ahp + (size_t)az * aStrideZ;
    const u16* Bh = Bhp + (size_t)z * bStrideZ;
    const u16* Bl = Blp + (size_t)z * bStrideZ;

    float acc[4][4][4];
#pragma unroll
    for (int i = 0; i < 4; i++)
#pragma unroll
        for (int j = 0; j < 4; j++)
#pragma unroll
            for (int k = 0; k < 4; k++) acc[i][j][k] = 0.0f;

    const int nk = K >> 6;

    stage_load(sb, 0, Ah, Bh, Bl, mBase, nBase, K, 0, tid);
    asm volatile("cp.async.commit_group;");

    const int arow = (lane & 15);
    const int acb  = (lane >> 4);
    const int brow = (lane & 7) + ((lane >> 4) << 3);
    const int bcb  = (lane >> 3) & 1;

    int slot = 0;
    for (int kt = 0; kt < nk; kt++) {
        asm volatile("cp.async.wait_group 0;");
        __syncthreads();
        if (kt + 1 < nk) {
            stage_load(sb, slot ^ 1, Ah, Bh, Bl, mBase, nBase, K, kt + 1, tid);
            asm volatile("cp.async.commit_group;");
        }
        const u32 so = sb + slot * 49152;
#pragma unroll
        for (int ks = 0; ks < 4; ks++) {
            u32 a_hi[4][4], b_hi[2][4], b_lo[2][4];
#pragma unroll
            for (int mi = 0; mi < 4; mi++) {
                const int r = rowBase + mi * 16 + arow;
                const int c = ks * 2 + acb;
                ldsm4(a_hi[mi], so + r * 128 + (((c ^ (r & 7)) & 7) << 4));
            }
#pragma unroll
            for (int nj = 0; nj < 2; nj++) {
                const int r = colBase + nj * 16 + brow;
                const int c = ks * 2 + bcb;
                const u32 sw = (((c ^ (r & 7)) & 7) << 4);
                ldsm4(b_hi[nj], so + 16384 + r * 128 + sw);
                ldsm4(b_lo[nj], so + 32768 + r * 128 + sw);
            }
#pragma unroll
            for (int mi = 0; mi < 4; mi++)
#pragma unroll
                for (int ni = 0; ni < 4; ni++)
                    mma16816(acc[mi][ni], a_hi[mi], &b_hi[ni >> 1][(ni & 1) * 2]);
#pragma unroll
            for (int mi = 0; mi < 4; mi++)
#pragma unroll
                for (int ni = 0; ni < 4; ni++)
                    mma16816(acc[mi][ni], a_hi[mi], &b_lo[ni >> 1][(ni & 1) * 2]);
        }
        slot ^= 1;
    }

    // ---------------- epilogue ----------------
    const float* bias = (z == 0) ? bias0 : (z == 1) ? bias1 : bias2;
    if (mode == 3) {
        const float* qbz = plain0 + (size_t)z * 65536;   // qbias[z][128][512]
#pragma unroll
        for (int mi = 0; mi < 4; mi++) {
#pragma unroll
            for (int h = 0; h < 2; h++) {
                const int m = mBase + rowBase + mi * 16 + (lane >> 2) + h * 8;
                const float* qrow = qbz + (size_t)(m >> 5) * 512;
                float s = 0.0f;
#pragma unroll
                for (int ni = 0; ni < 4; ni++) {
                    const int n = nBase + colBase + ni * 8 + (lane & 3) * 2;
                    const float2 qv = *(const float2*)&qrow[n];
                    s += tanhf(acc[mi][ni][h * 2]     + qv.x) * vatt[z * 512 + n];
                    s += tanhf(acc[mi][ni][h * 2 + 1] + qv.y) * vatt[z * 512 + n + 1];
                }
                s += __shfl_xor_sync(0xffffffffu, s, 1);
                s += __shfl_xor_sync(0xffffffffu, s, 2);
                if ((lane & 3) == 0)
                    upart[((size_t)(nt * 4 + warpN) * 6 + z) * KBM + m] = s;
            }
        }
        return;
    }
#pragma unroll
    for (int mi = 0; mi < 4; mi++) {
#pragma unroll
        for (int h = 0; h < 2; h++) {
            const int m = mBase + rowBase + mi * 16 + (lane >> 2) + h * 8;
#pragma unroll
            for (int ni = 0; ni < 4; ni++) {
                const int n = nBase + colBase + ni * 8 + (lane & 3) * 2;
                float v0 = acc[mi][ni][h * 2];
                float v1 = acc[mi][ni][h * 2 + 1];
                if (mode != 6) { v0 += bias[n]; v1 += bias[n + 1]; }
                const size_t i0 = (size_t)m * 512 + n;
                if (mode == 6) {
                    *(float2*)&plain0[(size_t)z * 65536 + i0] = make_float2(v0, v1);
                } else if (mode == 4) {
                    const float e = p_eng[m];
                    const float wc0 = 1.0f / (1.0f + expf(-v0));
                    const float wc1 = 1.0f / (1.0f + expf(-v1));
                    const float2 cc = *(const float2*)&p_cell[i0];
                    const float2 aa = *(const float2*)&p_arn[i0];
                    const float2 dd = *(const float2*)&p_add[i0];
                    const float uc0 = cc.x + aa.x * dd.x * e;
                    const float uc1 = cc.y + aa.y * dd.y * e;
                    *(float2*)&outC[i0] = make_float2(uc0, uc1);
                    *(float2*)&outH[i0] = make_float2(wc0 * tanhf(uc0), wc1 * tanhf(uc1));
                } else if (mode == 5 && z < 2) {
                    float* pl = (z == 0) ? plain0 : plain1;
                    if (z == 0) { v0 = 1.0f / (1.0f + expf(-v0)); v1 = 1.0f / (1.0f + expf(-v1)); }
                    else        { v0 = tanhf(v0); v1 = tanhf(v1); }
                    *(float2*)&pl[i0] = make_float2(v0, v1);
                } else {
                    v0 = fmaxf(v0, 0.0f); v1 = fmaxf(v1, 0.0f);
                    u16* dH = oH + (mode == 5 ? 0 : (size_t)z * oStrideZ);
                    *(u32*)&dH[i0] = cvt2(v0, v1);
                }
            }
        }
    }
}

// ---------------- merged weight prepack ---------------------------------------
struct PrepackDesc { const float* s0; const float* s1; size_t off; int K; };
struct PrepackParams { PrepackDesc d[22]; };

__global__ void prepack_all(PrepackParams p) {
    __shared__ float t[32][33];
    const PrepackDesc de = p.d[blockIdx.z];
    const int K = de.K;
    const int k0 = blockIdx.x * 32;
    if (k0 >= K) return;
    const int n0 = blockIdx.y * 32;
    const int tx = threadIdx.x, ty = threadIdx.y;
#pragma unroll
    for (int i = 0; i < 4; i++) {
        const int k = k0 + ty + i * 8;
        t[ty + i * 8][tx] = (k < 512) ? de.s0[(size_t)k * 512 + n0 + tx]
                                      : de.s1[(size_t)(k - 512) * 512 + n0 + tx];
    }
    __syncthreads();
#pragma unroll
    for (int i = 0; i < 4; i++) {
        const int n = n0 + ty + i * 8;
        const int k = k0 + tx;
        u16 h, l; split2(t[tx][ty + i * 8], h, l);
        g_wbh[de.off + (size_t)n * K + k] = h;
        g_wbl[de.off + (size_t)n * K + k] = l;
    }
}

// ---------------- activation converters ---------------------------------------
__global__ void convert_info(const float* __restrict__ x, const float* __restrict__ h,
                             u16* __restrict__ dh) {
    const size_t T = (size_t)blockIdx.x * 256 + threadIdx.x;
    const int m = (int)(T >> 8);
    const int k = ((int)T & 255) << 2;
    const float4 v = (k < 512) ? *(const float4*)(x + (size_t)m * 512 + k)
                               : *(const float4*)(h + (size_t)m * 512 + (k - 512));
    const u64 hw = (u64)cvt2(v.x, v.y) | ((u64)cvt2(v.z, v.w) << 32);
    *(u64*)&dh[(size_t)m * 1024 + k] = hw;
}
__global__ void convert_att(const float* __restrict__ kbk, const float* __restrict__ q) {
    const int y = blockIdx.y;
    const size_t T = (size_t)blockIdx.x * 256 + threadIdx.x;
    const int m = (int)(T >> 7);
    const int k = ((int)T & 127) << 2;
    float4 v;
    u16* dh;
    const size_t off = (size_t)m * 512 + k;
    if (y < 3) {
        v = *(const float4*)(kbk + ((size_t)y * 4096 + m) * 512 + k);
        dh = g_atth + (size_t)y * ATTZ;
    } else {
        if (m >= 128) return;
        v = *(const float4*)(q + (size_t)m * 512 + k);
        dh = g_qh;
    }
    const u64 hw = (u64)cvt2(v.x, v.y) | ((u64)cvt2(v.z, v.w) << 32);
    *(u64*)&dh[off] = hw;
}

// ---------------- small kernels -------------------------------------------------
__global__ void eng_kernel(const float* __restrict__ cell, const float* __restrict__ w,
                           float* __restrict__ eng) {
    const int row = blockIdx.x * 8 + (threadIdx.x >> 5);
    const int lane = threadIdx.x & 31;
    const float* c = cell + (size_t)row * HD;
    float s = 0.0f;
#pragma unroll 4
    for (int k = lane; k < HD; k += 32) s += c[k] * w[k];
#pragma unroll
    for (int o = 16; o; o >>= 1) s += __shfl_down_sync(0xffffffffu, s, o);
    if (!lane) eng[row] = s;
}
__global__ void detect_mask_kernel(const unsigned int* __restrict__ w) {
    __shared__ int sF, sG;
    if (threadIdx.x == 0) { sF = 0; sG = 0; }
    __syncthreads();
    int f = 0, g = 0;
    for (int i = threadIdx.x; i < 65536; i += blockDim.x) {
        const unsigned int v = w[i];
        if (v == 0x3F800000u) f = 1;
        else if (v > 1u) g = 1;
    }
    if (f) atomicOr(&sF, 1);
    if (g) atomicOr(&sG, 1);
    __syncthreads();
    if (threadIdx.x == 0) g_maskmode = sF ? 2 : (sG ? 0 : 1);
}
__global__ void utk_kernel(const float* __restrict__ up, const void* __restrict__ maskraw,
                           float* __restrict__ out) {
    __shared__ float S[3][32];
    const int b = blockIdx.y;
    if (threadIdx.x < 96) {
        const int d = threadIdx.x >> 5, i = threadIdx.x & 31;
        float s = 0.0f;
#pragma unroll
        for (int p = 0; p < 16; p++)
#pragma unroll
            for (int hop = 0; hop < 2; hop++)
                s += up[((size_t)p * 6 + hop * 3 + d) * KBM + b * 32 + i];
        S[d][i] = s;
    }
    __syncthreads();
    const int mode = g_maskmode;
    const int j = blockIdx.x * 256 + threadIdx.x;
    const float v = S[0][j >> 10] + S[1][(j >> 5) & 31] + S[2][j & 31];
    const size_t o = (size_t)b * KBTOT + j;
    bool msk;
    if (mode == 0)      msk = ((const unsigned char*)maskraw)[o] != 0;
    else if (mode == 1) msk = ((const int*)maskraw)[o] != 0;
    else                msk = ((const float*)maskraw)[o] != 0.0f;
    out[o] = msk ? 0.0f : v;
}

// ---------------- host -----------------------------------------------------------
extern "C" void kernel_launch(void* const* d_in, const int* in_sizes, int n_in,
                              void* d_out, int out_size) {
    const float* query   = (const float*)d_in[0];
    const float* kb_keys = (const float*)d_in[1];
    const float* Wq      = (const float*)d_in[2];
    const float* Wk      = (const float*)d_in[3];
    const float* v_att   = (const float*)d_in[4];
    const float* x       = (const float*)d_in[5];
    const float* hidden  = (const float*)d_in[6];
    const float* cell    = (const float*)d_in[7];
    const float* arn_w1  = (const float*)d_in[8];
    const float* arn_b1  = (const float*)d_in[9];
    const float* arn_w2  = (const float*)d_in[10];
    const float* arn_b2  = (const float*)d_in[11];
    const float* arn_w3  = (const float*)d_in[12];
    const float* arn_b3  = (const float*)d_in[13];
    const float* add_w1  = (const float*)d_in[14];
    const float* add_b1  = (const float*)d_in[15];
    const float* add_w2  = (const float*)d_in[16];
    const float* add_b2  = (const float*)d_in[17];
    const float* add_w3  = (const float*)d_in[18];
    const float* add_b3  = (const float*)d_in[19];
    const float* eng_w   = (const float*)d_in[20];
    const float* wc_w1   = (const float*)d_in[21];
    const float* wc_b1   = (const float*)d_in[22];
    const float* wc_w2   = (const float*)d_in[23];
    const float* wc_b2   = (const float*)d_in[24];
    const float* wc_w3   = (const float*)d_in[25];
    const float* wc_b3   = (const float*)d_in[26];
    const float* wc_w4   = (const float*)d_in[27];
    const float* wc_b4   = (const float*)d_in[28];
    const void*  kb_mask = d_in[29];

    float* out     = (float*)d_out;
    float* out_utk = out;
    float* outH    = out + (size_t)BSZ * KBTOT;
    float* outC    = outH + (size_t)BT * HD;

    u16 *wbh, *wbl, *atth, *qh, *ah;
    float *qb, *arnp, *addp, *upart, *engp;
    cudaGetSymbolAddress((void**)&wbh,  g_wbh);
    cudaGetSymbolAddress((void**)&wbl,  g_wbl);
    cudaGetSymbolAddress((void**)&atth, g_atth);
    cudaGetSymbolAddress((void**)&qh,   g_qh);
    cudaGetSymbolAddress((void**)&ah,   g_ah);
    cudaGetSymbolAddress((void**)&qb,   g_qb);
    cudaGetSymbolAddress((void**)&arnp, g_arn);
    cudaGetSymbolAddress((void**)&addp, g_add);
    cudaGetSymbolAddress((void**)&upart,g_upart);
    cudaGetSymbolAddress((void**)&engp, g_eng);

    static int once = 0;
    if (!once) {
        cudaFuncSetAttribute(gemm_tc, cudaFuncAttributeMaxDynamicSharedMemorySize, 98304);
        once = 1;
    }

    // launch 0: merged prepack
    PrepackParams pp;
    pp.d[0] = {arn_w1, arn_w1 + 262144, W1OFF + 0 * BIG, 1024};
    pp.d[1] = {add_w1, add_w1 + 262144, W1OFF + 1 * BIG, 1024};
    pp.d[2] = {wc_w1,  wc_w1  + 262144, W1OFF + 2 * BIG, 1024};
    for (int i = 0; i < 6; i++) {
        pp.d[3 + i] = {Wk + (size_t)i * 262144, Wk + (size_t)i * 262144, WKOFF + i * SMALL, 512};
        pp.d[9 + i] = {Wq + (size_t)i * 262144, Wq + (size_t)i * 262144, WQOFF + i * SMALL, 512};
    }
    const float* sw[7] = {arn_w2, arn_w3, add_w2, add_w3, wc_w2, wc_w3, wc_w4};
    for (int j = 0; j < 7; j++)
        pp.d[15 + j] = {sw[j], sw[j], WSOFF2 + j * SMALL, 512};
    prepack_all<<<dim3(32, 16, 22), dim3(32, 8)>>>(pp);

    // launch 1: attention operand conversion (hi planes only)
    convert_att<<<dim3(2048, 4), 256>>>(kb_keys, query);

    // launch 2: qbias[z] = query @ Wq[z]  (raw fp32 out)
    gemm_tc<<<dim3(4, 1, 6), 256, 98304>>>(
        qh, 0, 1, wbh + WQOFF, wbl + WQOFF, SMALL, 512,
        nullptr, nullptr, nullptr, 6,
        nullptr, 0, qb, nullptr, nullptr, nullptr,
        nullptr, nullptr, nullptr, nullptr, nullptr, nullptr);

    // launch 3: attention GEMM  <-- ncu capture index
    gemm_tc<<<dim3(4, 32, 6), 256, 98304>>>(
        atth, ATTZ, 3, wbh + WKOFF, wbl + WKOFF, SMALL, 512,
        nullptr, nullptr, nullptr, 3,
        nullptr, 0, qb, nullptr, v_att, upart,
        nullptr, nullptr, nullptr, nullptr, nullptr, nullptr);

    // launch 4-7: small kernels + info conversion
    detect_mask_kernel<<<1, 1024>>>((const unsigned int*)kb_mask);
    convert_info<<<32768, 256>>>(x, hidden, ah);
    utk_kernel<<<dim3(KBTOT / 256, BSZ), 256>>>(upart, kb_mask, out_utk);
    eng_kernel<<<BT / 8, 256>>>(cell, eng_w, engp);

    // L1: info @ w1 -> h1 hi planes (relu)
    gemm_tc<<<dim3(4, 256, 3), 256, 98304>>>(
        ah, 0, 0, wbh + W1OFF, wbl + W1OFF, BIG, 1024,
        arn_b1, add_b1, wc_b1, 0,
        ah + H1_OFF, H1S, nullptr, nullptr, nullptr, nullptr,
        nullptr, nullptr, nullptr, nullptr, nullptr, nullptr);
    // L2: h1 @ w2 -> h2 hi planes (relu)
    gemm_tc<<<dim3(4, 256, 3), 256, 98304>>>(
        ah + H1_OFF, H1S, 0, wbh + WSOFF2, wbl + WSOFF2, 2 * SMALL, 512,
        arn_b2, add_b2, wc_b2, 0,
        ah + H2_OFF, H1S, nullptr, nullptr, nullptr, nullptr,
        nullptr, nullptr, nullptr, nullptr, nullptr, nullptr);
    // L3: h2 @ w3; z0 sigmoid->arn, z1 tanh->add, z2 relu->h3 plane
    gemm_tc<<<dim3(4, 256, 3), 256, 98304>>>(
        ah + H2_OFF, H1S, 0, wbh + WSOFF2 + SMALL, wbl + WSOFF2 + SMALL, 2 * SMALL, 512,
        arn_b3, add_b3, wc_b3, 5,
        ah + H1_OFF, 0, arnp, addp, nullptr, nullptr,
        nullptr, nullptr, nullptr, nullptr, nullptr, nullptr);
    // L4: h3 @ wc_w4 -> fused final epilogue
    gemm_tc<<<dim3(4, 256, 1), 256, 98304>>>(
        ah + H1_OFF, 0, 0, wbh + WSOFF2 + 6 * SMALL, wbl + WSOFF2 + 6 * SMALL, SMALL, 512,
        wc_b4, wc_b4, wc_b4, 4,
        nullptr, 0, nullptr, nullptr, nullptr, nullptr,
        arnp, addp, cell, engp, outH, outC);
}

// round 10
// speedup vs baseline: 7.5064x; 1.4368x over previous
#include <cuda_runtime.h>
#include <cuda_fp16.h>
#include <cstdint>

#define HD 512
#define BT 32768
#define BSZ 128
#define KBM 4096
#define KBTOT 32768

typedef unsigned int u32;
typedef unsigned long long u64;
typedef unsigned short u16;

// weight plane slot offsets (elements)
#define BIG    524288ULL                  // 512n x 1024k
#define SMALL  262144ULL                  // 512n x 512k
#define W1OFF  0ULL                       // 3 BIG: arn1, add1, wc1
#define WKOFF  (3ULL*BIG)                 // 6 SMALL Wk
#define WQOFF  (WKOFF + 6ULL*SMALL)       // 6 SMALL Wq
#define WSOFF2 (WQOFF + 6ULL*SMALL)       // 7 SMALL: arn2,arn3,add2,add3,wc2,wc3,wc4
#define WTOT   (WSOFF2 + 7ULL*SMALL)

#define ATTZ   2097152ULL                 // 4096 x 512 per dim
#define H1S    16777216ULL                // 32768 x 512
#define H1_OFF 33554432ULL
#define H2_OFF (H1_OFF + 3*H1S)

__device__ u16   g_wbh[WTOT];
__device__ u16   g_wbl[WTOT];
__device__ u16   g_atth[3*ATTZ];
__device__ u16   g_qh[65536];
__device__ u16   g_ah[134217728];         // hi planes: info + h1[3] + h2[3] (+h3)
__device__ float g_qb[6*128*512];
__device__ float g_arn[(size_t)BT*HD];
__device__ float g_add[(size_t)BT*HD];
__device__ float g_upart[16*6*KBM];
__device__ float g_eng[BT];
__device__ int   g_maskmode;

__device__ __forceinline__ void split2(float v, u16& h, u16& l) {
    __half hh = __float2half_rn(v);
    h = __half_as_ushort(hh);
    l = __half_as_ushort(__float2half_rn(v - __half2float(hh)));
}
__device__ __forceinline__ u32 cvt2(float v0, float v1) {
    u32 r;
    asm("cvt.rn.f16x2.f32 %0, %1, %2;" : "=r"(r) : "f"(v1), "f"(v0));
    return r;
}
__device__ __forceinline__ u32 smem_u32(const void* p) {
    u32 a;
    asm("{ .reg .u64 t; cvta.to.shared.u64 t, %1; cvt.u32.u64 %0, t; }" : "=r"(a) : "l"(p));
    return a;
}
__device__ __forceinline__ void cp16(u32 dst, const void* src) {
    asm volatile("cp.async.cg.shared.global [%0], [%1], 16;" :: "r"(dst), "l"(src));
}
__device__ __forceinline__ void ldsm4(u32* r, u32 a) {
    asm volatile("ldmatrix.sync.aligned.m8n8.x4.shared.b16 {%0,%1,%2,%3}, [%4];"
                 : "=r"(r[0]), "=r"(r[1]), "=r"(r[2]), "=r"(r[3]) : "r"(a));
}
__device__ __forceinline__ void mma16816(float* c, const u32* a, const u32* b) {
    asm volatile("mma.sync.aligned.m16n8k16.row.col.f32.f16.f16.f32 "
                 "{%0,%1,%2,%3},{%4,%5,%6,%7},{%8,%9},{%0,%1,%2,%3};"
                 : "+f"(c[0]), "+f"(c[1]), "+f"(c[2]), "+f"(c[3])
                 : "r"(a[0]), "r"(a[1]), "r"(a[2]), "r"(a[3]), "r"(b[0]), "r"(b[1]));
}

// ---------------- stage loader: k-tile 64, 128B rows, chunk^(row&7) swizzle --
// BTERMS==2: A-hi @0, B-hi @16384, B-lo @32768; stride 49152.
// BTERMS==1: A-hi @0, B-hi @16384;               stride 32768.
template <int BTERMS>
__device__ __forceinline__ void stage_load(
    u32 sb, int slot,
    const u16* __restrict__ Ah,
    const u16* __restrict__ Bh, const u16* __restrict__ Bl,
    int mBase, int nBase, int K, int kt, int tid) {
    constexpr u32 STG = (BTERMS == 2) ? 49152 : 32768;
    const u32 so = sb + slot * STG;
    const int kOff = kt * 64;
#pragma unroll
    for (int j = 0; j < 4; j++) {
        const int id = tid + j * 256;          // 0..1023
        const int r = id >> 3, c = id & 7;
        const u32 dst = so + r * 128 + (((c ^ (r & 7)) & 7) << 4);
        const size_t aoff = (size_t)(mBase + r) * K + kOff + c * 8;
        const size_t boff = (size_t)(nBase + r) * K + kOff + c * 8;
        cp16(dst,          Ah + aoff);
        cp16(dst + 16384,  Bh + boff);
        if (BTERMS == 2) cp16(dst + 32768, Bl + boff);
    }
}

// ---------------- GEMM: C[M,128tile] = act(A @ B^T + bias), fp16 ------------
// modes: 0 relu->hi plane, 3 attention, 4 final fused, 5 L3 combo, 6 raw->plain0
template <int BTERMS>
__global__ __launch_bounds__(256, 2)
void gemm_tc(const u16* __restrict__ Ahp, size_t aStrideZ, int aZmod,
             const u16* __restrict__ Bhp, const u16* __restrict__ Blp,
             size_t bStrideZ, int K,
             const float* __restrict__ bias0, const float* __restrict__ bias1,
             const float* __restrict__ bias2, int mode,
             u16* __restrict__ oH, size_t oStrideZ,
             float* __restrict__ plain0, float* __restrict__ plain1,
             const float* __restrict__ vatt, float* __restrict__ upart,
             const float* __restrict__ p_arn, const float* __restrict__ p_add,
             const float* __restrict__ p_cell, const float* __restrict__ p_eng,
             float* __restrict__ outH, float* __restrict__ outC) {
    extern __shared__ char smem[];
    const u32 sb = smem_u32(smem);
    const int tid = threadIdx.x, lane = tid & 31, warp = tid >> 5;
    const int warpM = warp >> 2, warpN = warp & 3;
    const int rowBase = warpM * 64, colBase = warpN * 32;
    const int nt = blockIdx.x, mt = blockIdx.y, z = blockIdx.z;
    const int mBase = mt * 128, nBase = nt * 128;
    constexpr u32 STG = (BTERMS == 2) ? 49152 : 32768;

    const int az = aZmod ? (z % aZmod) : z;
    const u16* Ah = Ahp + (size_t)az * aStrideZ;
    const u16* Bh = Bhp + (size_t)z * bStrideZ;
    const u16* Bl = Blp + (size_t)z * bStrideZ;

    float acc[4][4][4];
#pragma unroll
    for (int i = 0; i < 4; i++)
#pragma unroll
        for (int j = 0; j < 4; j++)
#pragma unroll
            for (int k = 0; k < 4; k++) acc[i][j][k] = 0.0f;

    const int nk = K >> 6;

    stage_load<BTERMS>(sb, 0, Ah, Bh, Bl, mBase, nBase, K, 0, tid);
    asm volatile("cp.async.commit_group;");

    const int arow = (lane & 15);
    const int acb  = (lane >> 4);
    const int brow = (lane & 7) + ((lane >> 4) << 3);
    const int bcb  = (lane >> 3) & 1;

    int slot = 0;
    for (int kt = 0; kt < nk; kt++) {
        asm volatile("cp.async.wait_group 0;");
        __syncthreads();
        if (kt + 1 < nk) {
            stage_load<BTERMS>(sb, slot ^ 1, Ah, Bh, Bl, mBase, nBase, K, kt + 1, tid);
            asm volatile("cp.async.commit_group;");
        }
        const u32 so = sb + slot * STG;
#pragma unroll
        for (int ks = 0; ks < 4; ks++) {
            u32 a_hi[4][4], b_hi[2][4], b_lo[2][4];
#pragma unroll
            for (int mi = 0; mi < 4; mi++) {
                const int r = rowBase + mi * 16 + arow;
                const int c = ks * 2 + acb;
                ldsm4(a_hi[mi], so + r * 128 + (((c ^ (r & 7)) & 7) << 4));
            }
#pragma unroll
            for (int nj = 0; nj < 2; nj++) {
                const int r = colBase + nj * 16 + brow;
                const int c = ks * 2 + bcb;
                const u32 sw = (((c ^ (r & 7)) & 7) << 4);
                ldsm4(b_hi[nj], so + 16384 + r * 128 + sw);
                if (BTERMS == 2) ldsm4(b_lo[nj], so + 32768 + r * 128 + sw);
            }
#pragma unroll
            for (int mi = 0; mi < 4; mi++)
#pragma unroll
                for (int ni = 0; ni < 4; ni++)
                    mma16816(acc[mi][ni], a_hi[mi], &b_hi[ni >> 1][(ni & 1) * 2]);
            if (BTERMS == 2) {
#pragma unroll
                for (int mi = 0; mi < 4; mi++)
#pragma unroll
                    for (int ni = 0; ni < 4; ni++)
                        mma16816(acc[mi][ni], a_hi[mi], &b_lo[ni >> 1][(ni & 1) * 2]);
            }
        }
        slot ^= 1;
    }

    // ---------------- epilogue ----------------
    const float* bias = (z == 0) ? bias0 : (z == 1) ? bias1 : bias2;
    if (mode == 3) {
        const float* qbz = plain0 + (size_t)z * 65536;   // qbias[z][128][512]
#pragma unroll
        for (int mi = 0; mi < 4; mi++) {
#pragma unroll
            for (int h = 0; h < 2; h++) {
                const int m = mBase + rowBase + mi * 16 + (lane >> 2) + h * 8;
                const float* qrow = qbz + (size_t)(m >> 5) * 512;
                float s = 0.0f;
#pragma unroll
                for (int ni = 0; ni < 4; ni++) {
                    const int n = nBase + colBase + ni * 8 + (lane & 3) * 2;
                    const float2 qv = *(const float2*)&qrow[n];
                    s += tanhf(acc[mi][ni][h * 2]     + qv.x) * vatt[z * 512 + n];
                    s += tanhf(acc[mi][ni][h * 2 + 1] + qv.y) * vatt[z * 512 + n + 1];
                }
                s += __shfl_xor_sync(0xffffffffu, s, 1);
                s += __shfl_xor_sync(0xffffffffu, s, 2);
                if ((lane & 3) == 0)
                    upart[((size_t)(nt * 4 + warpN) * 6 + z) * KBM + m] = s;
            }
        }
        return;
    }
#pragma unroll
    for (int mi = 0; mi < 4; mi++) {
#pragma unroll
        for (int h = 0; h < 2; h++) {
            const int m = mBase + rowBase + mi * 16 + (lane >> 2) + h * 8;
#pragma unroll
            for (int ni = 0; ni < 4; ni++) {
                const int n = nBase + colBase + ni * 8 + (lane & 3) * 2;
                float v0 = acc[mi][ni][h * 2];
                float v1 = acc[mi][ni][h * 2 + 1];
                if (mode != 6) { v0 += bias[n]; v1 += bias[n + 1]; }
                const size_t i0 = (size_t)m * 512 + n;
                if (mode == 6) {
                    *(float2*)&plain0[(size_t)z * 65536 + i0] = make_float2(v0, v1);
                } else if (mode == 4) {
                    const float e = p_eng[m];
                    const float wc0 = 1.0f / (1.0f + expf(-v0));
                    const float wc1 = 1.0f / (1.0f + expf(-v1));
                    const float2 cc = *(const float2*)&p_cell[i0];
                    const float2 aa = *(const float2*)&p_arn[i0];
                    const float2 dd = *(const float2*)&p_add[i0];
                    const float uc0 = cc.x + aa.x * dd.x * e;
                    const float uc1 = cc.y + aa.y * dd.y * e;
                    *(float2*)&outC[i0] = make_float2(uc0, uc1);
                    *(float2*)&outH[i0] = make_float2(wc0 * tanhf(uc0), wc1 * tanhf(uc1));
                } else if (mode == 5 && z < 2) {
                    float* pl = (z == 0) ? plain0 : plain1;
                    if (z == 0) { v0 = 1.0f / (1.0f + expf(-v0)); v1 = 1.0f / (1.0f + expf(-v1)); }
                    else        { v0 = tanhf(v0); v1 = tanhf(v1); }
                    *(float2*)&pl[i0] = make_float2(v0, v1);
                } else {
                    v0 = fmaxf(v0, 0.0f); v1 = fmaxf(v1, 0.0f);
                    u16* dH = oH + (mode == 5 ? 0 : (size_t)z * oStrideZ);
                    *(u32*)&dH[i0] = cvt2(v0, v1);
                }
            }
        }
    }
}

// ---------------- merged weight prepack ---------------------------------------
struct PrepackDesc { const float* s0; const float* s1; size_t off; int K; };
struct PrepackParams { PrepackDesc d[22]; };

__global__ void prepack_all(PrepackParams p) {
    __shared__ float t[32][33];
    const PrepackDesc de = p.d[blockIdx.z];
    const int K = de.K;
    const int k0 = blockIdx.x * 32;
    if (k0 >= K) return;
    const int n0 = blockIdx.y * 32;
    const int tx = threadIdx.x, ty = threadIdx.y;
#pragma unroll
    for (int i = 0; i < 4; i++) {
        const int k = k0 + ty + i * 8;
        t[ty + i * 8][tx] = (k < 512) ? de.s0[(size_t)k * 512 + n0 + tx]
                                      : de.s1[(size_t)(k - 512) * 512 + n0 + tx];
    }
    __syncthreads();
#pragma unroll
    for (int i = 0; i < 4; i++) {
        const int n = n0 + ty + i * 8;
        const int k = k0 + tx;
        u16 h, l; split2(t[tx][ty + i * 8], h, l);
        g_wbh[de.off + (size_t)n * K + k] = h;
        g_wbl[de.off + (size_t)n * K + k] = l;
    }
}

// ---------------- activation converters ---------------------------------------
__global__ void convert_info(const float* __restrict__ x, const float* __restrict__ h,
                             u16* __restrict__ dh) {
    const size_t T = (size_t)blockIdx.x * 256 + threadIdx.x;
    const int m = (int)(T >> 8);
    const int k = ((int)T & 255) << 2;
    const float4 v = (k < 512) ? *(const float4*)(x + (size_t)m * 512 + k)
                               : *(const float4*)(h + (size_t)m * 512 + (k - 512));
    const u64 hw = (u64)cvt2(v.x, v.y) | ((u64)cvt2(v.z, v.w) << 32);
    *(u64*)&dh[(size_t)m * 1024 + k] = hw;
}
__global__ void convert_att(const float* __restrict__ kbk, const float* __restrict__ q) {
    const int y = blockIdx.y;
    const size_t T = (size_t)blockIdx.x * 256 + threadIdx.x;
    const int m = (int)(T >> 7);
    const int k = ((int)T & 127) << 2;
    float4 v;
    u16* dh;
    const size_t off = (size_t)m * 512 + k;
    if (y < 3) {
        v = *(const float4*)(kbk + ((size_t)y * 4096 + m) * 512 + k);
        dh = g_atth + (size_t)y * ATTZ;
    } else {
        if (m >= 128) return;
        v = *(const float4*)(q + (size_t)m * 512 + k);
        dh = g_qh;
    }
    const u64 hw = (u64)cvt2(v.x, v.y) | ((u64)cvt2(v.z, v.w) << 32);
    *(u64*)&dh[off] = hw;
}

// ---------------- small kernels -------------------------------------------------
__global__ void eng_kernel(const float* __restrict__ cell, const float* __restrict__ w,
                           float* __restrict__ eng) {
    const int row = blockIdx.x * 8 + (threadIdx.x >> 5);
    const int lane = threadIdx.x & 31;
    const float* c = cell + (size_t)row * HD;
    float s = 0.0f;
#pragma unroll 4
    for (int k = lane; k < HD; k += 32) s += c[k] * w[k];
#pragma unroll
    for (int o = 16; o; o >>= 1) s += __shfl_down_sync(0xffffffffu, s, o);
    if (!lane) eng[row] = s;
}
__global__ void detect_mask_kernel(const unsigned int* __restrict__ w) {
    __shared__ int sF, sG;
    if (threadIdx.x == 0) { sF = 0; sG = 0; }
    __syncthreads();
    int f = 0, g = 0;
    for (int i = threadIdx.x; i < 65536; i += blockDim.x) {
        const unsigned int v = w[i];
        if (v == 0x3F800000u) f = 1;
        else if (v > 1u) g = 1;
    }
    if (f) atomicOr(&sF, 1);
    if (g) atomicOr(&sG, 1);
    __syncthreads();
    if (threadIdx.x == 0) g_maskmode = sF ? 2 : (sG ? 0 : 1);
}
__global__ void utk_kernel(const float* __restrict__ up, const void* __restrict__ maskraw,
                           float* __restrict__ out) {
    __shared__ float S[3][32];
    const int b = blockIdx.y;
    if (threadIdx.x < 96) {
        const int d = threadIdx.x >> 5, i = threadIdx.x & 31;
        float s = 0.0f;
#pragma unroll
        for (int p = 0; p < 16; p++)
#pragma unroll
            for (int hop = 0; hop < 2; hop++)
                s += up[((size_t)p * 6 + hop * 3 + d) * KBM + b * 32 + i];
        S[d][i] = s;
    }
    __syncthreads();
    const int mode = g_maskmode;
    const int j = blockIdx.x * 256 + threadIdx.x;
    const float v = S[0][j >> 10] + S[1][(j >> 5) & 31] + S[2][j & 31];
    const size_t o = (size_t)b * KBTOT + j;
    bool msk;
    if (mode == 0)      msk = ((const unsigned char*)maskraw)[o] != 0;
    else if (mode == 1) msk = ((const int*)maskraw)[o] != 0;
    else                msk = ((const float*)maskraw)[o] != 0.0f;
    out[o] = msk ? 0.0f : v;
}

// ---------------- host -----------------------------------------------------------
extern "C" void kernel_launch(void* const* d_in, const int* in_sizes, int n_in,
                              void* d_out, int out_size) {
    const float* query   = (const float*)d_in[0];
    const float* kb_keys = (const float*)d_in[1];
    const float* Wq      = (const float*)d_in[2];
    const float* Wk      = (const float*)d_in[3];
    const float* v_att   = (const float*)d_in[4];
    const float* x       = (const float*)d_in[5];
    const float* hidden  = (const float*)d_in[6];
    const float* cell    = (const float*)d_in[7];
    const float* arn_w1  = (const float*)d_in[8];
    const float* arn_b1  = (const float*)d_in[9];
    const float* arn_w2  = (const float*)d_in[10];
    const float* arn_b2  = (const float*)d_in[11];
    const float* arn_w3  = (const float*)d_in[12];
    const float* arn_b3  = (const float*)d_in[13];
    const float* add_w1  = (const float*)d_in[14];
    const float* add_b1  = (const float*)d_in[15];
    const float* add_w2  = (const float*)d_in[16];
    const float* add_b2  = (const float*)d_in[17];
    const float* add_w3  = (const float*)d_in[18];
    const float* add_b3  = (const float*)d_in[19];
    const float* eng_w   = (const float*)d_in[20];
    const float* wc_w1   = (const float*)d_in[21];
    const float* wc_b1   = (const float*)d_in[22];
    const float* wc_w2   = (const float*)d_in[23];
    const float* wc_b2   = (const float*)d_in[24];
    const float* wc_w3   = (const float*)d_in[25];
    const float* wc_b3   = (const float*)d_in[26];
    const float* wc_w4   = (const float*)d_in[27];
    const float* wc_b4   = (const float*)d_in[28];
    const void*  kb_mask = d_in[29];

    float* out     = (float*)d_out;
    float* out_utk = out;
    float* outH    = out + (size_t)BSZ * KBTOT;
    float* outC    = outH + (size_t)BT * HD;

    u16 *wbh, *wbl, *atth, *qh, *ah;
    float *qb, *arnp, *addp, *upart, *engp;
    cudaGetSymbolAddress((void**)&wbh,  g_wbh);
    cudaGetSymbolAddress((void**)&wbl,  g_wbl);
    cudaGetSymbolAddress((void**)&atth, g_atth);
    cudaGetSymbolAddress((void**)&qh,   g_qh);
    cudaGetSymbolAddress((void**)&ah,   g_ah);
    cudaGetSymbolAddress((void**)&qb,   g_qb);
    cudaGetSymbolAddress((void**)&arnp, g_arn);
    cudaGetSymbolAddress((void**)&addp, g_add);
    cudaGetSymbolAddress((void**)&upart,g_upart);
    cudaGetSymbolAddress((void**)&engp, g_eng);

    static int once = 0;
    if (!once) {
        cudaFuncSetAttribute(gemm_tc<2>, cudaFuncAttributeMaxDynamicSharedMemorySize, 98304);
        cudaFuncSetAttribute(gemm_tc<1>, cudaFuncAttributeMaxDynamicSharedMemorySize, 65536);
        once = 1;
    }

    // launch 0: merged prepack
    PrepackParams pp;
    pp.d[0] = {arn_w1, arn_w1 + 262144, W1OFF + 0 * BIG, 1024};
    pp.d[1] = {add_w1, add_w1 + 262144, W1OFF + 1 * BIG, 1024};
    pp.d[2] = {wc_w1,  wc_w1  + 262144, W1OFF + 2 * BIG, 1024};
    for (int i = 0; i < 6; i++) {
        pp.d[3 + i] = {Wk + (size_t)i * 262144, Wk + (size_t)i * 262144, WKOFF + i * SMALL, 512};
        pp.d[9 + i] = {Wq + (size_t)i * 262144, Wq + (size_t)i * 262144, WQOFF + i * SMALL, 512};
    }
    const float* sw[7] = {arn_w2, arn_w3, add_w2, add_w3, wc_w2, wc_w3, wc_w4};
    for (int j = 0; j < 7; j++)
        pp.d[15 + j] = {sw[j], sw[j], WSOFF2 + j * SMALL, 512};
    prepack_all<<<dim3(32, 16, 22), dim3(32, 8)>>>(pp);

    // launch 1, 2: operand conversions
    convert_info<<<32768, 256>>>(x, hidden, ah);
    convert_att<<<dim3(2048, 4), 256>>>(kb_keys, query);

    // launch 3: L1 (1-term) — ncu capture index
    gemm_tc<1><<<dim3(4, 256, 3), 256, 65536>>>(
        ah, 0, 0, wbh + W1OFF, nullptr, BIG, 1024,
        arn_b1, add_b1, wc_b1, 0,
        ah + H1_OFF, H1S, nullptr, nullptr, nullptr, nullptr,
        nullptr, nullptr, nullptr, nullptr, nullptr, nullptr);

    // launch 4: qbias[z] = query @ Wq[z]  (2-term, raw fp32 out)
    gemm_tc<2><<<dim3(4, 1, 6), 256, 98304>>>(
        qh, 0, 1, wbh + WQOFF, wbl + WQOFF, SMALL, 512,
        nullptr, nullptr, nullptr, 6,
        nullptr, 0, qb, nullptr, nullptr, nullptr,
        nullptr, nullptr, nullptr, nullptr, nullptr, nullptr);

    // launch 5: attention GEMM (2-term)
    gemm_tc<2><<<dim3(4, 32, 6), 256, 98304>>>(
        atth, ATTZ, 3, wbh + WKOFF, wbl + WKOFF, SMALL, 512,
        nullptr, nullptr, nullptr, 3,
        nullptr, 0, qb, nullptr, v_att, upart,
        nullptr, nullptr, nullptr, nullptr, nullptr, nullptr);

    // launch 6-8: small kernels
    detect_mask_kernel<<<1, 1024>>>((const unsigned int*)kb_mask);
    utk_kernel<<<dim3(KBTOT / 256, BSZ), 256>>>(upart, kb_mask, out_utk);
    eng_kernel<<<BT / 8, 256>>>(cell, eng_w, engp);

    // L2: h1 @ w2 -> h2 hi planes (relu), 1-term
    gemm_tc<1><<<dim3(4, 256, 3), 256, 65536>>>(
        ah + H1_OFF, H1S, 0, wbh + WSOFF2, nullptr, 2 * SMALL, 512,
        arn_b2, add_b2, wc_b2, 0,
        ah + H2_OFF, H1S, nullptr, nullptr, nullptr, nullptr,
        nullptr, nullptr, nullptr, nullptr, nullptr, nullptr);
    // L3: h2 @ w3; z0 sigmoid->arn, z1 tanh->add, z2 relu->h3 plane, 1-term
    gemm_tc<1><<<dim3(4, 256, 3), 256, 65536>>>(
        ah + H2_OFF, H1S, 0, wbh + WSOFF2 + SMALL, nullptr, 2 * SMALL, 512,
        arn_b3, add_b3, wc_b3, 5,
        ah + H1_OFF, 0, arnp, addp, nullptr, nullptr,
        nullptr, nullptr, nullptr, nullptr, nullptr, nullptr);
    // L4: h3 @ wc_w4 -> fused final epilogue (2-term)
    gemm_tc<2><<<dim3(4, 256, 1), 256, 98304>>>(
        ah + H1_OFF, 0, 0, wbh + WSOFF2 + 6 * SMALL, wbl + WSOFF2 + 6 * SMALL, SMALL, 512,
        wc_b4, wc_b4, wc_b4, 4,
        nullptr, 0, nullptr, nullptr, nullptr, nullptr,
        arnp, addp, cell, engp, outH, outC);
}

// round 11
// speedup vs baseline: 8.4150x; 1.1210x over previous
#include <cuda_runtime.h>
#include <cuda_fp16.h>
#include <cstdint>

#define HD 512
#define BT 32768
#define BSZ 128
#define KBM 4096
#define KBTOT 32768

typedef unsigned int u32;
typedef unsigned long long u64;
typedef unsigned short u16;

// weight plane slot offsets (elements)
#define BIG    524288ULL                  // 512n x 1024k
#define SMALL  262144ULL                  // 512n x 512k
#define W1OFF  0ULL                       // 3 BIG: arn1, add1, wc1
#define WKOFF  (3ULL*BIG)                 // 6 SMALL Wk
#define WQOFF  (WKOFF + 6ULL*SMALL)       // 6 SMALL Wq
#define WSOFF2 (WQOFF + 6ULL*SMALL)       // 7 SMALL: arn2,arn3,add2,add3,wc2,wc3,wc4
#define WTOT   (WSOFF2 + 7ULL*SMALL)

#define ATTZ   2097152ULL                 // 4096 x 512 per dim
#define H1S    16777216ULL                // 32768 x 512
#define H1_OFF 33554432ULL
#define H2_OFF (H1_OFF + 3*H1S)

__device__ u16   g_wbh[WTOT];
__device__ u16   g_wbl[WTOT];
__device__ u16   g_atth[3*ATTZ];
__device__ u16   g_qh[65536];
__device__ u16   g_ah[134217728];         // hi planes: info + h1[3] + h2[3] (+h3)
__device__ float g_qb[6*128*512];
__device__ float g_arn[(size_t)BT*HD];
__device__ float g_add[(size_t)BT*HD];
__device__ float g_upart[16*6*KBM];
__device__ float g_eng[BT];
__device__ int   g_maskmode;

__device__ __forceinline__ void split2(float v, u16& h, u16& l) {
    __half hh = __float2half_rn(v);
    h = __half_as_ushort(hh);
    l = __half_as_ushort(__float2half_rn(v - __half2float(hh)));
}
__device__ __forceinline__ u32 cvt2(float v0, float v1) {
    u32 r;
    asm("cvt.rn.f16x2.f32 %0, %1, %2;" : "=r"(r) : "f"(v1), "f"(v0));
    return r;
}
__device__ __forceinline__ u32 smem_u32(const void* p) {
    u32 a;
    asm("{ .reg .u64 t; cvta.to.shared.u64 t, %1; cvt.u32.u64 %0, t; }" : "=r"(a) : "l"(p));
    return a;
}
__device__ __forceinline__ void cp16(u32 dst, const void* src) {
    asm volatile("cp.async.cg.shared.global [%0], [%1], 16;" :: "r"(dst), "l"(src));
}
__device__ __forceinline__ void ldsm4(u32* r, u32 a) {
    asm volatile("ldmatrix.sync.aligned.m8n8.x4.shared.b16 {%0,%1,%2,%3}, [%4];"
                 : "=r"(r[0]), "=r"(r[1]), "=r"(r[2]), "=r"(r[3]) : "r"(a));
}
__device__ __forceinline__ void mma16816(float* c, const u32* a, const u32* b) {
    asm volatile("mma.sync.aligned.m16n8k16.row.col.f32.f16.f16.f32 "
                 "{%0,%1,%2,%3},{%4,%5,%6,%7},{%8,%9},{%0,%1,%2,%3};"
                 : "+f"(c[0]), "+f"(c[1]), "+f"(c[2]), "+f"(c[3])
                 : "r"(a[0]), "r"(a[1]), "r"(a[2]), "r"(a[3]), "r"(b[0]), "r"(b[1]));
}

// ---------------- stage loader: k-tile 64, 128B rows, chunk^(row&7) swizzle --
// A-hi @0 (16KB), B-hi @16384; stage stride 32768.
__device__ __forceinline__ void stage_load(
    u32 sb, int slot,
    const u16* __restrict__ Ah, const u16* __restrict__ Bh,
    int mBase, int nBase, int K, int kt, int tid) {
    const u32 so = sb + slot * 32768;
    const int kOff = kt * 64;
#pragma unroll
    for (int j = 0; j < 4; j++) {
        const int id = tid + j * 256;          // 0..1023
        const int r = id >> 3, c = id & 7;
        const u32 dst = so + r * 128 + (((c ^ (r & 7)) & 7) << 4);
        cp16(dst,         Ah + (size_t)(mBase + r) * K + kOff + c * 8);
        cp16(dst + 16384, Bh + (size_t)(nBase + r) * K + kOff + c * 8);
    }
}

// ---------------- GEMM: C[M,128tile] = act(A @ B^T + bias), 1-term fp16 -----
// modes: 0 relu->hi plane, 3 attention, 4 final fused, 5 L3 combo, 6 raw->plain0
__global__ __launch_bounds__(256, 2)
void gemm_tc(const u16* __restrict__ Ahp, size_t aStrideZ, int aZmod,
             const u16* __restrict__ Bhp, size_t bStrideZ, int K,
             const float* __restrict__ bias0, const float* __restrict__ bias1,
             const float* __restrict__ bias2, int mode,
             u16* __restrict__ oH, size_t oStrideZ,
             float* __restrict__ plain0, float* __restrict__ plain1,
             const float* __restrict__ vatt, float* __restrict__ upart,
             const float* __restrict__ p_arn, const float* __restrict__ p_add,
             const float* __restrict__ p_cell, const float* __restrict__ p_eng,
             float* __restrict__ outH, float* __restrict__ outC) {
    extern __shared__ char smem[];
    const u32 sb = smem_u32(smem);
    const int tid = threadIdx.x, lane = tid & 31, warp = tid >> 5;
    const int warpM = warp >> 2, warpN = warp & 3;
    const int rowBase = warpM * 64, colBase = warpN * 32;
    const int nt = blockIdx.x, mt = blockIdx.y, z = blockIdx.z;
    const int mBase = mt * 128, nBase = nt * 128;

    const int az = aZmod ? (z % aZmod) : z;
    const u16* Ah = Ahp + (size_t)az * aStrideZ;
    const u16* Bh = Bhp + (size_t)z * bStrideZ;

    float acc[4][4][4];
#pragma unroll
    for (int i = 0; i < 4; i++)
#pragma unroll
        for (int j = 0; j < 4; j++)
#pragma unroll
            for (int k = 0; k < 4; k++) acc[i][j][k] = 0.0f;

    const int nk = K >> 6;

    stage_load(sb, 0, Ah, Bh, mBase, nBase, K, 0, tid);
    asm volatile("cp.async.commit_group;");

    const int arow = (lane & 15);
    const int acb  = (lane >> 4);
    const int brow = (lane & 7) + ((lane >> 4) << 3);
    const int bcb  = (lane >> 3) & 1;

    int slot = 0;
    for (int kt = 0; kt < nk; kt++) {
        asm volatile("cp.async.wait_group 0;");
        __syncthreads();
        if (kt + 1 < nk) {
            stage_load(sb, slot ^ 1, Ah, Bh, mBase, nBase, K, kt + 1, tid);
            asm volatile("cp.async.commit_group;");
        }
        const u32 so = sb + slot * 32768;
#pragma unroll
        for (int ks = 0; ks < 4; ks++) {
            u32 a_hi[4][4], b_hi[2][4];
#pragma unroll
            for (int mi = 0; mi < 4; mi++) {
                const int r = rowBase + mi * 16 + arow;
                const int c = ks * 2 + acb;
                ldsm4(a_hi[mi], so + r * 128 + (((c ^ (r & 7)) & 7) << 4));
            }
#pragma unroll
            for (int nj = 0; nj < 2; nj++) {
                const int r = colBase + nj * 16 + brow;
                const int c = ks * 2 + bcb;
                ldsm4(b_hi[nj], so + 16384 + r * 128 + (((c ^ (r & 7)) & 7) << 4));
            }
#pragma unroll
            for (int mi = 0; mi < 4; mi++)
#pragma unroll
                for (int ni = 0; ni < 4; ni++)
                    mma16816(acc[mi][ni], a_hi[mi], &b_hi[ni >> 1][(ni & 1) * 2]);
        }
        slot ^= 1;
    }

    // ---------------- epilogue ----------------
    const float* bias = (z == 0) ? bias0 : (z == 1) ? bias1 : bias2;
    if (mode == 3) {
        const float* qbz = plain0 + (size_t)z * 65536;   // qbias[z][128][512]
#pragma unroll
        for (int mi = 0; mi < 4; mi++) {
#pragma unroll
            for (int h = 0; h < 2; h++) {
                const int m = mBase + rowBase + mi * 16 + (lane >> 2) + h * 8;
                const float* qrow = qbz + (size_t)(m >> 5) * 512;
                float s = 0.0f;
#pragma unroll
                for (int ni = 0; ni < 4; ni++) {
                    const int n = nBase + colBase + ni * 8 + (lane & 3) * 2;
                    const float2 qv = *(const float2*)&qrow[n];
                    s += tanhf(acc[mi][ni][h * 2]     + qv.x) * vatt[z * 512 + n];
                    s += tanhf(acc[mi][ni][h * 2 + 1] + qv.y) * vatt[z * 512 + n + 1];
                }
                s += __shfl_xor_sync(0xffffffffu, s, 1);
                s += __shfl_xor_sync(0xffffffffu, s, 2);
                if ((lane & 3) == 0)
                    upart[((size_t)(nt * 4 + warpN) * 6 + z) * KBM + m] = s;
            }
        }
        return;
    }
#pragma unroll
    for (int mi = 0; mi < 4; mi++) {
#pragma unroll
        for (int h = 0; h < 2; h++) {
            const int m = mBase + rowBase + mi * 16 + (lane >> 2) + h * 8;
#pragma unroll
            for (int ni = 0; ni < 4; ni++) {
                const int n = nBase + colBase + ni * 8 + (lane & 3) * 2;
                float v0 = acc[mi][ni][h * 2];
                float v1 = acc[mi][ni][h * 2 + 1];
                if (mode != 6) { v0 += bias[n]; v1 += bias[n + 1]; }
                const size_t i0 = (size_t)m * 512 + n;
                if (mode == 6) {
                    *(float2*)&plain0[(size_t)z * 65536 + i0] = make_float2(v0, v1);
                } else if (mode == 4) {
                    const float e = p_eng[m];
                    const float wc0 = 1.0f / (1.0f + expf(-v0));
                    const float wc1 = 1.0f / (1.0f + expf(-v1));
                    const float2 cc = *(const float2*)&p_cell[i0];
                    const float2 aa = *(const float2*)&p_arn[i0];
                    const float2 dd = *(const float2*)&p_add[i0];
                    const float uc0 = cc.x + aa.x * dd.x * e;
                    const float uc1 = cc.y + aa.y * dd.y * e;
                    *(float2*)&outC[i0] = make_float2(uc0, uc1);
                    *(float2*)&outH[i0] = make_float2(wc0 * tanhf(uc0), wc1 * tanhf(uc1));
                } else if (mode == 5 && z < 2) {
                    float* pl = (z == 0) ? plain0 : plain1;
                    if (z == 0) { v0 = 1.0f / (1.0f + expf(-v0)); v1 = 1.0f / (1.0f + expf(-v1)); }
                    else        { v0 = tanhf(v0); v1 = tanhf(v1); }
                    *(float2*)&pl[i0] = make_float2(v0, v1);
                } else {
                    v0 = fmaxf(v0, 0.0f); v1 = fmaxf(v1, 0.0f);
                    u16* dH = oH + (mode == 5 ? 0 : (size_t)z * oStrideZ);
                    *(u32*)&dH[i0] = cvt2(v0, v1);
                }
            }
        }
    }
}

// ---------------- merged weight prepack ---------------------------------------
struct PrepackDesc { const float* s0; const float* s1; size_t off; int K; };
struct PrepackParams { PrepackDesc d[22]; };

__global__ void prepack_all(PrepackParams p) {
    __shared__ float t[32][33];
    const PrepackDesc de = p.d[blockIdx.z];
    const int K = de.K;
    const int k0 = blockIdx.x * 32;
    if (k0 >= K) return;
    const int n0 = blockIdx.y * 32;
    const int tx = threadIdx.x, ty = threadIdx.y;
#pragma unroll
    for (int i = 0; i < 4; i++) {
        const int k = k0 + ty + i * 8;
        t[ty + i * 8][tx] = (k < 512) ? de.s0[(size_t)k * 512 + n0 + tx]
                                      : de.s1[(size_t)(k - 512) * 512 + n0 + tx];
    }
    __syncthreads();
#pragma unroll
    for (int i = 0; i < 4; i++) {
        const int n = n0 + ty + i * 8;
        const int k = k0 + tx;
        u16 h, l; split2(t[tx][ty + i * 8], h, l);
        g_wbh[de.off + (size_t)n * K + k] = h;
        g_wbl[de.off + (size_t)n * K + k] = l;
    }
}

// ---------------- activation converters ---------------------------------------
__global__ void convert_info(const float* __restrict__ x, const float* __restrict__ h,
                             u16* __restrict__ dh) {
    const size_t T = (size_t)blockIdx.x * 256 + threadIdx.x;
    const int m = (int)(T >> 8);
    const int k = ((int)T & 255) << 2;
    const float4 v = (k < 512) ? *(const float4*)(x + (size_t)m * 512 + k)
                               : *(const float4*)(h + (size_t)m * 512 + (k - 512));
    const u64 hw = (u64)cvt2(v.x, v.y) | ((u64)cvt2(v.z, v.w) << 32);
    *(u64*)&dh[(size_t)m * 1024 + k] = hw;
}
__global__ void convert_att(const float* __restrict__ kbk, const float* __restrict__ q) {
    const int y = blockIdx.y;
    const size_t T = (size_t)blockIdx.x * 256 + threadIdx.x;
    const int m = (int)(T >> 7);
    const int k = ((int)T & 127) << 2;
    float4 v;
    u16* dh;
    const size_t off = (size_t)m * 512 + k;
    if (y < 3) {
        v = *(const float4*)(kbk + ((size_t)y * 4096 + m) * 512 + k);
        dh = g_atth + (size_t)y * ATTZ;
    } else {
        if (m >= 128) return;
        v = *(const float4*)(q + (size_t)m * 512 + k);
        dh = g_qh;
    }
    const u64 hw = (u64)cvt2(v.x, v.y) | ((u64)cvt2(v.z, v.w) << 32);
    *(u64*)&dh[off] = hw;
}

// ---------------- small kernels -------------------------------------------------
__global__ void eng_kernel(const float* __restrict__ cell, const float* __restrict__ w,
                           float* __restrict__ eng) {
    const int row = blockIdx.x * 8 + (threadIdx.x >> 5);
    const int lane = threadIdx.x & 31;
    const float* c = cell + (size_t)row * HD;
    float s = 0.0f;
#pragma unroll 4
    for (int k = lane; k < HD; k += 32) s += c[k] * w[k];
#pragma unroll
    for (int o = 16; o; o >>= 1) s += __shfl_down_sync(0xffffffffu, s, o);
    if (!lane) eng[row] = s;
}
__global__ void detect_mask_kernel(const unsigned int* __restrict__ w) {
    __shared__ int sF, sG;
    if (threadIdx.x == 0) { sF = 0; sG = 0; }
    __syncthreads();
    int f = 0, g = 0;
    for (int i = threadIdx.x; i < 65536; i += blockDim.x) {
        const unsigned int v = w[i];
        if (v == 0x3F800000u) f = 1;
        else if (v > 1u) g = 1;
    }
    if (f) atomicOr(&sF, 1);
    if (g) atomicOr(&sG, 1);
    __syncthreads();
    if (threadIdx.x == 0) g_maskmode = sF ? 2 : (sG ? 0 : 1);
}
__global__ void utk_kernel(const float* __restrict__ up, const void* __restrict__ maskraw,
                           float* __restrict__ out) {
    __shared__ float S[3][32];
    const int b = blockIdx.y;
    if (threadIdx.x < 96) {
        const int d = threadIdx.x >> 5, i = threadIdx.x & 31;
        float s = 0.0f;
#pragma unroll
        for (int p = 0; p < 16; p++)
#pragma unroll
            for (int hop = 0; hop < 2; hop++)
                s += up[((size_t)p * 6 + hop * 3 + d) * KBM + b * 32 + i];
        S[d][i] = s;
    }
    __syncthreads();
    const int mode = g_maskmode;
    const int j = blockIdx.x * 256 + threadIdx.x;
    const float v = S[0][j >> 10] + S[1][(j >> 5) & 31] + S[2][j & 31];
    const size_t o = (size_t)b * KBTOT + j;
    bool msk;
    if (mode == 0)      msk = ((const unsigned char*)maskraw)[o] != 0;
    else if (mode == 1) msk = ((const int*)maskraw)[o] != 0;
    else                msk = ((const float*)maskraw)[o] != 0.0f;
    out[o] = msk ? 0.0f : v;
}

// ---------------- host -----------------------------------------------------------
extern "C" void kernel_launch(void* const* d_in, const int* in_sizes, int n_in,
                              void* d_out, int out_size) {
    const float* query   = (const float*)d_in[0];
    const float* kb_keys = (const float*)d_in[1];
    const float* Wq      = (const float*)d_in[2];
    const float* Wk      = (const float*)d_in[3];
    const float* v_att   = (const float*)d_in[4];
    const float* x       = (const float*)d_in[5];
    const float* hidden  = (const float*)d_in[6];
    const float* cell    = (const float*)d_in[7];
    const float* arn_w1  = (const float*)d_in[8];
    const float* arn_b1  = (const float*)d_in[9];
    const float* arn_w2  = (const float*)d_in[10];
    const float* arn_b2  = (const float*)d_in[11];
    const float* arn_w3  = (const float*)d_in[12];
    const float* arn_b3  = (const float*)d_in[13];
    const float* add_w1  = (const float*)d_in[14];
    const float* add_b1  = (const float*)d_in[15];
    const float* add_w2  = (const float*)d_in[16];
    const float* add_b2  = (const float*)d_in[17];
    const float* add_w3  = (const float*)d_in[18];
    const float* add_b3  = (const float*)d_in[19];
    const float* eng_w   = (const float*)d_in[20];
    const float* wc_w1   = (const float*)d_in[21];
    const float* wc_b1   = (const float*)d_in[22];
    const float* wc_w2   = (const float*)d_in[23];
    const float* wc_b2   = (const float*)d_in[24];
    const float* wc_w3   = (const float*)d_in[25];
    const float* wc_b3   = (const float*)d_in[26];
    const float* wc_w4   = (const float*)d_in[27];
    const float* wc_b4   = (const float*)d_in[28];
    const void*  kb_mask = d_in[29];

    float* out     = (float*)d_out;
    float* out_utk = out;
    float* outH    = out + (size_t)BSZ * KBTOT;
    float* outC    = outH + (size_t)BT * HD;

    u16 *wbh, *wbl, *atth, *qh, *ah;
    float *qb, *arnp, *addp, *upart, *engp;
    cudaGetSymbolAddress((void**)&wbh,  g_wbh);
    cudaGetSymbolAddress((void**)&wbl,  g_wbl);
    cudaGetSymbolAddress((void**)&atth, g_atth);
    cudaGetSymbolAddress((void**)&qh,   g_qh);
    cudaGetSymbolAddress((void**)&ah,   g_ah);
    cudaGetSymbolAddress((void**)&qb,   g_qb);
    cudaGetSymbolAddress((void**)&arnp, g_arn);
    cudaGetSymbolAddress((void**)&addp, g_add);
    cudaGetSymbolAddress((void**)&upart,g_upart);
    cudaGetSymbolAddress((void**)&engp, g_eng);

    static cudaStream_t s2 = nullptr;
    static cudaEvent_t evFork = nullptr, evJoin = nullptr;
    if (!s2) {
        cudaFuncSetAttribute(gemm_tc, cudaFuncAttributeMaxDynamicSharedMemorySize, 65536);
        cudaStreamCreateWithFlags(&s2, cudaStreamNonBlocking);
        cudaEventCreateWithFlags(&evFork, cudaEventDisableTiming);
        cudaEventCreateWithFlags(&evJoin, cudaEventDisableTiming);
    }

    // launch 0: merged prepack (feeds BOTH chains)
    PrepackParams pp;
    pp.d[0] = {arn_w1, arn_w1 + 262144, W1OFF + 0 * BIG, 1024};
    pp.d[1] = {add_w1, add_w1 + 262144, W1OFF + 1 * BIG, 1024};
    pp.d[2] = {wc_w1,  wc_w1  + 262144, W1OFF + 2 * BIG, 1024};
    for (int i = 0; i < 6; i++) {
        pp.d[3 + i] = {Wk + (size_t)i * 262144, Wk + (size_t)i * 262144, WKOFF + i * SMALL, 512};
        pp.d[9 + i] = {Wq + (size_t)i * 262144, Wq + (size_t)i * 262144, WQOFF + i * SMALL, 512};
    }
    const float* sw[7] = {arn_w2, arn_w3, add_w2, add_w3, wc_w2, wc_w3, wc_w4};
    for (int j = 0; j < 7; j++)
        pp.d[15 + j] = {sw[j], sw[j], WSOFF2 + j * SMALL, 512};
    prepack_all<<<dim3(32, 16, 22), dim3(32, 8)>>>(pp);

    // ---- fork: attention chain on s2 -------------------------------------------
    cudaEventRecord(evFork, 0);
    cudaStreamWaitEvent(s2, evFork, 0);

    convert_att<<<dim3(2048, 4), 256, 0, s2>>>(kb_keys, query);
    // qbias[z] = query @ Wq[z]
    gemm_tc<<<dim3(4, 1, 6), 256, 65536, s2>>>(
        qh, 0, 1, wbh + WQOFF, SMALL, 512,
        nullptr, nullptr, nullptr, 6,
        nullptr, 0, qb, nullptr, nullptr, nullptr,
        nullptr, nullptr, nullptr, nullptr, nullptr, nullptr);
    // attention GEMM  (launch idx 3 — ncu capture)
    gemm_tc<<<dim3(4, 32, 6), 256, 65536, s2>>>(
        atth, ATTZ, 3, wbh + WKOFF, SMALL, 512,
        nullptr, nullptr, nullptr, 3,
        nullptr, 0, qb, nullptr, v_att, upart,
        nullptr, nullptr, nullptr, nullptr, nullptr, nullptr);
    detect_mask_kernel<<<1, 1024, 0, s2>>>((const unsigned int*)kb_mask);
    utk_kernel<<<dim3(KBTOT / 256, BSZ), 256, 0, s2>>>(upart, kb_mask, out_utk);
    cudaEventRecord(evJoin, s2);

    // ---- main: MLP chain ---------------------------------------------------------
    convert_info<<<32768, 256>>>(x, hidden, ah);
    eng_kernel<<<BT / 8, 256>>>(cell, eng_w, engp);

    // L1: info @ w1 -> h1 hi planes (relu)
    gemm_tc<<<dim3(4, 256, 3), 256, 65536>>>(
        ah, 0, 0, wbh + W1OFF, BIG, 1024,
        arn_b1, add_b1, wc_b1, 0,
        ah + H1_OFF, H1S, nullptr, nullptr, nullptr, nullptr,
        nullptr, nullptr, nullptr, nullptr, nullptr, nullptr);
    // L2: h1 @ w2 -> h2 hi planes (relu)
    gemm_tc<<<dim3(4, 256, 3), 256, 65536>>>(
        ah + H1_OFF, H1S, 0, wbh + WSOFF2, 2 * SMALL, 512,
        arn_b2, add_b2, wc_b2, 0,
        ah + H2_OFF, H1S, nullptr, nullptr, nullptr, nullptr,
        nullptr, nullptr, nullptr, nullptr, nullptr, nullptr);
    // L3: h2 @ w3; z0 sigmoid->arn, z1 tanh->add, z2 relu->h3 plane
    gemm_tc<<<dim3(4, 256, 3), 256, 65536>>>(
        ah + H2_OFF, H1S, 0, wbh + WSOFF2 + SMALL, 2 * SMALL, 512,
        arn_b3, add_b3, wc_b3, 5,
        ah + H1_OFF, 0, arnp, addp, nullptr, nullptr,
        nullptr, nullptr, nullptr, nullptr, nullptr, nullptr);
    // L4: h3 @ wc_w4 -> fused final epilogue
    gemm_tc<<<dim3(4, 256, 1), 256, 65536>>>(
        ah + H1_OFF, 0, 0, wbh + WSOFF2 + 6 * SMALL, SMALL, 512,
        wc_b4, wc_b4, wc_b4, 4,
        nullptr, 0, nullptr, nullptr, nullptr, nullptr,
        arnp, addp, cell, engp, outH, outC);

    // ---- join: attention chain must finish before capture ends ------------------
    cudaStreamWaitEvent(0, evJoin, 0);
}

// round 12
// speedup vs baseline: 8.5705x; 1.0185x over previous
#include <cuda_runtime.h>
#include <cuda_fp16.h>
#include <cstdint>

#define HD 512
#define BT 32768
#define BSZ 128
#define KBM 4096
#define KBTOT 32768

typedef unsigned int u32;
typedef unsigned long long u64;
typedef unsigned short u16;

// weight plane slot offsets (elements)
#define BIG    524288ULL                  // 512n x 1024k
#define SMALL  262144ULL                  // 512n x 512k
#define W1OFF  0ULL                       // 3 BIG: arn1, add1, wc1
#define WKOFF  (3ULL*BIG)                 // 6 SMALL Wk
#define WQOFF  (WKOFF + 6ULL*SMALL)       // 6 SMALL Wq
#define WSOFF2 (WQOFF + 6ULL*SMALL)       // 7 SMALL: arn2,arn3,add2,add3,wc2,wc3,wc4
#define WTOT   (WSOFF2 + 7ULL*SMALL)

#define ATTZ   2097152ULL                 // 4096 x 512 per dim
#define H1S    16777216ULL                // 32768 x 512
#define H1_OFF 33554432ULL
#define H2_OFF (H1_OFF + 3*H1S)

__device__ u16   g_wbh[WTOT];
__device__ u16   g_wbl[WTOT];
__device__ u16   g_atth[3*ATTZ];
__device__ u16   g_qh[65536];
__device__ u16   g_ah[134217728];         // hi planes: info + h1[3] + h2[3] (+h3)
__device__ float g_qb[6*128*512];
__device__ u16   g_arnh[(size_t)BT*HD];
__device__ u16   g_addh[(size_t)BT*HD];
__device__ float g_upart[16*6*KBM];
__device__ float g_eng[BT];
__device__ int   g_maskmode;

__device__ __forceinline__ void split2(float v, u16& h, u16& l) {
    __half hh = __float2half_rn(v);
    h = __half_as_ushort(hh);
    l = __half_as_ushort(__float2half_rn(v - __half2float(hh)));
}
__device__ __forceinline__ u32 cvt2(float v0, float v1) {
    u32 r;
    asm("cvt.rn.f16x2.f32 %0, %1, %2;" : "=r"(r) : "f"(v1), "f"(v0));
    return r;
}
__device__ __forceinline__ u32 smem_u32(const void* p) {
    u32 a;
    asm("{ .reg .u64 t; cvta.to.shared.u64 t, %1; cvt.u32.u64 %0, t; }" : "=r"(a) : "l"(p));
    return a;
}
__device__ __forceinline__ void cp16(u32 dst, const void* src) {
    asm volatile("cp.async.cg.shared.global [%0], [%1], 16;" :: "r"(dst), "l"(src));
}
__device__ __forceinline__ void ldsm4(u32* r, u32 a) {
    asm volatile("ldmatrix.sync.aligned.m8n8.x4.shared.b16 {%0,%1,%2,%3}, [%4];"
                 : "=r"(r[0]), "=r"(r[1]), "=r"(r[2]), "=r"(r[3]) : "r"(a));
}
__device__ __forceinline__ void mma16816(float* c, const u32* a, const u32* b) {
    asm volatile("mma.sync.aligned.m16n8k16.row.col.f32.f16.f16.f32 "
                 "{%0,%1,%2,%3},{%4,%5,%6,%7},{%8,%9},{%0,%1,%2,%3};"
                 : "+f"(c[0]), "+f"(c[1]), "+f"(c[2]), "+f"(c[3])
                 : "r"(a[0]), "r"(a[1]), "r"(a[2]), "r"(a[3]), "r"(b[0]), "r"(b[1]));
}

// ---------------- stage loader: k-tile 64, 128B rows, chunk^(row&7) swizzle --
// A-hi @0 (16KB), B-hi @16384; stage stride 32768; 3 stages.
__device__ __forceinline__ void stage_load(
    u32 sb, int slot,
    const u16* __restrict__ Ah, const u16* __restrict__ Bh,
    int mBase, int nBase, int K, int kt, int tid) {
    const u32 so = sb + slot * 32768;
    const int kOff = kt * 64;
#pragma unroll
    for (int j = 0; j < 4; j++) {
        const int id = tid + j * 256;          // 0..1023
        const int r = id >> 3, c = id & 7;
        const u32 dst = so + r * 128 + (((c ^ (r & 7)) & 7) << 4);
        cp16(dst,         Ah + (size_t)(mBase + r) * K + kOff + c * 8);
        cp16(dst + 16384, Bh + (size_t)(nBase + r) * K + kOff + c * 8);
    }
}

// ---------------- GEMM: C[M,128tile] = act(A @ B^T + bias), 1-term fp16 -----
// modes: 0 relu->hi plane, 3 attention, 4 final fused, 5 L3 combo, 6 raw->plain0
__global__ __launch_bounds__(256, 2)
void gemm_tc(const u16* __restrict__ Ahp, size_t aStrideZ, int aZmod,
             const u16* __restrict__ Bhp, size_t bStrideZ, int K,
             const float* __restrict__ bias0, const float* __restrict__ bias1,
             const float* __restrict__ bias2, int mode,
             u16* __restrict__ oH, size_t oStrideZ,
             float* __restrict__ plain0,
             u16* __restrict__ pH0, u16* __restrict__ pH1,
             const float* __restrict__ vatt, float* __restrict__ upart,
             const u16* __restrict__ p_arnh, const u16* __restrict__ p_addh,
             const float* __restrict__ p_cell, const float* __restrict__ p_eng,
             float* __restrict__ outH, float* __restrict__ outC) {
    extern __shared__ char smem[];
    const u32 sb = smem_u32(smem);
    const int tid = threadIdx.x, lane = tid & 31, warp = tid >> 5;
    const int warpM = warp >> 2, warpN = warp & 3;
    const int rowBase = warpM * 64, colBase = warpN * 32;
    const int nt = blockIdx.x, mt = blockIdx.y, z = blockIdx.z;
    const int mBase = mt * 128, nBase = nt * 128;

    const int az = aZmod ? (z % aZmod) : z;
    const u16* Ah = Ahp + (size_t)az * aStrideZ;
    const u16* Bh = Bhp + (size_t)z * bStrideZ;

    float acc[4][4][4];
#pragma unroll
    for (int i = 0; i < 4; i++)
#pragma unroll
        for (int j = 0; j < 4; j++)
#pragma unroll
            for (int k = 0; k < 4; k++) acc[i][j][k] = 0.0f;

    const int nk = K >> 6;   // >= 8 for all uses

    // 3-stage prologue
    stage_load(sb, 0, Ah, Bh, mBase, nBase, K, 0, tid);
    asm volatile("cp.async.commit_group;");
    stage_load(sb, 1, Ah, Bh, mBase, nBase, K, 1, tid);
    asm volatile("cp.async.commit_group;");

    const int arow = (lane & 15);
    const int acb  = (lane >> 4);
    const int brow = (lane & 7) + ((lane >> 4) << 3);
    const int bcb  = (lane >> 3) & 1;

    int slot = 0;
    for (int kt = 0; kt < nk; kt++) {
        if (kt + 1 < nk) asm volatile("cp.async.wait_group 1;");
        else             asm volatile("cp.async.wait_group 0;");
        __syncthreads();
        if (kt + 2 < nk) {
            int ps = slot + 2; if (ps >= 3) ps -= 3;
            stage_load(sb, ps, Ah, Bh, mBase, nBase, K, kt + 2, tid);
            asm volatile("cp.async.commit_group;");
        }
        const u32 so = sb + slot * 32768;
#pragma unroll
        for (int ks = 0; ks < 4; ks++) {
            u32 a_hi[4][4], b_hi[2][4];
#pragma unroll
            for (int mi = 0; mi < 4; mi++) {
                const int r = rowBase + mi * 16 + arow;
                const int c = ks * 2 + acb;
                ldsm4(a_hi[mi], so + r * 128 + (((c ^ (r & 7)) & 7) << 4));
            }
#pragma unroll
            for (int nj = 0; nj < 2; nj++) {
                const int r = colBase + nj * 16 + brow;
                const int c = ks * 2 + bcb;
                ldsm4(b_hi[nj], so + 16384 + r * 128 + (((c ^ (r & 7)) & 7) << 4));
            }
#pragma unroll
            for (int mi = 0; mi < 4; mi++)
#pragma unroll
                for (int ni = 0; ni < 4; ni++)
                    mma16816(acc[mi][ni], a_hi[mi], &b_hi[ni >> 1][(ni & 1) * 2]);
        }
        slot++; if (slot == 3) slot = 0;
    }

    // ---------------- epilogue ----------------
    const float* bias = (z == 0) ? bias0 : (z == 1) ? bias1 : bias2;
    if (mode == 3) {
        const float* qbz = plain0 + (size_t)z * 65536;   // qbias[z][128][512]
#pragma unroll
        for (int mi = 0; mi < 4; mi++) {
#pragma unroll
            for (int h = 0; h < 2; h++) {
                const int m = mBase + rowBase + mi * 16 + (lane >> 2) + h * 8;
                const float* qrow = qbz + (size_t)(m >> 5) * 512;
                float s = 0.0f;
#pragma unroll
                for (int ni = 0; ni < 4; ni++) {
                    const int n = nBase + colBase + ni * 8 + (lane & 3) * 2;
                    const float2 qv = *(const float2*)&qrow[n];
                    s += tanhf(acc[mi][ni][h * 2]     + qv.x) * vatt[z * 512 + n];
                    s += tanhf(acc[mi][ni][h * 2 + 1] + qv.y) * vatt[z * 512 + n + 1];
                }
                s += __shfl_xor_sync(0xffffffffu, s, 1);
                s += __shfl_xor_sync(0xffffffffu, s, 2);
                if ((lane & 3) == 0)
                    upart[((size_t)(nt * 4 + warpN) * 6 + z) * KBM + m] = s;
            }
        }
        return;
    }
#pragma unroll
    for (int mi = 0; mi < 4; mi++) {
#pragma unroll
        for (int h = 0; h < 2; h++) {
            const int m = mBase + rowBase + mi * 16 + (lane >> 2) + h * 8;
#pragma unroll
            for (int ni = 0; ni < 4; ni++) {
                const int n = nBase + colBase + ni * 8 + (lane & 3) * 2;
                float v0 = acc[mi][ni][h * 2];
                float v1 = acc[mi][ni][h * 2 + 1];
                if (mode != 6) { v0 += bias[n]; v1 += bias[n + 1]; }
                const size_t i0 = (size_t)m * 512 + n;
                if (mode == 6) {
                    *(float2*)&plain0[(size_t)z * 65536 + i0] = make_float2(v0, v1);
                } else if (mode == 4) {
                    const float e = p_eng[m];
                    const float wc0 = 1.0f / (1.0f + expf(-v0));
                    const float wc1 = 1.0f / (1.0f + expf(-v1));
                    const float2 cc = *(const float2*)&p_cell[i0];
                    const float2 aa = __half22float2(*(const __half2*)&p_arnh[i0]);
                    const float2 dd = __half22float2(*(const __half2*)&p_addh[i0]);
                    const float uc0 = cc.x + aa.x * dd.x * e;
                    const float uc1 = cc.y + aa.y * dd.y * e;
                    *(float2*)&outC[i0] = make_float2(uc0, uc1);
                    *(float2*)&outH[i0] = make_float2(wc0 * tanhf(uc0), wc1 * tanhf(uc1));
                } else if (mode == 5 && z < 2) {
                    u16* pl = (z == 0) ? pH0 : pH1;
                    if (z == 0) { v0 = 1.0f / (1.0f + expf(-v0)); v1 = 1.0f / (1.0f + expf(-v1)); }
                    else        { v0 = tanhf(v0); v1 = tanhf(v1); }
                    *(u32*)&pl[i0] = cvt2(v0, v1);
                } else {
                    v0 = fmaxf(v0, 0.0f); v1 = fmaxf(v1, 0.0f);
                    u16* dH = oH + (mode == 5 ? 0 : (size_t)z * oStrideZ);
                    *(u32*)&dH[i0] = cvt2(v0, v1);
                }
            }
        }
    }
}

// ---------------- merged weight prepack ---------------------------------------
struct PrepackDesc { const float* s0; const float* s1; size_t off; int K; };
struct PrepackParams { PrepackDesc d[12]; };

__global__ void prepack_all(PrepackParams p) {
    __shared__ float t[32][33];
    const PrepackDesc de = p.d[blockIdx.z];
    const int K = de.K;
    const int k0 = blockIdx.x * 32;
    if (k0 >= K) return;
    const int n0 = blockIdx.y * 32;
    const int tx = threadIdx.x, ty = threadIdx.y;
#pragma unroll
    for (int i = 0; i < 4; i++) {
        const int k = k0 + ty + i * 8;
        t[ty + i * 8][tx] = (k < 512) ? de.s0[(size_t)k * 512 + n0 + tx]
                                      : de.s1[(size_t)(k - 512) * 512 + n0 + tx];
    }
    __syncthreads();
#pragma unroll
    for (int i = 0; i < 4; i++) {
        const int n = n0 + ty + i * 8;
        const int k = k0 + tx;
        u16 h, l; split2(t[tx][ty + i * 8], h, l);
        g_wbh[de.off + (size_t)n * K + k] = h;
        g_wbl[de.off + (size_t)n * K + k] = l;
    }
}

// ---------------- activation converters ---------------------------------------
__global__ void convert_info(const float* __restrict__ x, const float* __restrict__ h,
                             u16* __restrict__ dh) {
    const size_t T = (size_t)blockIdx.x * 256 + threadIdx.x;
    const int m = (int)(T >> 8);
    const int k = ((int)T & 255) << 2;
    const float4 v = (k < 512) ? *(const float4*)(x + (size_t)m * 512 + k)
                               : *(const float4*)(h + (size_t)m * 512 + (k - 512));
    const u64 hw = (u64)cvt2(v.x, v.y) | ((u64)cvt2(v.z, v.w) << 32);
    *(u64*)&dh[(size_t)m * 1024 + k] = hw;
}
__global__ void convert_att(const float* __restrict__ kbk, const float* __restrict__ q) {
    const int y = blockIdx.y;
    const size_t T = (size_t)blockIdx.x * 256 + threadIdx.x;
    const int m = (int)(T >> 7);
    const int k = ((int)T & 127) << 2;
    float4 v;
    u16* dh;
    const size_t off = (size_t)m * 512 + k;
    if (y < 3) {
        v = *(const float4*)(kbk + ((size_t)y * 4096 + m) * 512 + k);
        dh = g_atth + (size_t)y * ATTZ;
    } else {
        if (m >= 128) return;
        v = *(const float4*)(q + (size_t)m * 512 + k);
        dh = g_qh;
    }
    const u64 hw = (u64)cvt2(v.x, v.y) | ((u64)cvt2(v.z, v.w) << 32);
    *(u64*)&dh[off] = hw;
}

// ---------------- small kernels -------------------------------------------------
__global__ void eng_kernel(const float* __restrict__ cell, const float* __restrict__ w,
                           float* __restrict__ eng) {
    const int row = blockIdx.x * 8 + (threadIdx.x >> 5);
    const int lane = threadIdx.x & 31;
    const float* c = cell + (size_t)row * HD;
    float s = 0.0f;
#pragma unroll 4
    for (int k = lane; k < HD; k += 32) s += c[k] * w[k];
#pragma unroll
    for (int o = 16; o; o >>= 1) s += __shfl_down_sync(0xffffffffu, s, o);
    if (!lane) eng[row] = s;
}
__global__ void detect_mask_kernel(const unsigned int* __restrict__ w) {
    __shared__ int sF, sG;
    if (threadIdx.x == 0) { sF = 0; sG = 0; }
    __syncthreads();
    int f = 0, g = 0;
    for (int i = threadIdx.x; i < 65536; i += blockDim.x) {
        const unsigned int v = w[i];
        if (v == 0x3F800000u) f = 1;
        else if (v > 1u) g = 1;
    }
    if (f) atomicOr(&sF, 1);
    if (g) atomicOr(&sG, 1);
    __syncthreads();
    if (threadIdx.x == 0) g_maskmode = sF ? 2 : (sG ? 0 : 1);
}
__global__ void utk_kernel(const float* __restrict__ up, const void* __restrict__ maskraw,
                           float* __restrict__ out) {
    __shared__ float S[3][32];
    const int b = blockIdx.y;
    if (threadIdx.x < 96) {
        const int d = threadIdx.x >> 5, i = threadIdx.x & 31;
        float s = 0.0f;
#pragma unroll
        for (int p = 0; p < 16; p++)
#pragma unroll
            for (int hop = 0; hop < 2; hop++)
                s += up[((size_t)p * 6 + hop * 3 + d) * KBM + b * 32 + i];
        S[d][i] = s;
    }
    __syncthreads();
    const int mode = g_maskmode;
    const int j = blockIdx.x * 256 + threadIdx.x;
    const float v = S[0][j >> 10] + S[1][(j >> 5) & 31] + S[2][j & 31];
    const size_t o = (size_t)b * KBTOT + j;
    bool msk;
    if (mode == 0)      msk = ((const unsigned char*)maskraw)[o] != 0;
    else if (mode == 1) msk = ((const int*)maskraw)[o] != 0;
    else                msk = ((const float*)maskraw)[o] != 0.0f;
    out[o] = msk ? 0.0f : v;
}

// ---------------- host -----------------------------------------------------------
extern "C" void kernel_launch(void* const* d_in, const int* in_sizes, int n_in,
                              void* d_out, int out_size) {
    const float* query   = (const float*)d_in[0];
    const float* kb_keys = (const float*)d_in[1];
    const float* Wq      = (const float*)d_in[2];
    const float* Wk      = (const float*)d_in[3];
    const float* v_att   = (const float*)d_in[4];
    const float* x       = (const float*)d_in[5];
    const float* hidden  = (const float*)d_in[6];
    const float* cell    = (const float*)d_in[7];
    const float* arn_w1  = (const float*)d_in[8];
    const float* arn_b1  = (const float*)d_in[9];
    const float* arn_w2  = (const float*)d_in[10];
    const float* arn_b2  = (const float*)d_in[11];
    const float* arn_w3  = (const float*)d_in[12];
    const float* arn_b3  = (const float*)d_in[13];
    const float* add_w1  = (const float*)d_in[14];
    const float* add_b1  = (const float*)d_in[15];
    const float* add_w2  = (const float*)d_in[16];
    const float* add_b2  = (const float*)d_in[17];
    const float* add_w3  = (const float*)d_in[18];
    const float* add_b3  = (const float*)d_in[19];
    const float* eng_w   = (const float*)d_in[20];
    const float* wc_w1   = (const float*)d_in[21];
    const float* wc_b1   = (const float*)d_in[22];
    const float* wc_w2   = (const float*)d_in[23];
    const float* wc_b2   = (const float*)d_in[24];
    const float* wc_w3   = (const float*)d_in[25];
    const float* wc_b3   = (const float*)d_in[26];
    const float* wc_w4   = (const float*)d_in[27];
    const float* wc_b4   = (const float*)d_in[28];
    const void*  kb_mask = d_in[29];

    float* out     = (float*)d_out;
    float* out_utk = out;
    float* outH    = out + (size_t)BSZ * KBTOT;
    float* outC    = outH + (size_t)BT * HD;

    u16 *wbh, *atth, *qh, *ah, *arnh, *addh;
    float *qb, *upart, *engp;
    cudaGetSymbolAddress((void**)&wbh,  g_wbh);
    cudaGetSymbolAddress((void**)&atth, g_atth);
    cudaGetSymbolAddress((void**)&qh,   g_qh);
    cudaGetSymbolAddress((void**)&ah,   g_ah);
    cudaGetSymbolAddress((void**)&arnh, g_arnh);
    cudaGetSymbolAddress((void**)&addh, g_addh);
    cudaGetSymbolAddress((void**)&qb,   g_qb);
    cudaGetSymbolAddress((void**)&upart,g_upart);
    cudaGetSymbolAddress((void**)&engp, g_eng);

    static cudaStream_t s2 = nullptr;
    static cudaEvent_t evFork = nullptr, evJoin = nullptr;
    if (!s2) {
        cudaFuncSetAttribute(gemm_tc, cudaFuncAttributeMaxDynamicSharedMemorySize, 98304);
        cudaStreamCreateWithFlags(&s2, cudaStreamNonBlocking);
        cudaEventCreateWithFlags(&evFork, cudaEventDisableTiming);
        cudaEventCreateWithFlags(&evJoin, cudaEventDisableTiming);
    }

    // ---- fork immediately: attention chain fully parallel with MLP chain --------
    cudaEventRecord(evFork, 0);
    cudaStreamWaitEvent(s2, evFork, 0);

    // s2: attention weight prepack (12 SMALL slots: Wk, Wq)
    PrepackParams pa;
    for (int i = 0; i < 6; i++) {
        pa.d[i]     = {Wk + (size_t)i * 262144, Wk + (size_t)i * 262144, WKOFF + i * SMALL, 512};
        pa.d[6 + i] = {Wq + (size_t)i * 262144, Wq + (size_t)i * 262144, WQOFF + i * SMALL, 512};
    }
    prepack_all<<<dim3(16, 16, 12), dim3(32, 8), 0, s2>>>(pa);
    convert_att<<<dim3(2048, 4), 256, 0, s2>>>(kb_keys, query);
    // qbias[z] = query @ Wq[z]
    gemm_tc<<<dim3(4, 1, 6), 256, 98304, s2>>>(
        qh, 0, 1, wbh + WQOFF, SMALL, 512,
        nullptr, nullptr, nullptr, 6,
        nullptr, 0, qb, nullptr, nullptr, nullptr, nullptr,
        nullptr, nullptr, nullptr, nullptr, nullptr, nullptr);
    // attention GEMM
    gemm_tc<<<dim3(4, 32, 6), 256, 98304, s2>>>(
        atth, ATTZ, 3, wbh + WKOFF, SMALL, 512,
        nullptr, nullptr, nullptr, 3,
        nullptr, 0, qb, nullptr, nullptr, v_att, upart,
        nullptr, nullptr, nullptr, nullptr, nullptr, nullptr);
    detect_mask_kernel<<<1, 1024, 0, s2>>>((const unsigned int*)kb_mask);
    utk_kernel<<<dim3(KBTOT / 256, BSZ), 256, 0, s2>>>(upart, kb_mask, out_utk);
    cudaEventRecord(evJoin, s2);

    // ---- main: MLP chain ---------------------------------------------------------
    // MLP weight prepack (3 BIG + 7 SMALL)
    PrepackParams pm;
    pm.d[0] = {arn_w1, arn_w1 + 262144, W1OFF + 0 * BIG, 1024};
    pm.d[1] = {add_w1, add_w1 + 262144, W1OFF + 1 * BIG, 1024};
    pm.d[2] = {wc_w1,  wc_w1  + 262144, W1OFF + 2 * BIG, 1024};
    const float* sw[7] = {arn_w2, arn_w3, add_w2, add_w3, wc_w2, wc_w3, wc_w4};
    for (int j = 0; j < 7; j++)
        pm.d[3 + j] = {sw[j], sw[j], WSOFF2 + j * SMALL, 512};
    for (int j = 10; j < 12; j++) pm.d[j] = pm.d[9];   // padded, harmless rewrite
    prepack_all<<<dim3(32, 16, 10), dim3(32, 8)>>>(pm);

    convert_info<<<32768, 256>>>(x, hidden, ah);
    eng_kernel<<<BT / 8, 256>>>(cell, eng_w, engp);

    // L1: info @ w1 -> h1 hi planes (relu)
    gemm_tc<<<dim3(4, 256, 3), 256, 98304>>>(
        ah, 0, 0, wbh + W1OFF, BIG, 1024,
        arn_b1, add_b1, wc_b1, 0,
        ah + H1_OFF, H1S, nullptr, nullptr, nullptr, nullptr, nullptr,
        nullptr, nullptr, nullptr, nullptr, nullptr, nullptr);
    // L2: h1 @ w2 -> h2 hi planes (relu)
    gemm_tc<<<dim3(4, 256, 3), 256, 98304>>>(
        ah + H1_OFF, H1S, 0, wbh + WSOFF2, 2 * SMALL, 512,
        arn_b2, add_b2, wc_b2, 0,
        ah + H2_OFF, H1S, nullptr, nullptr, nullptr, nullptr, nullptr,
        nullptr, nullptr, nullptr, nullptr, nullptr, nullptr);
    // L3: h2 @ w3; z0 sigmoid->arnh(fp16), z1 tanh->addh(fp16), z2 relu->h3 plane
    gemm_tc<<<dim3(4, 256, 3), 256, 98304>>>(
        ah + H2_OFF, H1S, 0, wbh + WSOFF2 + SMALL, 2 * SMALL, 512,
        arn_b3, add_b3, wc_b3, 5,
        ah + H1_OFF, 0, nullptr, arnh, addh, nullptr, nullptr,
        nullptr, nullptr, nullptr, nullptr, nullptr, nullptr);
    // L4: h3 @ wc_w4 -> fused final epilogue
    gemm_tc<<<dim3(4, 256, 1), 256, 98304>>>(
        ah + H1_OFF, 0, 0, wbh + WSOFF2 + 6 * SMALL, SMALL, 512,
        wc_b4, wc_b4, wc_b4, 4,
        nullptr, 0, nullptr, nullptr, nullptr, nullptr, nullptr,
        arnh, addh, cell, engp, outH, outC);

    // ---- join ---------------------------------------------------------------------
    cudaStreamWaitEvent(0, evJoin, 0);
}